// round 2
// baseline (speedup 1.0000x reference)
#include <cuda_runtime.h>
#include <cuda_bf16.h>
#include <cfloat>
#include <math.h>

// ---------------- problem constants ----------------
#define BB 2
#define TT 8
#define NN 1792
#define DD 4096
#define HH 8
#define DHH 96
#define INNER 768          // H*DH
#define NL 16
#define FF 8192
#define BT 16              // B*T
#define XROWS 28672        // BT*NN
#define LATROWS 256        // BT*NL
#define EPS 1e-5f
#define ATTN_SCALE 0.10206207261596577f  // 96^-0.5

// ---------------- scratch (static device memory; no allocs allowed) --------
__device__ float g_mean[XROWS];
__device__ float g_rstd[XROWS];
__device__ float g_kv[(size_t)XROWS * 1536];   // 176 MB: [row, 0:768]=K, [768:1536]=V
__device__ float g_ql[NL * DD];
__device__ float g_q[NL * INNER];
__device__ float g_attnout[LATROWS * INNER];
__device__ float g_lat1[LATROWS * DD];
__device__ float g_ffln[LATROWS * DD];
__device__ float g_h1[(size_t)LATROWS * FF];
__device__ float g_lat2[LATROWS * DD];
__device__ float g_maskf[XROWS];               // BT*NN mask as float 0/1
__device__ int   g_mask_kind;                  // 0 = byte-bool, 1 = int32-bool

// ---------------- mask dtype detection + conversion ------------------------
// If the harness stores bool as int32, every u32 word is 0 or 1.
// If stored as 1-byte bools, words over the first 28672 bytes contain packed
// 0/1 bytes -> some word exceeds 1 with probability 1 - 2^-large.
__global__ void detect_mask_kernel(const unsigned int* __restrict__ m) {
    if (threadIdx.x == 0) {
        unsigned int orv = 0;
        for (int i = 0; i < XROWS / 4; i++) orv |= m[i];
        g_mask_kind = (orv <= 1u) ? 1 : 0;
    }
}

__global__ void convert_mask_kernel(const void* __restrict__ m,
                                    float* __restrict__ mf) {
    int i = blockIdx.x * blockDim.x + threadIdx.x;
    if (i < XROWS) {
        if (g_mask_kind == 1)
            mf[i] = (float)((const int*)m)[i];
        else
            mf[i] = (float)((const unsigned char*)m)[i];
    }
}

// ---------------- row statistics (mean, rstd) over D=4096 ------------------
__global__ void row_stats_kernel(const float* __restrict__ x,
                                 float* __restrict__ mean,
                                 float* __restrict__ rstd, int D) {
    int row = blockIdx.x;
    const float* xr = x + (size_t)row * D;
    float s = 0.f, q = 0.f;
    for (int i = threadIdx.x; i < D; i += blockDim.x) {
        float v = xr[i];
        s += v; q += v * v;
    }
    #pragma unroll
    for (int o = 16; o; o >>= 1) {
        s += __shfl_xor_sync(0xffffffffu, s, o);
        q += __shfl_xor_sync(0xffffffffu, q, o);
    }
    __shared__ float sh_s[8], sh_q[8];
    int w = threadIdx.x >> 5, l = threadIdx.x & 31;
    if (l == 0) { sh_s[w] = s; sh_q[w] = q; }
    __syncthreads();
    if (threadIdx.x == 0) {
        float S = 0.f, Q = 0.f;
        #pragma unroll
        for (int i = 0; i < 8; i++) { S += sh_s[i]; Q += sh_q[i]; }
        float m = S / (float)D;
        float var = Q / (float)D - m * m;
        mean[row] = m;
        rstd[row] = rsqrtf(var + EPS);
    }
}

// ---------------- full layernorm of rows (writes normalized output) --------
__global__ void ln_rows_kernel(const float* __restrict__ in,
                               float* __restrict__ out,
                               const float* __restrict__ g,
                               const float* __restrict__ b, int D) {
    int row = blockIdx.x;
    const float* xr = in + (size_t)row * D;
    float s = 0.f, q = 0.f;
    for (int i = threadIdx.x; i < D; i += blockDim.x) {
        float v = xr[i];
        s += v; q += v * v;
    }
    #pragma unroll
    for (int o = 16; o; o >>= 1) {
        s += __shfl_xor_sync(0xffffffffu, s, o);
        q += __shfl_xor_sync(0xffffffffu, q, o);
    }
    __shared__ float sh_s[8], sh_q[8];
    __shared__ float m_sh, r_sh;
    int w = threadIdx.x >> 5, l = threadIdx.x & 31;
    if (l == 0) { sh_s[w] = s; sh_q[w] = q; }
    __syncthreads();
    if (threadIdx.x == 0) {
        float S = 0.f, Q = 0.f;
        #pragma unroll
        for (int i = 0; i < 8; i++) { S += sh_s[i]; Q += sh_q[i]; }
        float m = S / (float)D;
        float var = Q / (float)D - m * m;
        m_sh = m;
        r_sh = rsqrtf(var + EPS);
    }
    __syncthreads();
    float m = m_sh, r = r_sh;
    for (int i = threadIdx.x; i < D; i += blockDim.x)
        out[(size_t)row * D + i] = (xr[i] - m) * r * g[i] + b[i];
}

// ---------------- generic fp32 GEMM: C[M,N] = A'[M,K] @ B[K,N] -------------
// A' = A when ln_mean==nullptr, else A' = layernorm(A) row-wise with
// precomputed (mean,rstd) and affine (ln_g, ln_b) over the K axis.
// Requirements: N % 128 == 0, K % 16 == 0. M arbitrary (guarded).
#define GT 128
#define GKT 16
__global__ void __launch_bounds__(256, 2)
gemm_kernel(const float* __restrict__ A, const float* __restrict__ B,
            float* __restrict__ C, int M, int N, int K,
            const float* __restrict__ ln_mean, const float* __restrict__ ln_rstd,
            const float* __restrict__ ln_g, const float* __restrict__ ln_b) {
    __shared__ float As[GKT][GT + 4];
    __shared__ float Bs[GKT][GT];

    int tid = threadIdx.x;
    int row0 = blockIdx.y * GT;
    int col0 = blockIdx.x * GT;
    int ty = tid >> 4, tx = tid & 15;

    float acc[8][8];
    #pragma unroll
    for (int u = 0; u < 8; u++)
        #pragma unroll
        for (int v = 0; v < 8; v++) acc[u][v] = 0.f;

    // A tile load mapping: each thread loads 8 consecutive k of one row
    int a_m = tid >> 1;
    int a_k = (tid & 1) * 8;
    int a_row = row0 + a_m;
    bool arow_ok = a_row < M;
    bool use_ln = (ln_mean != nullptr);
    float mean = 0.f, rstd = 1.f;
    if (use_ln && arow_ok) { mean = ln_mean[a_row]; rstd = ln_rstd[a_row]; }

    // B tile load mapping
    int b_n = tid & 127;
    int b_k0 = tid >> 7;   // 0 or 1

    for (int k0 = 0; k0 < K; k0 += GKT) {
        // load A tile (with optional fused layernorm)
        if (use_ln) {
            #pragma unroll
            for (int i = 0; i < 8; i++) {
                int kk = a_k + i;
                float v = arow_ok ? A[(size_t)a_row * K + k0 + kk] : 0.f;
                v = (v - mean) * rstd * ln_g[k0 + kk] + ln_b[k0 + kk];
                As[kk][a_m] = v;
            }
        } else {
            #pragma unroll
            for (int i = 0; i < 8; i++) {
                int kk = a_k + i;
                As[kk][a_m] = arow_ok ? A[(size_t)a_row * K + k0 + kk] : 0.f;
            }
        }
        // load B tile
        #pragma unroll
        for (int i = 0; i < 8; i++) {
            int kk = b_k0 + i * 2;
            Bs[kk][b_n] = B[(size_t)(k0 + kk) * N + col0 + b_n];
        }
        __syncthreads();

        #pragma unroll
        for (int kk = 0; kk < GKT; kk++) {
            float4 a0 = *(const float4*)&As[kk][ty * 8];
            float4 a1 = *(const float4*)&As[kk][ty * 8 + 4];
            float4 b0 = *(const float4*)&Bs[kk][tx * 8];
            float4 b1 = *(const float4*)&Bs[kk][tx * 8 + 4];
            float af[8] = {a0.x, a0.y, a0.z, a0.w, a1.x, a1.y, a1.z, a1.w};
            float bf[8] = {b0.x, b0.y, b0.z, b0.w, b1.x, b1.y, b1.z, b1.w};
            #pragma unroll
            for (int u = 0; u < 8; u++)
                #pragma unroll
                for (int v = 0; v < 8; v++)
                    acc[u][v] = fmaf(af[u], bf[v], acc[u][v]);
        }
        __syncthreads();
    }

    #pragma unroll
    for (int u = 0; u < 8; u++) {
        int r = row0 + ty * 8 + u;
        if (r < M) {
            float* cp = C + (size_t)r * N + col0 + tx * 8;
            float4 o0 = make_float4(acc[u][0], acc[u][1], acc[u][2], acc[u][3]);
            float4 o1 = make_float4(acc[u][4], acc[u][5], acc[u][6], acc[u][7]);
            *(float4*)(cp) = o0;
            *(float4*)(cp + 4) = o1;
        }
    }
}

// ---------------- attention: one block per (bt, h) -------------------------
// Exact reference numerics:
//   sim0 = SCALE * q.k ; m0 = max_j sim0
//   s = mask ? finfo.min : (sim0 - m0) ; s *= guidance[j]
//   attn = softmax_j(s) ; out = attn @ v
#define JT 128
#define KVS 97   // padded row stride for kv tile (conflict-free)
__global__ void attn_kernel(const float* __restrict__ guid,
                            const float* __restrict__ maskf) {
    extern __shared__ float sm[];
    float* q_s  = sm;                    // 16*96
    float* sim  = q_s + NL * DHH;        // 16*1792
    float* kvt  = sim + NL * NN;         // 128*97
    float* gu   = kvt + JT * KVS;        // 1792
    float* mk   = gu + NN;               // 1792

    int bt = blockIdx.x >> 3;
    int h  = blockIdx.x & 7;
    int tid = threadIdx.x;

    for (int idx = tid; idx < NL * DHH; idx += 256) {
        int i = idx / DHH, d = idx % DHH;
        q_s[idx] = g_q[i * INNER + h * DHH + d];
    }
    for (int j = tid; j < NN; j += 256) {
        gu[j] = guid[bt * NN + j];
        mk[j] = maskf[bt * NN + j];
    }
    __syncthreads();

    size_t kvbase = (size_t)bt * NN * 1536;

    // ---- pass 1: scores ----
    for (int j0 = 0; j0 < NN; j0 += JT) {
        for (int idx = tid; idx < JT * DHH; idx += 256) {
            int j = idx / DHH, d = idx % DHH;
            kvt[j * KVS + d] = g_kv[kvbase + (size_t)(j0 + j) * 1536 + h * DHH + d];
        }
        __syncthreads();
        #pragma unroll
        for (int p = 0; p < 8; p++) {
            int idx = tid + p * 256;       // 16*128 = 2048 pairs
            int i = idx >> 7, j = idx & 127;
            const float* qp = q_s + i * DHH;
            const float* kp = kvt + j * KVS;
            float a = 0.f;
            #pragma unroll 8
            for (int d = 0; d < DHH; d++) a = fmaf(qp[d], kp[d], a);
            sim[i * NN + j0 + j] = a * ATTN_SCALE;
        }
        __syncthreads();
    }

    // ---- softmax transform: warp w handles rows w and w+8 ----
    int warp = tid >> 5, lane = tid & 31;
    for (int r = warp; r < NL; r += 8) {
        float* srow = sim + r * NN;
        float m0 = -FLT_MAX;
        for (int j = lane; j < NN; j += 32) m0 = fmaxf(m0, srow[j]);
        #pragma unroll
        for (int o = 16; o; o >>= 1) m0 = fmaxf(m0, __shfl_xor_sync(0xffffffffu, m0, o));

        float m1 = -FLT_MAX;
        for (int j = lane; j < NN; j += 32) {
            float s = srow[j] - m0;
            if (mk[j] != 0.f) s = -3.402823466e38f;  // finfo(f32).min
            s *= gu[j];
            srow[j] = s;
            m1 = fmaxf(m1, s);
        }
        #pragma unroll
        for (int o = 16; o; o >>= 1) m1 = fmaxf(m1, __shfl_xor_sync(0xffffffffu, m1, o));

        float sum = 0.f;
        for (int j = lane; j < NN; j += 32) {
            float e = expf(srow[j] - m1);
            srow[j] = e;
            sum += e;
        }
        #pragma unroll
        for (int o = 16; o; o >>= 1) sum += __shfl_xor_sync(0xffffffffu, sum, o);
        float inv = 1.f / sum;
        for (int j = lane; j < NN; j += 32) srow[j] *= inv;
    }
    __syncthreads();

    // ---- pass 2: attn @ V ----
    float acc[6];
    #pragma unroll
    for (int p = 0; p < 6; p++) acc[p] = 0.f;
    for (int j0 = 0; j0 < NN; j0 += JT) {
        for (int idx = tid; idx < JT * DHH; idx += 256) {
            int j = idx / DHH, d = idx % DHH;
            kvt[j * KVS + d] = g_kv[kvbase + (size_t)(j0 + j) * 1536 + INNER + h * DHH + d];
        }
        __syncthreads();
        #pragma unroll
        for (int p = 0; p < 6; p++) {
            int idx = tid + p * 256;       // 16*96 = 1536 pairs
            int i = idx / DHH, d = idx % DHH;
            const float* srow = sim + i * NN + j0;
            float a = acc[p];
            #pragma unroll 4
            for (int j = 0; j < JT; j++) a = fmaf(srow[j], kvt[j * KVS + d], a);
            acc[p] = a;
        }
        __syncthreads();
    }
    #pragma unroll
    for (int p = 0; p < 6; p++) {
        int idx = tid + p * 256;
        int i = idx / DHH, d = idx % DHH;
        g_attnout[(bt * NL + i) * INNER + h * DHH + d] = acc[p];
    }
}

// ---------------- small elementwise kernels ---------------------------------
__global__ void add_latents_kernel(float* __restrict__ lat1,
                                   const float* __restrict__ latents) {
    int idx = blockIdx.x * blockDim.x + threadIdx.x;   // LATROWS*DD
    int r = idx >> 12, c = idx & 4095;
    lat1[idx] += latents[(r & 15) * DD + c];
}

__global__ void gelu_kernel(float* __restrict__ h, int n) {
    int idx = blockIdx.x * blockDim.x + threadIdx.x;
    if (idx < n) {
        float v = h[idx];
        h[idx] = 0.5f * v * (1.0f + erff(v * 0.70710678118654752f));
    }
}

__global__ void add_kernel(float* __restrict__ a, const float* __restrict__ b, int n) {
    int idx = blockIdx.x * blockDim.x + threadIdx.x;
    if (idx < n) a[idx] += b[idx];
}

// ---------------- launch ----------------------------------------------------
extern "C" void kernel_launch(void* const* d_in, const int* in_sizes, int n_in,
                              void* d_out, int out_size) {
    const float*         x       = (const float*)d_in[0];
    const float*         guid    = (const float*)d_in[1];
    const void*          mask    = d_in[2];
    const float*         latents = (const float*)d_in[3];
    const float*         nm_g    = (const float*)d_in[4];
    const float*         nm_b    = (const float*)d_in[5];
    const float*         nl_g    = (const float*)d_in[6];
    const float*         nl_b    = (const float*)d_in[7];
    const float*         wq      = (const float*)d_in[8];
    const float*         wkv     = (const float*)d_in[9];
    const float*         wout    = (const float*)d_in[10];
    const float*         ff_g    = (const float*)d_in[11];
    const float*         ff_b    = (const float*)d_in[12];
    const float*         w1      = (const float*)d_in[13];
    const float*         w2      = (const float*)d_in[14];
    const float*         fn_g    = (const float*)d_in[15];
    const float*         fn_b    = (const float*)d_in[16];
    float* out = (float*)d_out;

    float *p_mean, *p_rstd, *p_kv, *p_ql, *p_q, *p_attnout, *p_lat1, *p_ffln, *p_h1, *p_lat2, *p_maskf;
    cudaGetSymbolAddress((void**)&p_mean,    g_mean);
    cudaGetSymbolAddress((void**)&p_rstd,    g_rstd);
    cudaGetSymbolAddress((void**)&p_kv,      g_kv);
    cudaGetSymbolAddress((void**)&p_ql,      g_ql);
    cudaGetSymbolAddress((void**)&p_q,       g_q);
    cudaGetSymbolAddress((void**)&p_attnout, g_attnout);
    cudaGetSymbolAddress((void**)&p_lat1,    g_lat1);
    cudaGetSymbolAddress((void**)&p_ffln,    g_ffln);
    cudaGetSymbolAddress((void**)&p_h1,      g_h1);
    cudaGetSymbolAddress((void**)&p_lat2,    g_lat2);
    cudaGetSymbolAddress((void**)&p_maskf,   g_maskf);

    // 0. mask dtype detection + expansion to float
    detect_mask_kernel<<<1, 32>>>((const unsigned int*)mask);
    convert_mask_kernel<<<(XROWS + 255) / 256, 256>>>(mask, p_maskf);

    // 1. row stats of x (for fused LN in KV GEMM)
    row_stats_kernel<<<XROWS, 256>>>(x, p_mean, p_rstd, DD);

    // 2. ql = LN(latents)  (shared across all b,t)
    ln_rows_kernel<<<NL, 256>>>(latents, p_ql, nl_g, nl_b, DD);

    // 3. q = ql @ wq   (16 x 4096 x 768)
    gemm_kernel<<<dim3(INNER / GT, 1), 256>>>(p_ql, wq, p_q, NL, INNER, DD,
                                              nullptr, nullptr, nullptr, nullptr);

    // 4. kv = LN(x) @ wkv   (28672 x 4096 x 1536) -- dominant GEMM
    gemm_kernel<<<dim3(1536 / GT, XROWS / GT), 256>>>(x, wkv, p_kv, XROWS, 1536, DD,
                                                      p_mean, p_rstd, nm_g, nm_b);

    // 5. attention (128 blocks = BT*H)
    {
        int smem_bytes = (NL * DHH + NL * NN + JT * KVS + 2 * NN) * (int)sizeof(float);
        cudaFuncSetAttribute(attn_kernel, cudaFuncAttributeMaxDynamicSharedMemorySize,
                             smem_bytes);
        attn_kernel<<<BT * HH, 256, smem_bytes>>>(guid, p_maskf);
    }

    // 6. lat1 = attnout @ wout + latents  (256 x 768 x 4096)
    gemm_kernel<<<dim3(DD / GT, LATROWS / GT), 256>>>(p_attnout, wout, p_lat1,
                                                      LATROWS, DD, INNER,
                                                      nullptr, nullptr, nullptr, nullptr);
    add_latents_kernel<<<(LATROWS * DD) / 256, 256>>>(p_lat1, latents);

    // 7. ffln = LN(lat1)
    ln_rows_kernel<<<LATROWS, 256>>>(p_lat1, p_ffln, ff_g, ff_b, DD);

    // 8. h1 = gelu(ffln @ w1)   (256 x 4096 x 8192)
    gemm_kernel<<<dim3(FF / GT, LATROWS / GT), 256>>>(p_ffln, w1, p_h1,
                                                      LATROWS, FF, DD,
                                                      nullptr, nullptr, nullptr, nullptr);
    gelu_kernel<<<(LATROWS * FF) / 256, 256>>>(p_h1, LATROWS * FF);

    // 9. lat2 = h1 @ w2 + lat1   (256 x 8192 x 4096)
    gemm_kernel<<<dim3(DD / GT, LATROWS / GT), 256>>>(p_h1, w2, p_lat2,
                                                      LATROWS, DD, FF,
                                                      nullptr, nullptr, nullptr, nullptr);
    add_kernel<<<(LATROWS * DD) / 256, 256>>>(p_lat2, p_lat1, LATROWS * DD);

    // 10. out = LN(lat2)
    ln_rows_kernel<<<LATROWS, 256>>>(p_lat2, out, fn_g, fn_b, DD);
}

// round 3
// speedup vs baseline: 3.1374x; 3.1374x over previous
#include <cuda_runtime.h>
#include <cuda_bf16.h>
#include <cfloat>
#include <math.h>

// ---------------- problem constants ----------------
#define NN 1792
#define DD 4096
#define HH 8
#define DHH 96
#define INNER 768
#define NL 16
#define FF 8192
#define BT 16
#define XROWS 28672        // BT*NN
#define LATROWS 256        // BT*NL
#define EPS 1e-5f
#define ATTN_SCALE 0.10206207261596577f  // 96^-0.5

// ---------------- scratch ----------------
__device__ float g_mean[XROWS];
__device__ float g_rstd[XROWS];
__device__ float g_maskf[XROWS];
__device__ int   g_mask_kind;

__device__ float g_ql[NL * DD];
__device__ float g_qp[8 * NL * INNER];
__device__ float g_q[NL * INNER];

__device__ float g_QTT[DD * 128];
__device__ float g_QGT[DD * 128];
__device__ float g_u[128];
__device__ float g_v[128];
__device__ float g_bv[INNER];

__device__ float g_S0p[2 * (size_t)XROWS * 128];
__device__ float g_S0[(size_t)XROWS * 128];

__device__ float g_C[(size_t)BT * 128 * NN];     // [bt][h*16+i][j] = attn*r_j
__device__ float g_s[BT * 128];                  // sum_j attn*r*m

__device__ float g_AX[(size_t)BT * 128 * DD];    // [bt][h*16+i][d]
__device__ float g_Y[(size_t)HH * LATROWS * DD]; // [h][bt*16+i][d]

__device__ float g_Vp[8 * (size_t)LATROWS * INNER];
__device__ float g_attnv[LATROWS * INNER];

__device__ float g_woutp[2 * (size_t)LATROWS * DD];
__device__ float g_lat1[LATROWS * DD];
__device__ float g_ffln[LATROWS * DD];
__device__ float g_ff1p[4 * (size_t)LATROWS * FF];
__device__ float g_h1[(size_t)LATROWS * FF];
__device__ float g_ff2p[8 * (size_t)LATROWS * DD];
__device__ float g_lat2[LATROWS * DD];

// ---------------- mask handling ----------------
__global__ void detect_mask_kernel(const unsigned int* __restrict__ m) {
    if (threadIdx.x == 0) {
        unsigned int orv = 0;
        for (int i = 0; i < XROWS / 4; i++) orv |= m[i];
        g_mask_kind = (orv <= 1u) ? 1 : 0;
    }
}
__global__ void convert_mask_kernel(const void* __restrict__ m, float* __restrict__ mf) {
    int i = blockIdx.x * blockDim.x + threadIdx.x;
    if (i < XROWS) {
        if (g_mask_kind == 1) mf[i] = (float)((const int*)m)[i];
        else                  mf[i] = (float)((const unsigned char*)m)[i];
    }
}

// ---------------- row stats ----------------
__global__ void row_stats_kernel(const float* __restrict__ x,
                                 float* __restrict__ mean, float* __restrict__ rstd) {
    int row = blockIdx.x;
    const float* xr = x + (size_t)row * DD;
    float s = 0.f, q = 0.f;
    for (int i = threadIdx.x; i < DD; i += blockDim.x) { float v = xr[i]; s += v; q += v * v; }
    #pragma unroll
    for (int o = 16; o; o >>= 1) {
        s += __shfl_xor_sync(0xffffffffu, s, o);
        q += __shfl_xor_sync(0xffffffffu, q, o);
    }
    __shared__ float sh_s[8], sh_q[8];
    int w = threadIdx.x >> 5, l = threadIdx.x & 31;
    if (l == 0) { sh_s[w] = s; sh_q[w] = q; }
    __syncthreads();
    if (threadIdx.x == 0) {
        float S = 0.f, Q = 0.f;
        #pragma unroll
        for (int i = 0; i < 8; i++) { S += sh_s[i]; Q += sh_q[i]; }
        float m = S / (float)DD;
        mean[row] = m;
        rstd[row] = rsqrtf(Q / (float)DD - m * m + EPS);
    }
}

// ---------------- full layernorm ----------------
__global__ void ln_rows_kernel(const float* __restrict__ in, float* __restrict__ out,
                               const float* __restrict__ g, const float* __restrict__ b) {
    int row = blockIdx.x;
    const float* xr = in + (size_t)row * DD;
    float s = 0.f, q = 0.f;
    for (int i = threadIdx.x; i < DD; i += blockDim.x) { float v = xr[i]; s += v; q += v * v; }
    #pragma unroll
    for (int o = 16; o; o >>= 1) {
        s += __shfl_xor_sync(0xffffffffu, s, o);
        q += __shfl_xor_sync(0xffffffffu, q, o);
    }
    __shared__ float sh_s[8], sh_q[8];
    __shared__ float m_sh, r_sh;
    int w = threadIdx.x >> 5, l = threadIdx.x & 31;
    if (l == 0) { sh_s[w] = s; sh_q[w] = q; }
    __syncthreads();
    if (threadIdx.x == 0) {
        float S = 0.f, Q = 0.f;
        #pragma unroll
        for (int i = 0; i < 8; i++) { S += sh_s[i]; Q += sh_q[i]; }
        float m = S / (float)DD;
        m_sh = m;
        r_sh = rsqrtf(Q / (float)DD - m * m + EPS);
    }
    __syncthreads();
    float m = m_sh, r = r_sh;
    for (int i = threadIdx.x; i < DD; i += blockDim.x)
        out[(size_t)row * DD + i] = (xr[i] - m) * r * g[i] + b[i];
}

// ---------------- generic batched split-K fp32 GEMM ----------------
// C_part[batch,split] = A[batch][M, Kchunk-slice] @ B[batch][Kchunk-slice, N]
// z = batch*nsplit + split. N guarded (N%8==0 required), M guarded, K%16==0.
#define GT 128
#define GKT 16
__global__ void __launch_bounds__(256, 2)
gemm2_kernel(const float* __restrict__ A, long long lda, long long abatch,
             const float* __restrict__ B, long long ldb, long long bbatch,
             float* __restrict__ C, long long ldc, long long cbatch, long long csplit,
             int M, int N, int Ktot, int nsplit) {
    __shared__ float As[GKT][GT + 4];
    __shared__ float Bs[GKT][GT];

    int z = blockIdx.z;
    int batch = z / nsplit, split = z - batch * nsplit;
    int Kchunk = Ktot / nsplit;
    int kbeg = split * Kchunk;

    const float* Ab = A + abatch * batch;
    const float* Bb = B + bbatch * batch;
    float* Cb = C + cbatch * batch + csplit * split;

    int tid = threadIdx.x;
    int row0 = blockIdx.y * GT;
    int col0 = blockIdx.x * GT;
    int ty = tid >> 4, tx = tid & 15;

    float acc[8][8];
    #pragma unroll
    for (int u = 0; u < 8; u++)
        #pragma unroll
        for (int v = 0; v < 8; v++) acc[u][v] = 0.f;

    int a_m = tid >> 1;
    int a_k = (tid & 1) * 8;
    int a_row = row0 + a_m;
    bool arow_ok = a_row < M;

    int b_n = tid & 127;
    int b_k0 = tid >> 7;
    bool bn_ok = (col0 + b_n) < N;

    for (int k0 = kbeg; k0 < kbeg + Kchunk; k0 += GKT) {
        #pragma unroll
        for (int i = 0; i < 8; i++) {
            int kk = a_k + i;
            As[kk][a_m] = arow_ok ? Ab[(long long)a_row * lda + k0 + kk] : 0.f;
        }
        #pragma unroll
        for (int i = 0; i < 8; i++) {
            int kk = b_k0 + i * 2;
            Bs[kk][b_n] = bn_ok ? Bb[(long long)(k0 + kk) * ldb + col0 + b_n] : 0.f;
        }
        __syncthreads();

        #pragma unroll
        for (int kk = 0; kk < GKT; kk++) {
            float4 a0 = *(const float4*)&As[kk][ty * 8];
            float4 a1 = *(const float4*)&As[kk][ty * 8 + 4];
            float4 b0 = *(const float4*)&Bs[kk][tx * 8];
            float4 b1 = *(const float4*)&Bs[kk][tx * 8 + 4];
            float af[8] = {a0.x, a0.y, a0.z, a0.w, a1.x, a1.y, a1.z, a1.w};
            float bf[8] = {b0.x, b0.y, b0.z, b0.w, b1.x, b1.y, b1.z, b1.w};
            #pragma unroll
            for (int u = 0; u < 8; u++)
                #pragma unroll
                for (int v = 0; v < 8; v++)
                    acc[u][v] = fmaf(af[u], bf[v], acc[u][v]);
        }
        __syncthreads();
    }

    #pragma unroll
    for (int u = 0; u < 8; u++) {
        int r = row0 + ty * 8 + u;
        int c = col0 + tx * 8;
        if (r < M && c < N) {
            float* cp = Cb + (long long)r * ldc + c;
            *(float4*)(cp)     = make_float4(acc[u][0], acc[u][1], acc[u][2], acc[u][3]);
            *(float4*)(cp + 4) = make_float4(acc[u][4], acc[u][5], acc[u][6], acc[u][7]);
        }
    }
}

// ---------------- generic split reduce + epilogue ----------------
// out[i] = f( sum_p parts[p*pstride+i] + bias[i%bias_period] ) + add
// add_mode: 0 none, 1 direct, 2 latents-broadcast (row%16)
__global__ void reduce_kernel(const float* __restrict__ parts, long long pstride, int nsplit,
                              float* __restrict__ out, long long n,
                              const float* __restrict__ addsrc, int add_mode,
                              const float* __restrict__ bias, int bias_period,
                              int do_gelu) {
    long long i = (long long)blockIdx.x * 256 + threadIdx.x;
    if (i >= n) return;
    float s = 0.f;
    for (int p = 0; p < nsplit; p++) s += parts[p * pstride + i];
    if (bias) s += bias[i % bias_period];
    if (do_gelu) s = 0.5f * s * (1.0f + erff(s * 0.70710678118654752f));
    if (add_mode == 1) s += addsrc[i];
    else if (add_mode == 2) {
        long long r = i >> 12;
        s += addsrc[((r & 15) << 12) + (i & 4095)];
    }
    out[i] = s;
}

// ---------------- QT kernel: QTT/QGT[d][h*16+i] ----------------
__global__ void qt_kernel(const float* __restrict__ q, const float* __restrict__ wkv,
                          const float* __restrict__ g,
                          float* __restrict__ QTT, float* __restrict__ QGT) {
    __shared__ float qs[NL * INNER];   // 48 KB
    for (int i = threadIdx.x; i < NL * INNER; i += 256) qs[i] = q[i];
    __syncthreads();
    int d = blockIdx.x * 32 + (threadIdx.x >> 3);
    int h = threadIdx.x & 7;
    const float* wrow = wkv + (long long)d * 1536 + h * DHH;
    float acc[NL];
    #pragma unroll
    for (int i = 0; i < NL; i++) acc[i] = 0.f;
    for (int dh = 0; dh < DHH; dh++) {
        float w = wrow[dh];
        #pragma unroll
        for (int i = 0; i < NL; i++) acc[i] = fmaf(qs[i * INNER + h * DHH + dh], w, acc[i]);
    }
    float gd = g[d];
    #pragma unroll
    for (int i = 0; i < NL; i++) {
        int ih = h * NL + i;
        QTT[(long long)d * 128 + ih] = acc[i];
        QGT[(long long)d * 128 + ih] = acc[i] * gd;
    }
}

// ---------------- u/v reduction over QTT columns ----------------
__global__ void uv_kernel(const float* __restrict__ QTT, const float* __restrict__ g,
                          const float* __restrict__ b,
                          float* __restrict__ u, float* __restrict__ v) {
    int ih = threadIdx.x;   // 128 threads
    float uu = 0.f, vv = 0.f;
    for (int d = 0; d < DD; d++) {
        float t = QTT[(long long)d * 128 + ih];
        uu = fmaf(t, g[d], uu);
        vv = fmaf(t, b[d], vv);
    }
    u[ih] = uu; v[ih] = vv;
}

// ---------------- bv[e] = b . Wv[:,e] ----------------
__global__ void bv_kernel(const float* __restrict__ b, const float* __restrict__ wkv,
                          float* __restrict__ bv) {
    int e = blockIdx.x * 128 + threadIdx.x;   // 6 blocks x 128
    float a = 0.f;
    for (int d = 0; d < DD; d++) a = fmaf(b[d], wkv[(long long)d * 1536 + INNER + e], a);
    bv[e] = a;
}

// ---------------- attention softmax: block per (bt, h) ----------------
__global__ void attn_kernel(const float* __restrict__ guid, const float* __restrict__ maskf,
                            const float* __restrict__ S0, const float* __restrict__ mean,
                            const float* __restrict__ rstd,
                            const float* __restrict__ u, const float* __restrict__ v,
                            float* __restrict__ C, float* __restrict__ s_out) {
    extern __shared__ float sm[];
    float* sim = sm;                  // 16*1792
    float* rj  = sim + NL * NN;       // 1792
    float* mj  = rj + NN;             // 1792
    float* gu  = mj + NN;             // 1792
    float* mk  = gu + NN;             // 1792
    float* us  = mk + NN;             // 16
    float* vs  = us + NL;             // 16

    int bt = blockIdx.x >> 3;
    int h  = blockIdx.x & 7;
    int tid = threadIdx.x;

    for (int j = tid; j < NN; j += 256) {
        rj[j] = rstd[bt * NN + j];
        mj[j] = mean[bt * NN + j];
        gu[j] = guid[bt * NN + j];
        mk[j] = maskf[bt * NN + j];
    }
    if (tid < NL) { us[tid] = u[h * NL + tid]; vs[tid] = v[h * NL + tid]; }
    __syncthreads();

    // sim0 = SCALE * (r_j * S0 - r_j*m_j*u_ih + v_ih)
    for (int idx = tid; idx < NL * NN; idx += 256) {
        int j = idx >> 4, i = idx & 15;
        float t = S0[((size_t)bt * NN + j) * 128 + h * NL + i];
        sim[i * NN + j] = ATTN_SCALE * (rj[j] * t - rj[j] * mj[j] * us[i] + vs[i]);
    }
    __syncthreads();

    int warp = tid >> 5, lane = tid & 31;
    for (int r = warp; r < NL; r += 8) {
        float* srow = sim + r * NN;
        float m0 = -FLT_MAX;
        for (int j = lane; j < NN; j += 32) m0 = fmaxf(m0, srow[j]);
        #pragma unroll
        for (int o = 16; o; o >>= 1) m0 = fmaxf(m0, __shfl_xor_sync(0xffffffffu, m0, o));

        float m1 = -FLT_MAX;
        for (int j = lane; j < NN; j += 32) {
            float s = srow[j] - m0;
            if (mk[j] != 0.f) s = -3.402823466e38f;
            s *= gu[j];
            srow[j] = s;
            m1 = fmaxf(m1, s);
        }
        #pragma unroll
        for (int o = 16; o; o >>= 1) m1 = fmaxf(m1, __shfl_xor_sync(0xffffffffu, m1, o));

        float sum = 0.f;
        for (int j = lane; j < NN; j += 32) {
            float e = expf(srow[j] - m1);
            srow[j] = e;
            sum += e;
        }
        #pragma unroll
        for (int o = 16; o; o >>= 1) sum += __shfl_xor_sync(0xffffffffu, sum, o);
        float inv = 1.f / sum;

        float sacc = 0.f;
        float* crow = C + ((size_t)bt * 128 + h * NL + r) * NN;
        for (int j = lane; j < NN; j += 32) {
            float a = srow[j] * inv;
            float c = a * rj[j];
            crow[j] = c;
            sacc = fmaf(c, mj[j], sacc);
        }
        #pragma unroll
        for (int o = 16; o; o >>= 1) sacc += __shfl_xor_sync(0xffffffffu, sacc, o);
        if (lane == 0) s_out[bt * 128 + h * NL + r] = sacc;
    }
}

// ---------------- Y[h][bt*16+i][d] = (AX[bt][h*16+i][d] - s)*g[d] ----------------
__global__ void y_kernel(const float* __restrict__ AX, const float* __restrict__ s,
                         const float* __restrict__ g, float* __restrict__ Y) {
    long long idx = (long long)blockIdx.x * 256 + threadIdx.x;  // 16*128*4096
    int d = idx & 4095;
    long long r = idx >> 12;        // bt*128 + h*16 + i
    int bt = (int)(r >> 7);
    int hi = (int)(r & 127);
    int h = hi >> 4, i = hi & 15;
    Y[(((long long)h * LATROWS + bt * NL + i) << 12) + d] = (AX[idx] - s[r]) * g[d];
}

// ---------------- launch ----------------
extern "C" void kernel_launch(void* const* d_in, const int* in_sizes, int n_in,
                              void* d_out, int out_size) {
    const float* x       = (const float*)d_in[0];
    const float* guid    = (const float*)d_in[1];
    const void*  mask    = d_in[2];
    const float* latents = (const float*)d_in[3];
    const float* nm_g    = (const float*)d_in[4];
    const float* nm_b    = (const float*)d_in[5];
    const float* nl_g    = (const float*)d_in[6];
    const float* nl_b    = (const float*)d_in[7];
    const float* wq      = (const float*)d_in[8];
    const float* wkv     = (const float*)d_in[9];
    const float* wout    = (const float*)d_in[10];
    const float* ff_g    = (const float*)d_in[11];
    const float* ff_b    = (const float*)d_in[12];
    const float* w1      = (const float*)d_in[13];
    const float* w2      = (const float*)d_in[14];
    const float* fn_g    = (const float*)d_in[15];
    const float* fn_b    = (const float*)d_in[16];
    float* out = (float*)d_out;

    float *p_mean, *p_rstd, *p_maskf, *p_ql, *p_qp, *p_q, *p_QTT, *p_QGT, *p_u, *p_v, *p_bv;
    float *p_S0p, *p_S0, *p_C, *p_s, *p_AX, *p_Y, *p_Vp, *p_attnv, *p_woutp;
    float *p_lat1, *p_ffln, *p_ff1p, *p_h1, *p_ff2p, *p_lat2;
    cudaGetSymbolAddress((void**)&p_mean, g_mean);
    cudaGetSymbolAddress((void**)&p_rstd, g_rstd);
    cudaGetSymbolAddress((void**)&p_maskf, g_maskf);
    cudaGetSymbolAddress((void**)&p_ql, g_ql);
    cudaGetSymbolAddress((void**)&p_qp, g_qp);
    cudaGetSymbolAddress((void**)&p_q, g_q);
    cudaGetSymbolAddress((void**)&p_QTT, g_QTT);
    cudaGetSymbolAddress((void**)&p_QGT, g_QGT);
    cudaGetSymbolAddress((void**)&p_u, g_u);
    cudaGetSymbolAddress((void**)&p_v, g_v);
    cudaGetSymbolAddress((void**)&p_bv, g_bv);
    cudaGetSymbolAddress((void**)&p_S0p, g_S0p);
    cudaGetSymbolAddress((void**)&p_S0, g_S0);
    cudaGetSymbolAddress((void**)&p_C, g_C);
    cudaGetSymbolAddress((void**)&p_s, g_s);
    cudaGetSymbolAddress((void**)&p_AX, g_AX);
    cudaGetSymbolAddress((void**)&p_Y, g_Y);
    cudaGetSymbolAddress((void**)&p_Vp, g_Vp);
    cudaGetSymbolAddress((void**)&p_attnv, g_attnv);
    cudaGetSymbolAddress((void**)&p_woutp, g_woutp);
    cudaGetSymbolAddress((void**)&p_lat1, g_lat1);
    cudaGetSymbolAddress((void**)&p_ffln, g_ffln);
    cudaGetSymbolAddress((void**)&p_ff1p, g_ff1p);
    cudaGetSymbolAddress((void**)&p_h1, g_h1);
    cudaGetSymbolAddress((void**)&p_ff2p, g_ff2p);
    cudaGetSymbolAddress((void**)&p_lat2, g_lat2);

    // mask + row stats
    detect_mask_kernel<<<1, 32>>>((const unsigned int*)mask);
    convert_mask_kernel<<<(XROWS + 255) / 256, 256>>>(mask, p_maskf);
    row_stats_kernel<<<XROWS, 256>>>(x, p_mean, p_rstd);

    // q = LN(latents) @ wq
    ln_rows_kernel<<<NL, 256>>>(latents, p_ql, nl_g, nl_b);
    gemm2_kernel<<<dim3(6, 1, 8), 256>>>(p_ql, DD, 0, wq, INNER, 0,
                                         p_qp, INNER, 0, NL * INNER,
                                         NL, INNER, DD, 8);
    reduce_kernel<<<(NL * INNER + 255) / 256, 256>>>(p_qp, NL * INNER, 8, p_q, NL * INNER,
                                                     nullptr, 0, nullptr, 1, 0);

    // QT / QG / u / v / bv precompute
    qt_kernel<<<DD / 32, 256>>>(p_q, wkv, nm_g, p_QTT, p_QGT);
    uv_kernel<<<1, 128>>>(p_QTT, nm_g, nm_b, p_u, p_v);
    bv_kernel<<<INNER / 128, 128>>>(nm_b, wkv, p_bv);

    // S0 = x @ QGT   (28672 x 128, K=4096, split 2)
    gemm2_kernel<<<dim3(1, XROWS / GT, 2), 256>>>(x, DD, 0, p_QGT, 128, 0,
                                                  p_S0p, 128, 0, (long long)XROWS * 128,
                                                  XROWS, 128, DD, 2);
    reduce_kernel<<<((long long)XROWS * 128 + 255) / 256, 256>>>(
        p_S0p, (long long)XROWS * 128, 2, p_S0, (long long)XROWS * 128,
        nullptr, 0, nullptr, 1, 0);

    // softmax -> C, s
    {
        int smem = (NL * NN + 4 * NN + 2 * NL) * (int)sizeof(float);
        cudaFuncSetAttribute(attn_kernel, cudaFuncAttributeMaxDynamicSharedMemorySize, smem);
        attn_kernel<<<BT * HH, 256, smem>>>(guid, p_maskf, p_S0, p_mean, p_rstd,
                                            p_u, p_v, p_C, p_s);
    }

    // AX[bt] = C[bt] @ x[bt]   (128 x 4096, K=1792, 16 batches)
    gemm2_kernel<<<dim3(DD / GT, 1, BT), 256>>>(p_C, NN, (long long)128 * NN,
                                                x, DD, (long long)NN * DD,
                                                p_AX, DD, (long long)128 * DD, 0,
                                                128, DD, NN, 1);

    // Y = (AX - s) * g, transposed to head-major
    y_kernel<<<(BT * 128 * DD) / 256, 256>>>(p_AX, p_s, nm_g, p_Y);

    // attnV: per head h: Y[h] (256x4096) @ Wv[:, h*96 : h*96+96], split-K 8
    gemm2_kernel<<<dim3(1, 2, 64), 256>>>(p_Y, DD, (long long)LATROWS * DD,
                                          wkv + INNER, 1536, 96,
                                          p_Vp, INNER, 96, (long long)LATROWS * INNER,
                                          LATROWS, 96, DD, 8);
    reduce_kernel<<<(LATROWS * INNER + 255) / 256, 256>>>(
        p_Vp, (long long)LATROWS * INNER, 8, p_attnv, LATROWS * INNER,
        nullptr, 0, p_bv, INNER, 0);

    // lat1 = attnv @ wout + latents (broadcast)
    gemm2_kernel<<<dim3(DD / GT, 2, 2), 256>>>(p_attnv, INNER, 0, wout, DD, 0,
                                               p_woutp, DD, 0, (long long)LATROWS * DD,
                                               LATROWS, DD, INNER, 2);
    reduce_kernel<<<(LATROWS * DD + 255) / 256, 256>>>(
        p_woutp, (long long)LATROWS * DD, 2, p_lat1, LATROWS * DD,
        latents, 2, nullptr, 1, 0);

    // FF
    ln_rows_kernel<<<LATROWS, 256>>>(p_lat1, p_ffln, ff_g, ff_b);
    gemm2_kernel<<<dim3(FF / GT, 2, 4), 256>>>(p_ffln, DD, 0, w1, FF, 0,
                                               p_ff1p, FF, 0, (long long)LATROWS * FF,
                                               LATROWS, FF, DD, 4);
    reduce_kernel<<<((long long)LATROWS * FF + 255) / 256, 256>>>(
        p_ff1p, (long long)LATROWS * FF, 4, p_h1, (long long)LATROWS * FF,
        nullptr, 0, nullptr, 1, 1);
    gemm2_kernel<<<dim3(DD / GT, 2, 8), 256>>>(p_h1, FF, 0, w2, DD, 0,
                                               p_ff2p, DD, 0, (long long)LATROWS * DD,
                                               LATROWS, DD, FF, 8);
    reduce_kernel<<<(LATROWS * DD + 255) / 256, 256>>>(
        p_ff2p, (long long)LATROWS * DD, 8, p_lat2, LATROWS * DD,
        p_lat1, 1, nullptr, 1, 0);

    // final LN
    ln_rows_kernel<<<LATROWS, 256>>>(p_lat2, out, fn_g, fn_b);
}

// round 5
// speedup vs baseline: 5.2777x; 1.6822x over previous
#include <cuda_runtime.h>
#include <cuda_bf16.h>
#include <cfloat>
#include <math.h>
#include <stdint.h>

// ---------------- problem constants ----------------
#define NN 1792
#define DD 4096
#define HH 8
#define DHH 96
#define INNER 768
#define NL 16
#define FF 8192
#define BT 16
#define XROWS 28672        // BT*NN
#define LATROWS 256        // BT*NL
#define EPS 1e-5f
#define ATTN_SCALE 0.10206207261596577f  // 96^-0.5

// ---------------- scratch (static device memory) ----------------
__device__ float g_mean[XROWS];
__device__ float g_rstd[XROWS];
__device__ float g_maskf[XROWS];
__device__ int   g_mask_kind;

__device__ float g_ql[NL * DD];
__device__ float g_qp[8 * NL * INNER];
__device__ float g_q[NL * INNER];

__device__ float g_QTT[DD * 128];
__device__ float g_u[128];
__device__ float g_v[128];
__device__ float g_bv[INNER];

__device__ float g_S0[(size_t)XROWS * 128];
__device__ float g_C[(size_t)BT * 128 * NN];
__device__ float g_s[BT * 128];
__device__ float g_AX[(size_t)BT * 128 * DD];
__device__ float g_Y[(size_t)HH * LATROWS * DD];

__device__ float g_Vp[8 * (size_t)LATROWS * INNER];
__device__ float g_attnv[LATROWS * INNER];
__device__ float g_woutp[2 * (size_t)LATROWS * DD];
__device__ float g_lat1[LATROWS * DD];
__device__ float g_ffln[LATROWS * DD];
__device__ float g_ff1p[2 * (size_t)LATROWS * FF];
__device__ float g_h1[(size_t)LATROWS * FF];
__device__ float g_ff2p[2 * (size_t)LATROWS * DD];
__device__ float g_lat2[LATROWS * DD];

// bf16 hi/lo pre-split operands (B side of hmma_gemm, [N][K] layout)
__device__ __nv_bfloat16 g_xTh[(size_t)BT * DD * NN];
__device__ __nv_bfloat16 g_xTl[(size_t)BT * DD * NN];
__device__ __nv_bfloat16 g_w1Th[(size_t)FF * DD];
__device__ __nv_bfloat16 g_w1Tl[(size_t)FF * DD];
__device__ __nv_bfloat16 g_w2Th[(size_t)DD * FF];
__device__ __nv_bfloat16 g_w2Tl[(size_t)DD * FF];
__device__ __nv_bfloat16 g_wqTh[INNER * DD];
__device__ __nv_bfloat16 g_wqTl[INNER * DD];
__device__ __nv_bfloat16 g_wvTh[INNER * DD];
__device__ __nv_bfloat16 g_wvTl[INNER * DD];
__device__ __nv_bfloat16 g_woTh[DD * INNER];
__device__ __nv_bfloat16 g_woTl[DD * INNER];
__device__ __nv_bfloat16 g_QGh[128 * DD];
__device__ __nv_bfloat16 g_QGl[128 * DD];

// ---------------- helpers ----------------
__device__ __forceinline__ uint32_t smem_u32(const void* p) {
    uint32_t a;
    asm("{ .reg .u64 t; cvta.to.shared.u64 t, %1; cvt.u32.u64 %0, t; }" : "=r"(a) : "l"(p));
    return a;
}
__device__ __forceinline__ void ldm_x4(uint32_t* r, uint32_t addr) {
    asm volatile("ldmatrix.sync.aligned.m8n8.x4.shared.b16 {%0,%1,%2,%3}, [%4];"
                 : "=r"(r[0]), "=r"(r[1]), "=r"(r[2]), "=r"(r[3]) : "r"(addr));
}
__device__ __forceinline__ void mma16816(float* c, const uint32_t* a, const uint32_t* b) {
    asm volatile(
        "mma.sync.aligned.m16n8k16.row.col.f32.bf16.bf16.f32 "
        "{%0,%1,%2,%3}, {%4,%5,%6,%7}, {%8,%9}, {%0,%1,%2,%3};"
        : "+f"(c[0]), "+f"(c[1]), "+f"(c[2]), "+f"(c[3])
        : "r"(a[0]), "r"(a[1]), "r"(a[2]), "r"(a[3]), "r"(b[0]), "r"(b[1]));
}

// ---------------- mask handling ----------------
__global__ void detect_mask_kernel(const unsigned int* __restrict__ m) {
    if (threadIdx.x == 0) {
        unsigned int orv = 0;
        for (int i = 0; i < XROWS / 4; i++) orv |= m[i];
        g_mask_kind = (orv <= 1u) ? 1 : 0;
    }
}
__global__ void convert_mask_kernel(const void* __restrict__ m, float* __restrict__ mf) {
    int i = blockIdx.x * blockDim.x + threadIdx.x;
    if (i < XROWS) {
        if (g_mask_kind == 1) mf[i] = (float)((const int*)m)[i];
        else                  mf[i] = (float)((const unsigned char*)m)[i];
    }
}

// ---------------- row stats ----------------
__global__ void row_stats_kernel(const float* __restrict__ x,
                                 float* __restrict__ mean, float* __restrict__ rstd) {
    int row = blockIdx.x;
    const float* xr = x + (size_t)row * DD;
    float s = 0.f, q = 0.f;
    for (int i = threadIdx.x; i < DD; i += blockDim.x) { float v = xr[i]; s += v; q += v * v; }
    #pragma unroll
    for (int o = 16; o; o >>= 1) {
        s += __shfl_xor_sync(0xffffffffu, s, o);
        q += __shfl_xor_sync(0xffffffffu, q, o);
    }
    __shared__ float sh_s[8], sh_q[8];
    int w = threadIdx.x >> 5, l = threadIdx.x & 31;
    if (l == 0) { sh_s[w] = s; sh_q[w] = q; }
    __syncthreads();
    if (threadIdx.x == 0) {
        float S = 0.f, Q = 0.f;
        #pragma unroll
        for (int i = 0; i < 8; i++) { S += sh_s[i]; Q += sh_q[i]; }
        float m = S / (float)DD;
        mean[row] = m;
        rstd[row] = rsqrtf(Q / (float)DD - m * m + EPS);
    }
}

// ---------------- full layernorm ----------------
__global__ void ln_rows_kernel(const float* __restrict__ in, float* __restrict__ out,
                               const float* __restrict__ g, const float* __restrict__ b) {
    int row = blockIdx.x;
    const float* xr = in + (size_t)row * DD;
    float s = 0.f, q = 0.f;
    for (int i = threadIdx.x; i < DD; i += blockDim.x) { float v = xr[i]; s += v; q += v * v; }
    #pragma unroll
    for (int o = 16; o; o >>= 1) {
        s += __shfl_xor_sync(0xffffffffu, s, o);
        q += __shfl_xor_sync(0xffffffffu, q, o);
    }
    __shared__ float sh_s[8], sh_q[8];
    __shared__ float m_sh, r_sh;
    int w = threadIdx.x >> 5, l = threadIdx.x & 31;
    if (l == 0) { sh_s[w] = s; sh_q[w] = q; }
    __syncthreads();
    if (threadIdx.x == 0) {
        float S = 0.f, Q = 0.f;
        #pragma unroll
        for (int i = 0; i < 8; i++) { S += sh_s[i]; Q += sh_q[i]; }
        float m = S / (float)DD;
        m_sh = m;
        r_sh = rsqrtf(Q / (float)DD - m * m + EPS);
    }
    __syncthreads();
    float m = m_sh, r = r_sh;
    for (int i = threadIdx.x; i < DD; i += blockDim.x)
        out[(size_t)row * DD + i] = (xr[i] - m) * r * g[i] + b[i];
}

// ---------------- transpose + bf16 hi/lo split ----------------
__global__ void tsplit_kernel(const float* __restrict__ in, long long ldin,
                              long long inbatch, int c0,
                              __nv_bfloat16* __restrict__ oh, __nv_bfloat16* __restrict__ ol,
                              long long ldout, long long outbatch) {
    __shared__ float t[32][33];
    int z = blockIdx.z;
    const float* ib = in + inbatch * z;
    __nv_bfloat16* ohb = oh + outbatch * z;
    __nv_bfloat16* olb = ol + outbatch * z;
    int r0 = blockIdx.y * 32, cc0 = blockIdx.x * 32;
    int tx = threadIdx.x & 31, ty = threadIdx.x >> 5;
    #pragma unroll
    for (int i = 0; i < 4; i++)
        t[ty + 8 * i][tx] = ib[(long long)(r0 + ty + 8 * i) * ldin + c0 + cc0 + tx];
    __syncthreads();
    #pragma unroll
    for (int i = 0; i < 4; i++) {
        float v = t[tx][ty + 8 * i];
        __nv_bfloat16 h = __float2bfloat16(v);
        float r = v - __bfloat162float(h);
        long long o = (long long)(cc0 + ty + 8 * i) * ldout + r0 + tx;
        ohb[o] = h;
        olb[o] = __float2bfloat16(r);
    }
}

// ---------------- HMMA GEMM: C = A[M,K](fp32) @ (Bh+Bl)[N,K]^T (3-term) -------
// 128x128 tile, 8 warps (4Mx2N), m16n8k16 bf16 atoms, fp32 accum.
#define HSTRIDE 40   // bf16 elems per smem row (conflict-free ldmatrix)
__global__ void __launch_bounds__(256, 2)
hmma_gemm(const float* __restrict__ A, long long lda, long long abatch,
          const __nv_bfloat16* __restrict__ Bh, const __nv_bfloat16* __restrict__ Bl,
          long long ldb, long long bbatch,
          float* __restrict__ Cc, long long ldc, long long cbatch, long long csplit,
          int M, int Nvalid, int Ktot, int nsplit) {
    __shared__ __nv_bfloat16 sAh[128 * HSTRIDE], sAl[128 * HSTRIDE];
    __shared__ __nv_bfloat16 sBh[128 * HSTRIDE], sBl[128 * HSTRIDE];

    int tid = threadIdx.x, wid = tid >> 5, lid = tid & 31;
    int z = blockIdx.z;
    int batch = z / nsplit, split = z - batch * nsplit;
    int n0 = blockIdx.x * 128, m0 = blockIdx.y * 128;
    int Kchunk = Ktot / nsplit, kbeg = split * Kchunk;

    const float* Ab = A + abatch * batch;
    const __nv_bfloat16* Bhb = Bh + bbatch * batch;
    const __nv_bfloat16* Blb = Bl + bbatch * batch;
    float* Cb = Cc + cbatch * batch + csplit * split;

    int ar = tid >> 1, ac = (tid & 1) * 16;
    bool aok = (m0 + ar) < M;
    bool bok = (n0 + ar) < Nvalid;
    const float* ap = Ab + (long long)(m0 + ar) * lda + kbeg + ac;
    const __nv_bfloat16* bhp = Bhb + (long long)(n0 + ar) * ldb + kbeg + ac;
    const __nv_bfloat16* blp = Blb + (long long)(n0 + ar) * ldb + kbeg + ac;

    uint32_t sAh_u = smem_u32(sAh), sAl_u = smem_u32(sAl);
    uint32_t sBh_u = smem_u32(sBh), sBl_u = smem_u32(sBl);

    int wm = wid >> 1, wn = wid & 1;
    float acc[2][8][4];
    #pragma unroll
    for (int a1 = 0; a1 < 2; a1++)
        #pragma unroll
        for (int b1 = 0; b1 < 8; b1++)
            #pragma unroll
            for (int c1 = 0; c1 < 4; c1++) acc[a1][b1][c1] = 0.f;

    // ldmatrix lane offsets (bytes), computed once
    uint32_t a_off = (uint32_t)(((lid & 15)) * HSTRIDE + (lid >> 4) * 8) * 2;
    uint32_t b_off = (uint32_t)(((lid & 7) + ((lid >> 4) << 3)) * HSTRIDE + ((lid >> 3) & 1) * 8) * 2;
    uint32_t st_off = (uint32_t)(ar * HSTRIDE + ac) * 2;

    for (int k0 = 0; k0 < Kchunk; k0 += 32) {
        // ---- A: 16 fp32 per thread -> hi/lo bf16 ----
        {
            unsigned hu[8], lu[8];
            #pragma unroll
            for (int q = 0; q < 4; q++) {
                float4 v = make_float4(0.f, 0.f, 0.f, 0.f);
                if (aok) v = *(const float4*)(ap + k0 + q * 4);
                __nv_bfloat162 h0 = __floats2bfloat162_rn(v.x, v.y);
                __nv_bfloat162 h1 = __floats2bfloat162_rn(v.z, v.w);
                float r0 = v.x - __bfloat162float(__low2bfloat16(h0));
                float r1 = v.y - __bfloat162float(__high2bfloat16(h0));
                float r2 = v.z - __bfloat162float(__low2bfloat16(h1));
                float r3 = v.w - __bfloat162float(__high2bfloat16(h1));
                __nv_bfloat162 l0 = __floats2bfloat162_rn(r0, r1);
                __nv_bfloat162 l1 = __floats2bfloat162_rn(r2, r3);
                hu[q * 2]     = *reinterpret_cast<unsigned*>(&h0);
                hu[q * 2 + 1] = *reinterpret_cast<unsigned*>(&h1);
                lu[q * 2]     = *reinterpret_cast<unsigned*>(&l0);
                lu[q * 2 + 1] = *reinterpret_cast<unsigned*>(&l1);
            }
            *(uint4*)((char*)sAh + st_off)      = make_uint4(hu[0], hu[1], hu[2], hu[3]);
            *(uint4*)((char*)sAh + st_off + 16) = make_uint4(hu[4], hu[5], hu[6], hu[7]);
            *(uint4*)((char*)sAl + st_off)      = make_uint4(lu[0], lu[1], lu[2], lu[3]);
            *(uint4*)((char*)sAl + st_off + 16) = make_uint4(lu[4], lu[5], lu[6], lu[7]);
        }
        // ---- B: copy pre-split bf16 ----
        {
            uint4 vh0 = make_uint4(0, 0, 0, 0), vh1 = vh0, vl0 = vh0, vl1 = vh0;
            if (bok) {
                vh0 = *(const uint4*)(bhp + k0);
                vh1 = *(const uint4*)(bhp + k0 + 8);
                vl0 = *(const uint4*)(blp + k0);
                vl1 = *(const uint4*)(blp + k0 + 8);
            }
            *(uint4*)((char*)sBh + st_off)      = vh0;
            *(uint4*)((char*)sBh + st_off + 16) = vh1;
            *(uint4*)((char*)sBl + st_off)      = vl0;
            *(uint4*)((char*)sBl + st_off + 16) = vl1;
        }
        __syncthreads();

        #pragma unroll
        for (int kk = 0; kk < 2; kk++) {
            uint32_t kof = kk * 32;   // 16 bf16 = 32 bytes
            uint32_t ah[2][4], al[2][4];
            #pragma unroll
            for (int mt = 0; mt < 2; mt++) {
                uint32_t ro = (uint32_t)((wm * 32 + mt * 16) * HSTRIDE) * 2 + a_off + kof;
                ldm_x4(ah[mt], sAh_u + ro);
                ldm_x4(al[mt], sAl_u + ro);
            }
            #pragma unroll
            for (int nt2 = 0; nt2 < 4; nt2++) {
                uint32_t bo = (uint32_t)((wn * 64 + nt2 * 16) * HSTRIDE) * 2 + b_off + kof;
                uint32_t bh[4], bl[4];
                ldm_x4(bh, sBh_u + bo);
                ldm_x4(bl, sBl_u + bo);
                #pragma unroll
                for (int mt = 0; mt < 2; mt++) {
                    mma16816(acc[mt][nt2 * 2],     ah[mt], bh);
                    mma16816(acc[mt][nt2 * 2],     ah[mt], bl);
                    mma16816(acc[mt][nt2 * 2],     al[mt], bh);
                    mma16816(acc[mt][nt2 * 2 + 1], ah[mt], bh + 2);
                    mma16816(acc[mt][nt2 * 2 + 1], ah[mt], bl + 2);
                    mma16816(acc[mt][nt2 * 2 + 1], al[mt], bh + 2);
                }
            }
        }
        __syncthreads();
    }

    // ---- epilogue ----
    int rr = lid >> 2, cc2 = (lid & 3) * 2;
    #pragma unroll
    for (int mt = 0; mt < 2; mt++) {
        #pragma unroll
        for (int nt = 0; nt < 8; nt++) {
            int row = m0 + wm * 32 + mt * 16 + rr;
            int col = n0 + wn * 64 + nt * 8 + cc2;
            if (col < Nvalid) {
                if (row < M)
                    *(float2*)(Cb + (long long)row * ldc + col) =
                        make_float2(acc[mt][nt][0], acc[mt][nt][1]);
                if (row + 8 < M)
                    *(float2*)(Cb + (long long)(row + 8) * ldc + col) =
                        make_float2(acc[mt][nt][2], acc[mt][nt][3]);
            }
        }
    }
}

// ---------------- generic split reduce + epilogue ----------------
__global__ void reduce_kernel(const float* __restrict__ parts, long long pstride, int nsplit,
                              float* __restrict__ out, long long n,
                              const float* __restrict__ addsrc, int add_mode,
                              const float* __restrict__ bias, int bias_period,
                              int do_gelu) {
    long long i = (long long)blockIdx.x * 256 + threadIdx.x;
    if (i >= n) return;
    float s = 0.f;
    for (int p = 0; p < nsplit; p++) s += parts[p * pstride + i];
    if (bias) s += bias[i % bias_period];
    if (do_gelu) s = 0.5f * s * (1.0f + erff(s * 0.70710678118654752f));
    if (add_mode == 1) s += addsrc[i];
    else if (add_mode == 2) {
        long long r = i >> 12;
        s += addsrc[((r & 15) << 12) + (i & 4095)];
    }
    out[i] = s;
}

// ---------------- QT precompute ----------------
__global__ void qt_kernel(const float* __restrict__ q, const float* __restrict__ wkv,
                          const float* __restrict__ g,
                          float* __restrict__ QTT,
                          __nv_bfloat16* __restrict__ QGh, __nv_bfloat16* __restrict__ QGl) {
    __shared__ float qs[NL * INNER];
    for (int i = threadIdx.x; i < NL * INNER; i += 256) qs[i] = q[i];
    __syncthreads();
    int d = blockIdx.x * 32 + (threadIdx.x >> 3);
    int h = threadIdx.x & 7;
    const float* wrow = wkv + (long long)d * 1536 + h * DHH;
    float acc[NL];
    #pragma unroll
    for (int i = 0; i < NL; i++) acc[i] = 0.f;
    for (int dh = 0; dh < DHH; dh++) {
        float w = wrow[dh];
        #pragma unroll
        for (int i = 0; i < NL; i++) acc[i] = fmaf(qs[i * INNER + h * DHH + dh], w, acc[i]);
    }
    float gd = g[d];
    #pragma unroll
    for (int i = 0; i < NL; i++) {
        int ih = h * NL + i;
        QTT[(long long)d * 128 + ih] = acc[i];
        float val = acc[i] * gd;
        __nv_bfloat16 hh = __float2bfloat16(val);
        QGh[(long long)ih * DD + d] = hh;
        QGl[(long long)ih * DD + d] = __float2bfloat16(val - __bfloat162float(hh));
    }
}

__global__ void uv_kernel(const float* __restrict__ QTT, const float* __restrict__ g,
                          const float* __restrict__ b,
                          float* __restrict__ u, float* __restrict__ v) {
    int ih = threadIdx.x;
    float uu = 0.f, vv = 0.f;
    for (int d = 0; d < DD; d++) {
        float t = QTT[(long long)d * 128 + ih];
        uu = fmaf(t, g[d], uu);
        vv = fmaf(t, b[d], vv);
    }
    u[ih] = uu; v[ih] = vv;
}

__global__ void bv_kernel(const float* __restrict__ b, const float* __restrict__ wkv,
                          float* __restrict__ bv) {
    int e = blockIdx.x * 128 + threadIdx.x;
    float a = 0.f;
    for (int d = 0; d < DD; d++) a = fmaf(b[d], wkv[(long long)d * 1536 + INNER + e], a);
    bv[e] = a;
}

// ---------------- attention softmax: block per (bt, h) ----------------
__global__ void attn_kernel(const float* __restrict__ guid, const float* __restrict__ maskf,
                            const float* __restrict__ S0, const float* __restrict__ mean,
                            const float* __restrict__ rstd,
                            const float* __restrict__ u, const float* __restrict__ v,
                            float* __restrict__ C, float* __restrict__ s_out) {
    extern __shared__ float sm[];
    float* sim = sm;
    float* rj  = sim + NL * NN;
    float* mj  = rj + NN;
    float* gu  = mj + NN;
    float* mk  = gu + NN;
    float* us  = mk + NN;
    float* vs  = us + NL;

    int bt = blockIdx.x >> 3;
    int h  = blockIdx.x & 7;
    int tid = threadIdx.x;

    for (int j = tid; j < NN; j += 256) {
        rj[j] = rstd[bt * NN + j];
        mj[j] = mean[bt * NN + j];
        gu[j] = guid[bt * NN + j];
        mk[j] = maskf[bt * NN + j];
    }
    if (tid < NL) { us[tid] = u[h * NL + tid]; vs[tid] = v[h * NL + tid]; }
    __syncthreads();

    for (int idx = tid; idx < NL * NN; idx += 256) {
        int j = idx >> 4, i = idx & 15;
        float t = S0[((size_t)bt * NN + j) * 128 + h * NL + i];
        sim[i * NN + j] = ATTN_SCALE * (rj[j] * t - rj[j] * mj[j] * us[i] + vs[i]);
    }
    __syncthreads();

    int warp = tid >> 5, lane = tid & 31;
    for (int r = warp; r < NL; r += 8) {
        float* srow = sim + r * NN;
        float m0 = -FLT_MAX;
        for (int j = lane; j < NN; j += 32) m0 = fmaxf(m0, srow[j]);
        #pragma unroll
        for (int o = 16; o; o >>= 1) m0 = fmaxf(m0, __shfl_xor_sync(0xffffffffu, m0, o));

        float m1 = -FLT_MAX;
        for (int j = lane; j < NN; j += 32) {
            float s = srow[j] - m0;
            if (mk[j] != 0.f) s = -3.402823466e38f;
            s *= gu[j];
            srow[j] = s;
            m1 = fmaxf(m1, s);
        }
        #pragma unroll
        for (int o = 16; o; o >>= 1) m1 = fmaxf(m1, __shfl_xor_sync(0xffffffffu, m1, o));

        float sum = 0.f;
        for (int j = lane; j < NN; j += 32) {
            float e = expf(srow[j] - m1);
            srow[j] = e;
            sum += e;
        }
        #pragma unroll
        for (int o = 16; o; o >>= 1) sum += __shfl_xor_sync(0xffffffffu, sum, o);
        float inv = 1.f / sum;

        float sacc = 0.f;
        float* crow = C + ((size_t)bt * 128 + h * NL + r) * NN;
        for (int j = lane; j < NN; j += 32) {
            float a = srow[j] * inv;
            float c = a * rj[j];
            crow[j] = c;
            sacc = fmaf(c, mj[j], sacc);
        }
        #pragma unroll
        for (int o = 16; o; o >>= 1) sacc += __shfl_xor_sync(0xffffffffu, sacc, o);
        if (lane == 0) s_out[bt * 128 + h * NL + r] = sacc;
    }
}

// ---------------- Y[h][bt*16+i][d] = (AX[bt][h*16+i][d] - s)*g[d] -------------
__global__ void y_kernel(const float* __restrict__ AX, const float* __restrict__ s,
                         const float* __restrict__ g, float* __restrict__ Y) {
    long long idx = (long long)blockIdx.x * 256 + threadIdx.x;
    int d = idx & 4095;
    long long r = idx >> 12;
    int bt = (int)(r >> 7);
    int hi = (int)(r & 127);
    int h = hi >> 4, i = hi & 15;
    Y[(((long long)h * LATROWS + bt * NL + i) << 12) + d] = (AX[idx] - s[r]) * g[d];
}

// ---------------- launch ----------------
extern "C" void kernel_launch(void* const* d_in, const int* in_sizes, int n_in,
                              void* d_out, int out_size) {
    const float* x       = (const float*)d_in[0];
    const float* guid    = (const float*)d_in[1];
    const void*  mask    = d_in[2];
    const float* latents = (const float*)d_in[3];
    const float* nm_g    = (const float*)d_in[4];
    const float* nm_b    = (const float*)d_in[5];
    const float* nl_g    = (const float*)d_in[6];
    const float* nl_b    = (const float*)d_in[7];
    const float* wq      = (const float*)d_in[8];
    const float* wkv     = (const float*)d_in[9];
    const float* wout    = (const float*)d_in[10];
    const float* ff_g    = (const float*)d_in[11];
    const float* ff_b    = (const float*)d_in[12];
    const float* w1      = (const float*)d_in[13];
    const float* w2      = (const float*)d_in[14];
    const float* fn_g    = (const float*)d_in[15];
    const float* fn_b    = (const float*)d_in[16];
    float* out = (float*)d_out;

    float *p_mean, *p_rstd, *p_maskf, *p_ql, *p_qp, *p_q, *p_QTT, *p_u, *p_v, *p_bv;
    float *p_S0, *p_C, *p_s, *p_AX, *p_Y, *p_Vp, *p_attnv, *p_woutp;
    float *p_lat1, *p_ffln, *p_ff1p, *p_h1, *p_ff2p, *p_lat2;
    __nv_bfloat16 *p_xTh, *p_xTl, *p_w1Th, *p_w1Tl, *p_w2Th, *p_w2Tl;
    __nv_bfloat16 *p_wqTh, *p_wqTl, *p_wvTh, *p_wvTl, *p_woTh, *p_woTl, *p_QGh, *p_QGl;
    cudaGetSymbolAddress((void**)&p_mean, g_mean);
    cudaGetSymbolAddress((void**)&p_rstd, g_rstd);
    cudaGetSymbolAddress((void**)&p_maskf, g_maskf);
    cudaGetSymbolAddress((void**)&p_ql, g_ql);
    cudaGetSymbolAddress((void**)&p_qp, g_qp);
    cudaGetSymbolAddress((void**)&p_q, g_q);
    cudaGetSymbolAddress((void**)&p_QTT, g_QTT);
    cudaGetSymbolAddress((void**)&p_u, g_u);
    cudaGetSymbolAddress((void**)&p_v, g_v);
    cudaGetSymbolAddress((void**)&p_bv, g_bv);
    cudaGetSymbolAddress((void**)&p_S0, g_S0);
    cudaGetSymbolAddress((void**)&p_C, g_C);
    cudaGetSymbolAddress((void**)&p_s, g_s);
    cudaGetSymbolAddress((void**)&p_AX, g_AX);
    cudaGetSymbolAddress((void**)&p_Y, g_Y);
    cudaGetSymbolAddress((void**)&p_Vp, g_Vp);
    cudaGetSymbolAddress((void**)&p_attnv, g_attnv);
    cudaGetSymbolAddress((void**)&p_woutp, g_woutp);
    cudaGetSymbolAddress((void**)&p_lat1, g_lat1);
    cudaGetSymbolAddress((void**)&p_ffln, g_ffln);
    cudaGetSymbolAddress((void**)&p_ff1p, g_ff1p);
    cudaGetSymbolAddress((void**)&p_h1, g_h1);
    cudaGetSymbolAddress((void**)&p_ff2p, g_ff2p);
    cudaGetSymbolAddress((void**)&p_lat2, g_lat2);
    cudaGetSymbolAddress((void**)&p_xTh, g_xTh);
    cudaGetSymbolAddress((void**)&p_xTl, g_xTl);
    cudaGetSymbolAddress((void**)&p_w1Th, g_w1Th);
    cudaGetSymbolAddress((void**)&p_w1Tl, g_w1Tl);
    cudaGetSymbolAddress((void**)&p_w2Th, g_w2Th);
    cudaGetSymbolAddress((void**)&p_w2Tl, g_w2Tl);
    cudaGetSymbolAddress((void**)&p_wqTh, g_wqTh);
    cudaGetSymbolAddress((void**)&p_wqTl, g_wqTl);
    cudaGetSymbolAddress((void**)&p_wvTh, g_wvTh);
    cudaGetSymbolAddress((void**)&p_wvTl, g_wvTl);
    cudaGetSymbolAddress((void**)&p_woTh, g_woTh);
    cudaGetSymbolAddress((void**)&p_woTl, g_woTl);
    cudaGetSymbolAddress((void**)&p_QGh, g_QGh);
    cudaGetSymbolAddress((void**)&p_QGl, g_QGl);

    // mask + row stats
    detect_mask_kernel<<<1, 32>>>((const unsigned int*)mask);
    convert_mask_kernel<<<(XROWS + 255) / 256, 256>>>(mask, p_maskf);
    row_stats_kernel<<<XROWS, 256>>>(x, p_mean, p_rstd);

    // transposes + hi/lo splits
    tsplit_kernel<<<dim3(DD / 32, NN / 32, BT), 256>>>(x, DD, (long long)NN * DD, 0,
                                                       p_xTh, p_xTl, NN, (long long)DD * NN);
    tsplit_kernel<<<dim3(INNER / 32, DD / 32, 1), 256>>>(wq, INNER, 0, 0,
                                                         p_wqTh, p_wqTl, DD, 0);
    tsplit_kernel<<<dim3(INNER / 32, DD / 32, 1), 256>>>(wkv, 1536, 0, INNER,
                                                         p_wvTh, p_wvTl, DD, 0);
    tsplit_kernel<<<dim3(DD / 32, INNER / 32, 1), 256>>>(wout, DD, 0, 0,
                                                         p_woTh, p_woTl, INNER, 0);
    tsplit_kernel<<<dim3(FF / 32, DD / 32, 1), 256>>>(w1, FF, 0, 0,
                                                      p_w1Th, p_w1Tl, DD, 0);
    tsplit_kernel<<<dim3(DD / 32, FF / 32, 1), 256>>>(w2, DD, 0, 0,
                                                      p_w2Th, p_w2Tl, FF, 0);

    // q = LN(latents) @ wq  (split-K 8)
    ln_rows_kernel<<<NL, 256>>>(latents, p_ql, nl_g, nl_b);
    hmma_gemm<<<dim3(6, 1, 8), 256>>>(p_ql, DD, 0, p_wqTh, p_wqTl, DD, 0,
                                      p_qp, INNER, 0, NL * INNER,
                                      NL, INNER, DD, 8);
    reduce_kernel<<<(NL * INNER + 255) / 256, 256>>>(p_qp, NL * INNER, 8, p_q, NL * INNER,
                                                     nullptr, 0, nullptr, 1, 0);

    // QT / QG / u / v / bv
    qt_kernel<<<DD / 32, 256>>>(p_q, wkv, nm_g, p_QTT, p_QGh, p_QGl);
    uv_kernel<<<1, 128>>>(p_QTT, nm_g, nm_b, p_u, p_v);
    bv_kernel<<<INNER / 128, 128>>>(nm_b, wkv, p_bv);

    // S0 = x @ QG^T   (28672 x 128, K=4096)
    hmma_gemm<<<dim3(1, XROWS / 128, 1), 256>>>(x, DD, 0, p_QGh, p_QGl, DD, 0,
                                                p_S0, 128, 0, 0,
                                                XROWS, 128, DD, 1);

    // softmax -> C, s
    {
        int smemb = (NL * NN + 4 * NN + 2 * NL) * (int)sizeof(float);
        cudaFuncSetAttribute(attn_kernel, cudaFuncAttributeMaxDynamicSharedMemorySize, smemb);
        attn_kernel<<<BT * HH, 256, smemb>>>(guid, p_maskf, p_S0, p_mean, p_rstd,
                                             p_u, p_v, p_C, p_s);
    }

    // AX[bt] = C[bt] @ xT[bt]^T   (128 x 4096, K=1792, 16 batches)
    hmma_gemm<<<dim3(DD / 128, 1, BT), 256>>>(
        p_C, NN, (long long)128 * NN, p_xTh, p_xTl, NN, (long long)DD * NN,
        p_AX, DD, (long long)128 * DD, 0, 128, DD, NN, 1);

    // Y = (AX - s) * g, head-major
    y_kernel<<<(BT * 128 * DD) / 256, 256>>>(p_AX, p_s, nm_g, p_Y);

    // attnV: per head h: Y[h] (256x4096) @ Wv_h^T, split-K 8
    hmma_gemm<<<dim3(1, 2, HH * 8), 256>>>(
        p_Y, DD, (long long)LATROWS * DD, p_wvTh, p_wvTl, DD, (long long)96 * DD,
        p_Vp, INNER, 96, (long long)LATROWS * INNER, LATROWS, 96, DD, 8);
    reduce_kernel<<<(LATROWS * INNER + 255) / 256, 256>>>(
        p_Vp, (long long)LATROWS * INNER, 8, p_attnv, LATROWS * INNER,
        nullptr, 0, p_bv, INNER, 0);

    // lat1 = attnv @ wout + latents (split-K 2)
    hmma_gemm<<<dim3(DD / 128, 2, 2), 256>>>(
        p_attnv, INNER, 0, p_woTh, p_woTl, INNER, 0,
        p_woutp, DD, 0, (long long)LATROWS * DD, LATROWS, DD, INNER, 2);
    reduce_kernel<<<(LATROWS * DD + 255) / 256, 256>>>(
        p_woutp, (long long)LATROWS * DD, 2, p_lat1, LATROWS * DD,
        latents, 2, nullptr, 1, 0);

    // FF
    ln_rows_kernel<<<LATROWS, 256>>>(p_lat1, p_ffln, ff_g, ff_b);
    hmma_gemm<<<dim3(FF / 128, 2, 2), 256>>>(
        p_ffln, DD, 0, p_w1Th, p_w1Tl, DD, 0,
        p_ff1p, FF, 0, (long long)LATROWS * FF, LATROWS, FF, DD, 2);
    reduce_kernel<<<((long long)LATROWS * FF + 255) / 256, 256>>>(
        p_ff1p, (long long)LATROWS * FF, 2, p_h1, (long long)LATROWS * FF,
        nullptr, 0, nullptr, 1, 1);
    hmma_gemm<<<dim3(DD / 128, 2, 2), 256>>>(
        p_h1, FF, 0, p_w2Th, p_w2Tl, FF, 0,
        p_ff2p, DD, 0, (long long)LATROWS * DD, LATROWS, DD, FF, 2);
    reduce_kernel<<<(LATROWS * DD + 255) / 256, 256>>>(
        p_ff2p, (long long)LATROWS * DD, 2, p_lat2, LATROWS * DD,
        p_lat1, 1, nullptr, 1, 0);

    // final LN
    ln_rows_kernel<<<LATROWS, 256>>>(p_lat2, out, fn_g, fn_b);
}

// round 6
// speedup vs baseline: 6.5076x; 1.2330x over previous
#include <cuda_runtime.h>
#include <cuda_bf16.h>
#include <cfloat>
#include <math.h>
#include <stdint.h>

// ---------------- problem constants ----------------
#define NN 1792
#define DD 4096
#define HH 8
#define DHH 96
#define INNER 768
#define NL 16
#define FF 8192
#define BT 16
#define XROWS 28672        // BT*NN
#define LATROWS 256        // BT*NL
#define EPS 1e-5f
#define ATTN_SCALE 0.10206207261596577f  // 96^-0.5

// ---------------- scratch (static device memory) ----------------
__device__ float g_mean[XROWS];
__device__ float g_rstd[XROWS];
__device__ int   g_mask_kind;

__device__ float g_ql[NL * DD];
__device__ float g_qp[8 * NL * INNER];
__device__ float g_q[NL * INNER];

__device__ float g_QTT[DD * 128];
__device__ float g_QG[DD * 128];       // B operand of S0: [K=d][N=128]
__device__ float g_u[128];
__device__ float g_v[128];
__device__ float g_bv[INNER];

__device__ float g_S0[(size_t)XROWS * 128];
__device__ float g_C[(size_t)BT * 128 * NN];
__device__ float g_s[BT * 128];
__device__ float g_AX[(size_t)BT * 128 * DD];
__device__ float g_Y[(size_t)HH * LATROWS * DD];

__device__ float g_Vp[8 * (size_t)LATROWS * INNER];
__device__ float g_attnv[LATROWS * INNER];
__device__ float g_woutp[2 * (size_t)LATROWS * DD];
__device__ float g_lat1[LATROWS * DD];
__device__ float g_ffln[LATROWS * DD];
__device__ float g_ff1p[2 * (size_t)LATROWS * FF];
__device__ float g_h1[(size_t)LATROWS * FF];
__device__ float g_ff2p[2 * (size_t)LATROWS * DD];
__device__ float g_lat2[LATROWS * DD];

// ---------------- helpers ----------------
__device__ __forceinline__ uint32_t smem_u32(const void* p) {
    uint32_t a;
    asm("{ .reg .u64 t; cvta.to.shared.u64 t, %1; cvt.u32.u64 %0, t; }" : "=r"(a) : "l"(p));
    return a;
}
__device__ __forceinline__ void ldm_x4(uint32_t* r, uint32_t addr) {
    asm volatile("ldmatrix.sync.aligned.m8n8.x4.shared.b16 {%0,%1,%2,%3}, [%4];"
                 : "=r"(r[0]), "=r"(r[1]), "=r"(r[2]), "=r"(r[3]) : "r"(addr));
}
__device__ __forceinline__ void ldm_x4t(uint32_t* r, uint32_t addr) {
    asm volatile("ldmatrix.sync.aligned.m8n8.x4.trans.shared.b16 {%0,%1,%2,%3}, [%4];"
                 : "=r"(r[0]), "=r"(r[1]), "=r"(r[2]), "=r"(r[3]) : "r"(addr));
}
__device__ __forceinline__ void mma16816(float* c, const uint32_t* a, const uint32_t* b) {
    asm volatile(
        "mma.sync.aligned.m16n8k16.row.col.f32.bf16.bf16.f32 "
        "{%0,%1,%2,%3}, {%4,%5,%6,%7}, {%8,%9}, {%0,%1,%2,%3};"
        : "+f"(c[0]), "+f"(c[1]), "+f"(c[2]), "+f"(c[3])
        : "r"(a[0]), "r"(a[1]), "r"(a[2]), "r"(a[3]), "r"(b[0]), "r"(b[1]));
}

// ---------------- mask kind detection (parallel) ----------------
__global__ void detect_mask_kernel(const unsigned int* __restrict__ m) {
    __shared__ unsigned int sh[8];
    unsigned int orv = 0;
    for (int i = threadIdx.x; i < XROWS / 4; i += 256) orv |= m[i];
    #pragma unroll
    for (int o = 16; o; o >>= 1) orv |= __shfl_xor_sync(0xffffffffu, orv, o);
    int w = threadIdx.x >> 5;
    if ((threadIdx.x & 31) == 0) sh[w] = orv;
    __syncthreads();
    if (threadIdx.x == 0) {
        unsigned int t = 0;
        #pragma unroll
        for (int i = 0; i < 8; i++) t |= sh[i];
        g_mask_kind = (t <= 1u) ? 1 : 0;
    }
}

// ---------------- full layernorm ----------------
__global__ void ln_rows_kernel(const float* __restrict__ in, float* __restrict__ out,
                               const float* __restrict__ g, const float* __restrict__ b) {
    int row = blockIdx.x;
    const float* xr = in + (size_t)row * DD;
    float s = 0.f, q = 0.f;
    for (int i = threadIdx.x; i < DD; i += blockDim.x) { float v = xr[i]; s += v; q += v * v; }
    #pragma unroll
    for (int o = 16; o; o >>= 1) {
        s += __shfl_xor_sync(0xffffffffu, s, o);
        q += __shfl_xor_sync(0xffffffffu, q, o);
    }
    __shared__ float sh_s[8], sh_q[8];
    __shared__ float m_sh, r_sh;
    int w = threadIdx.x >> 5, l = threadIdx.x & 31;
    if (l == 0) { sh_s[w] = s; sh_q[w] = q; }
    __syncthreads();
    if (threadIdx.x == 0) {
        float S = 0.f, Q = 0.f;
        #pragma unroll
        for (int i = 0; i < 8; i++) { S += sh_s[i]; Q += sh_q[i]; }
        float m = S / (float)DD;
        m_sh = m;
        r_sh = rsqrtf(Q / (float)DD - m * m + EPS);
    }
    __syncthreads();
    float m = m_sh, r = r_sh;
    for (int i = threadIdx.x; i < DD; i += blockDim.x)
        out[(size_t)row * DD + i] = (xr[i] - m) * r * g[i] + b[i];
}

// ---------------- HMMA GEMM: C = A[M,K](fp32) @ B[K,N](fp32), 3-term hi/lo ---
// A row-major [M][K]; B row-major [K][N] (trans-B fragments via ldmatrix.trans).
// Both split to bf16 hi/lo in-kernel. Optional fused row stats over A
// (requires nsplit==1, full-K coverage, gridDim.x==1 handled by caller).
#define HSTRIDE 40    // A smem row stride (bf16)
#define BST 136       // B smem row stride (bf16): 272B = 17 segments, conflict-free
__global__ void __launch_bounds__(256, 2)
hmma_gemm(const float* __restrict__ A, long long lda, long long abatch,
          const float* __restrict__ B, long long ldb, long long bbatch,
          float* __restrict__ Cc, long long ldc, long long cbatch, long long csplit,
          int M, int Nvalid, int Ktot, int nsplit,
          float* __restrict__ stats_mean, float* __restrict__ stats_rstd) {
    __shared__ __nv_bfloat16 sAh[128 * HSTRIDE], sAl[128 * HSTRIDE];
    __shared__ __nv_bfloat16 sBh[32 * BST], sBl[32 * BST];

    int tid = threadIdx.x, wid = tid >> 5, lid = tid & 31;
    int z = blockIdx.z;
    int batch = z / nsplit, split = z - batch * nsplit;
    int n0 = blockIdx.x * 128, m0 = blockIdx.y * 128;
    int Kchunk = Ktot / nsplit, kbeg = split * Kchunk;

    const float* Ab = A + abatch * batch;
    const float* Bb = B + bbatch * batch;
    float* Cb = Cc + cbatch * batch + csplit * split;

    // A load mapping: thread -> (row ar, 16 cols at ac)
    int ar = tid >> 1, ac = (tid & 1) * 16;
    bool aok = (m0 + ar) < M;
    const float* ap = Ab + (long long)(m0 + ar) * lda + kbeg + ac;
    // B load mapping: thread -> (k-row kb, 16 cols at cb)
    int kb = tid >> 3, cb = (tid & 7) * 16;
    const float* bp = Bb + (long long)(kbeg + kb) * ldb + n0 + cb;

    uint32_t sAh_u = smem_u32(sAh), sAl_u = smem_u32(sAl);
    uint32_t sBh_u = smem_u32(sBh), sBl_u = smem_u32(sBl);

    int wm = wid >> 1, wn = wid & 1;
    float acc[2][8][4];
    #pragma unroll
    for (int a1 = 0; a1 < 2; a1++)
        #pragma unroll
        for (int b1 = 0; b1 < 8; b1++)
            #pragma unroll
            for (int c1 = 0; c1 < 4; c1++) acc[a1][b1][c1] = 0.f;

    uint32_t a_off = (uint32_t)(((lid & 15)) * HSTRIDE + (lid >> 4) * 8) * 2;
    uint32_t b_off = (uint32_t)(((lid & 15)) * BST + ((lid >> 4) << 3)) * 2;
    uint32_t ast_off = (uint32_t)(ar * HSTRIDE + ac) * 2;
    uint32_t bst_off = (uint32_t)(kb * BST + cb) * 2;

    bool do_stats = (stats_mean != nullptr);
    float ssum = 0.f, sqsum = 0.f;

    for (int k0 = 0; k0 < Kchunk; k0 += 32) {
        // ---- A: 16 fp32 per thread -> hi/lo bf16 ----
        {
            unsigned hu[8], lu[8];
            #pragma unroll
            for (int q = 0; q < 4; q++) {
                float4 v = make_float4(0.f, 0.f, 0.f, 0.f);
                if (aok) v = *(const float4*)(ap + k0 + q * 4);
                if (do_stats) {
                    ssum += v.x + v.y + v.z + v.w;
                    sqsum += v.x * v.x + v.y * v.y + v.z * v.z + v.w * v.w;
                }
                __nv_bfloat162 h0 = __floats2bfloat162_rn(v.x, v.y);
                __nv_bfloat162 h1 = __floats2bfloat162_rn(v.z, v.w);
                float r0 = v.x - __bfloat162float(__low2bfloat16(h0));
                float r1 = v.y - __bfloat162float(__high2bfloat16(h0));
                float r2 = v.z - __bfloat162float(__low2bfloat16(h1));
                float r3 = v.w - __bfloat162float(__high2bfloat16(h1));
                __nv_bfloat162 l0 = __floats2bfloat162_rn(r0, r1);
                __nv_bfloat162 l1 = __floats2bfloat162_rn(r2, r3);
                hu[q * 2]     = *reinterpret_cast<unsigned*>(&h0);
                hu[q * 2 + 1] = *reinterpret_cast<unsigned*>(&h1);
                lu[q * 2]     = *reinterpret_cast<unsigned*>(&l0);
                lu[q * 2 + 1] = *reinterpret_cast<unsigned*>(&l1);
            }
            *(uint4*)((char*)sAh + ast_off)      = make_uint4(hu[0], hu[1], hu[2], hu[3]);
            *(uint4*)((char*)sAh + ast_off + 16) = make_uint4(hu[4], hu[5], hu[6], hu[7]);
            *(uint4*)((char*)sAl + ast_off)      = make_uint4(lu[0], lu[1], lu[2], lu[3]);
            *(uint4*)((char*)sAl + ast_off + 16) = make_uint4(lu[4], lu[5], lu[6], lu[7]);
        }
        // ---- B: 16 fp32 per thread (row-major [K][N]) -> hi/lo bf16 ----
        {
            const float* bsrc = bp + (long long)k0 * ldb;
            unsigned hu[8], lu[8];
            #pragma unroll
            for (int q = 0; q < 4; q++) {
                float4 v = make_float4(0.f, 0.f, 0.f, 0.f);
                if (n0 + cb + q * 4 < Nvalid) v = *(const float4*)(bsrc + q * 4);
                __nv_bfloat162 h0 = __floats2bfloat162_rn(v.x, v.y);
                __nv_bfloat162 h1 = __floats2bfloat162_rn(v.z, v.w);
                float r0 = v.x - __bfloat162float(__low2bfloat16(h0));
                float r1 = v.y - __bfloat162float(__high2bfloat16(h0));
                float r2 = v.z - __bfloat162float(__low2bfloat16(h1));
                float r3 = v.w - __bfloat162float(__high2bfloat16(h1));
                __nv_bfloat162 l0 = __floats2bfloat162_rn(r0, r1);
                __nv_bfloat162 l1 = __floats2bfloat162_rn(r2, r3);
                hu[q * 2]     = *reinterpret_cast<unsigned*>(&h0);
                hu[q * 2 + 1] = *reinterpret_cast<unsigned*>(&h1);
                lu[q * 2]     = *reinterpret_cast<unsigned*>(&l0);
                lu[q * 2 + 1] = *reinterpret_cast<unsigned*>(&l1);
            }
            *(uint4*)((char*)sBh + bst_off)      = make_uint4(hu[0], hu[1], hu[2], hu[3]);
            *(uint4*)((char*)sBh + bst_off + 16) = make_uint4(hu[4], hu[5], hu[6], hu[7]);
            *(uint4*)((char*)sBl + bst_off)      = make_uint4(lu[0], lu[1], lu[2], lu[3]);
            *(uint4*)((char*)sBl + bst_off + 16) = make_uint4(lu[4], lu[5], lu[6], lu[7]);
        }
        __syncthreads();

        #pragma unroll
        for (int kk = 0; kk < 2; kk++) {
            uint32_t ah[2][4], al[2][4];
            #pragma unroll
            for (int mt = 0; mt < 2; mt++) {
                uint32_t ro = (uint32_t)((wm * 32 + mt * 16) * HSTRIDE) * 2 + a_off + kk * 32;
                ldm_x4(ah[mt], sAh_u + ro);
                ldm_x4(al[mt], sAl_u + ro);
            }
            #pragma unroll
            for (int nt2 = 0; nt2 < 4; nt2++) {
                uint32_t bo = (uint32_t)(kk * 16 * BST) * 2 + b_off
                            + (uint32_t)((wn * 64 + nt2 * 16) * 2);
                uint32_t bh[4], bl[4];
                ldm_x4t(bh, sBh_u + bo);
                ldm_x4t(bl, sBl_u + bo);
                #pragma unroll
                for (int mt = 0; mt < 2; mt++) {
                    mma16816(acc[mt][nt2 * 2],     ah[mt], bh);
                    mma16816(acc[mt][nt2 * 2],     ah[mt], bl);
                    mma16816(acc[mt][nt2 * 2],     al[mt], bh);
                    mma16816(acc[mt][nt2 * 2 + 1], ah[mt], bh + 2);
                    mma16816(acc[mt][nt2 * 2 + 1], ah[mt], bl + 2);
                    mma16816(acc[mt][nt2 * 2 + 1], al[mt], bh + 2);
                }
            }
        }
        __syncthreads();
    }

    // ---- fused row stats (S0 launch only: nsplit=1, gridDim.x=1, full K) ----
    if (do_stats && aok) {
        float s2 = ssum + __shfl_xor_sync(0xffffffffu, ssum, 1);
        float q2 = sqsum + __shfl_xor_sync(0xffffffffu, sqsum, 1);
        if ((tid & 1) == 0) {
            float m = s2 / (float)DD;
            stats_mean[m0 + ar] = m;
            stats_rstd[m0 + ar] = rsqrtf(q2 / (float)DD - m * m + EPS);
        }
    }

    // ---- epilogue ----
    int rr = lid >> 2, cc2 = (lid & 3) * 2;
    #pragma unroll
    for (int mt = 0; mt < 2; mt++) {
        #pragma unroll
        for (int nt = 0; nt < 8; nt++) {
            int row = m0 + wm * 32 + mt * 16 + rr;
            int col = n0 + wn * 64 + nt * 8 + cc2;
            if (col < Nvalid) {
                if (row < M)
                    *(float2*)(Cb + (long long)row * ldc + col) =
                        make_float2(acc[mt][nt][0], acc[mt][nt][1]);
                if (row + 8 < M)
                    *(float2*)(Cb + (long long)(row + 8) * ldc + col) =
                        make_float2(acc[mt][nt][2], acc[mt][nt][3]);
            }
        }
    }
}

// ---------------- generic split reduce + epilogue ----------------
__global__ void reduce_kernel(const float* __restrict__ parts, long long pstride, int nsplit,
                              float* __restrict__ out, long long n,
                              const float* __restrict__ addsrc, int add_mode,
                              const float* __restrict__ bias, int bias_period,
                              int do_gelu) {
    long long i = (long long)blockIdx.x * 256 + threadIdx.x;
    if (i >= n) return;
    float s = 0.f;
    for (int p = 0; p < nsplit; p++) s += parts[p * pstride + i];
    if (bias) s += bias[i % bias_period];
    if (do_gelu) s = 0.5f * s * (1.0f + erff(s * 0.70710678118654752f));
    if (add_mode == 1) s += addsrc[i];
    else if (add_mode == 2) {
        long long r = i >> 12;
        s += addsrc[((r & 15) << 12) + (i & 4095)];
    }
    out[i] = s;
}

// ---------------- QT precompute: QTT & QG fp32 [d][128] ----------------
__global__ void qt_kernel(const float* __restrict__ q, const float* __restrict__ wkv,
                          const float* __restrict__ g,
                          float* __restrict__ QTT, float* __restrict__ QG) {
    __shared__ float qs[NL * INNER];
    for (int i = threadIdx.x; i < NL * INNER; i += 256) qs[i] = q[i];
    __syncthreads();
    int d = blockIdx.x * 32 + (threadIdx.x >> 3);
    int h = threadIdx.x & 7;
    const float* wrow = wkv + (long long)d * 1536 + h * DHH;
    float acc[NL];
    #pragma unroll
    for (int i = 0; i < NL; i++) acc[i] = 0.f;
    for (int dh = 0; dh < DHH; dh++) {
        float w = wrow[dh];
        #pragma unroll
        for (int i = 0; i < NL; i++) acc[i] = fmaf(qs[i * INNER + h * DHH + dh], w, acc[i]);
    }
    float gd = g[d];
    #pragma unroll
    for (int i = 0; i < NL; i++) {
        int ih = h * NL + i;
        QTT[(long long)d * 128 + ih] = acc[i];
        QG[(long long)d * 128 + ih] = acc[i] * gd;
    }
}

__global__ void uv_kernel(const float* __restrict__ QTT, const float* __restrict__ g,
                          const float* __restrict__ b,
                          float* __restrict__ u, float* __restrict__ v) {
    int ih = threadIdx.x;
    float uu = 0.f, vv = 0.f;
    for (int d = 0; d < DD; d++) {
        float t = QTT[(long long)d * 128 + ih];
        uu = fmaf(t, g[d], uu);
        vv = fmaf(t, b[d], vv);
    }
    u[ih] = uu; v[ih] = vv;
}

__global__ void bv_kernel(const float* __restrict__ b, const float* __restrict__ wkv,
                          float* __restrict__ bv) {
    int e = blockIdx.x * 128 + threadIdx.x;
    float a = 0.f;
    for (int d = 0; d < DD; d++) a = fmaf(b[d], wkv[(long long)d * 1536 + INNER + e], a);
    bv[e] = a;
}

// ---------------- attention softmax: block per (bt, h) ----------------
__global__ void attn_kernel(const float* __restrict__ guid, const void* __restrict__ mask,
                            const float* __restrict__ S0, const float* __restrict__ mean,
                            const float* __restrict__ rstd,
                            const float* __restrict__ u, const float* __restrict__ v,
                            float* __restrict__ C, float* __restrict__ s_out) {
    extern __shared__ float sm[];
    float* sim = sm;
    float* rj  = sim + NL * NN;
    float* mj  = rj + NN;
    float* gu  = mj + NN;
    float* mk  = gu + NN;
    float* us  = mk + NN;
    float* vs  = us + NL;

    int bt = blockIdx.x >> 3;
    int h  = blockIdx.x & 7;
    int tid = threadIdx.x;
    int kind = g_mask_kind;

    for (int j = tid; j < NN; j += 256) {
        rj[j] = rstd[bt * NN + j];
        mj[j] = mean[bt * NN + j];
        gu[j] = guid[bt * NN + j];
        mk[j] = (kind == 1) ? (float)((const int*)mask)[bt * NN + j]
                            : (float)((const unsigned char*)mask)[bt * NN + j];
    }
    if (tid < NL) { us[tid] = u[h * NL + tid]; vs[tid] = v[h * NL + tid]; }
    __syncthreads();

    for (int idx = tid; idx < NL * NN; idx += 256) {
        int j = idx >> 4, i = idx & 15;
        float t = S0[((size_t)bt * NN + j) * 128 + h * NL + i];
        sim[i * NN + j] = ATTN_SCALE * (rj[j] * t - rj[j] * mj[j] * us[i] + vs[i]);
    }
    __syncthreads();

    int warp = tid >> 5, lane = tid & 31;
    for (int r = warp; r < NL; r += 8) {
        float* srow = sim + r * NN;
        float m0 = -FLT_MAX;
        for (int j = lane; j < NN; j += 32) m0 = fmaxf(m0, srow[j]);
        #pragma unroll
        for (int o = 16; o; o >>= 1) m0 = fmaxf(m0, __shfl_xor_sync(0xffffffffu, m0, o));

        float m1 = -FLT_MAX;
        for (int j = lane; j < NN; j += 32) {
            float s = srow[j] - m0;
            if (mk[j] != 0.f) s = -3.402823466e38f;
            s *= gu[j];
            srow[j] = s;
            m1 = fmaxf(m1, s);
        }
        #pragma unroll
        for (int o = 16; o; o >>= 1) m1 = fmaxf(m1, __shfl_xor_sync(0xffffffffu, m1, o));

        float sum = 0.f;
        for (int j = lane; j < NN; j += 32) {
            float e = expf(srow[j] - m1);
            srow[j] = e;
            sum += e;
        }
        #pragma unroll
        for (int o = 16; o; o >>= 1) sum += __shfl_xor_sync(0xffffffffu, sum, o);
        float inv = 1.f / sum;

        float sacc = 0.f;
        float* crow = C + ((size_t)bt * 128 + h * NL + r) * NN;
        for (int j = lane; j < NN; j += 32) {
            float a = srow[j] * inv;
            float c = a * rj[j];
            crow[j] = c;
            sacc = fmaf(c, mj[j], sacc);
        }
        #pragma unroll
        for (int o = 16; o; o >>= 1) sacc += __shfl_xor_sync(0xffffffffu, sacc, o);
        if (lane == 0) s_out[bt * 128 + h * NL + r] = sacc;
    }
}

// ---------------- Y[h][bt*16+i][d] = (AX[bt][h*16+i][d] - s)*g[d] -------------
__global__ void y_kernel(const float* __restrict__ AX, const float* __restrict__ s,
                         const float* __restrict__ g, float* __restrict__ Y) {
    long long idx = (long long)blockIdx.x * 256 + threadIdx.x;
    int d = idx & 4095;
    long long r = idx >> 12;
    int bt = (int)(r >> 7);
    int hi = (int)(r & 127);
    int h = hi >> 4, i = hi & 15;
    Y[(((long long)h * LATROWS + bt * NL + i) << 12) + d] = (AX[idx] - s[r]) * g[d];
}

// ---------------- launch ----------------
extern "C" void kernel_launch(void* const* d_in, const int* in_sizes, int n_in,
                              void* d_out, int out_size) {
    const float* x       = (const float*)d_in[0];
    const float* guid    = (const float*)d_in[1];
    const void*  mask    = d_in[2];
    const float* latents = (const float*)d_in[3];
    const float* nm_g    = (const float*)d_in[4];
    const float* nm_b    = (const float*)d_in[5];
    const float* nl_g    = (const float*)d_in[6];
    const float* nl_b    = (const float*)d_in[7];
    const float* wq      = (const float*)d_in[8];
    const float* wkv     = (const float*)d_in[9];
    const float* wout    = (const float*)d_in[10];
    const float* ff_g    = (const float*)d_in[11];
    const float* ff_b    = (const float*)d_in[12];
    const float* w1      = (const float*)d_in[13];
    const float* w2      = (const float*)d_in[14];
    const float* fn_g    = (const float*)d_in[15];
    const float* fn_b    = (const float*)d_in[16];
    float* out = (float*)d_out;

    float *p_mean, *p_rstd, *p_ql, *p_qp, *p_q, *p_QTT, *p_QG, *p_u, *p_v, *p_bv;
    float *p_S0, *p_C, *p_s, *p_AX, *p_Y, *p_Vp, *p_attnv, *p_woutp;
    float *p_lat1, *p_ffln, *p_ff1p, *p_h1, *p_ff2p, *p_lat2;
    cudaGetSymbolAddress((void**)&p_mean, g_mean);
    cudaGetSymbolAddress((void**)&p_rstd, g_rstd);
    cudaGetSymbolAddress((void**)&p_ql, g_ql);
    cudaGetSymbolAddress((void**)&p_qp, g_qp);
    cudaGetSymbolAddress((void**)&p_q, g_q);
    cudaGetSymbolAddress((void**)&p_QTT, g_QTT);
    cudaGetSymbolAddress((void**)&p_QG, g_QG);
    cudaGetSymbolAddress((void**)&p_u, g_u);
    cudaGetSymbolAddress((void**)&p_v, g_v);
    cudaGetSymbolAddress((void**)&p_bv, g_bv);
    cudaGetSymbolAddress((void**)&p_S0, g_S0);
    cudaGetSymbolAddress((void**)&p_C, g_C);
    cudaGetSymbolAddress((void**)&p_s, g_s);
    cudaGetSymbolAddress((void**)&p_AX, g_AX);
    cudaGetSymbolAddress((void**)&p_Y, g_Y);
    cudaGetSymbolAddress((void**)&p_Vp, g_Vp);
    cudaGetSymbolAddress((void**)&p_attnv, g_attnv);
    cudaGetSymbolAddress((void**)&p_woutp, g_woutp);
    cudaGetSymbolAddress((void**)&p_lat1, g_lat1);
    cudaGetSymbolAddress((void**)&p_ffln, g_ffln);
    cudaGetSymbolAddress((void**)&p_ff1p, g_ff1p);
    cudaGetSymbolAddress((void**)&p_h1, g_h1);
    cudaGetSymbolAddress((void**)&p_ff2p, g_ff2p);
    cudaGetSymbolAddress((void**)&p_lat2, g_lat2);

    // mask kind
    detect_mask_kernel<<<1, 256>>>((const unsigned int*)mask);

    // q = LN(latents) @ wq  (split-K 8; B = wq natural [D][INNER])
    ln_rows_kernel<<<NL, 256>>>(latents, p_ql, nl_g, nl_b);
    hmma_gemm<<<dim3(6, 1, 8), 256>>>(p_ql, DD, 0, wq, INNER, 0,
                                      p_qp, INNER, 0, NL * INNER,
                                      NL, INNER, DD, 8, nullptr, nullptr);
    reduce_kernel<<<(NL * INNER + 255) / 256, 256>>>(p_qp, NL * INNER, 8, p_q, NL * INNER,
                                                     nullptr, 0, nullptr, 1, 0);

    // QT / QG / u / v / bv
    qt_kernel<<<DD / 32, 256>>>(p_q, wkv, nm_g, p_QTT, p_QG);
    uv_kernel<<<1, 128>>>(p_QTT, nm_g, nm_b, p_u, p_v);
    bv_kernel<<<INNER / 128, 128>>>(nm_b, wkv, p_bv);

    // S0 = x @ QG  (28672 x 128, K=4096; fused row stats of x)
    hmma_gemm<<<dim3(1, XROWS / 128, 1), 256>>>(x, DD, 0, p_QG, 128, 0,
                                                p_S0, 128, 0, 0,
                                                XROWS, 128, DD, 1, p_mean, p_rstd);

    // softmax -> C, s
    {
        int smemb = (NL * NN + 4 * NN + 2 * NL) * (int)sizeof(float);
        cudaFuncSetAttribute(attn_kernel, cudaFuncAttributeMaxDynamicSharedMemorySize, smemb);
        attn_kernel<<<BT * HH, 256, smemb>>>(guid, mask, p_S0, p_mean, p_rstd,
                                             p_u, p_v, p_C, p_s);
    }

    // AX[bt] = C[bt] @ x[bt]   (128 x 4096, K=1792; B = x natural [j][d])
    hmma_gemm<<<dim3(DD / 128, 1, BT), 256>>>(
        p_C, NN, (long long)128 * NN, x, DD, (long long)NN * DD,
        p_AX, DD, (long long)128 * DD, 0, 128, DD, NN, 1, nullptr, nullptr);

    // Y = (AX - s) * g, head-major
    y_kernel<<<(BT * 128 * DD) / 256, 256>>>(p_AX, p_s, nm_g, p_Y);

    // attnV: per head h: Y[h] (256x4096) @ Wv_h (B = wkv cols, natural), split-K 8
    hmma_gemm<<<dim3(1, 2, HH * 8), 256>>>(
        p_Y, DD, (long long)LATROWS * DD, wkv + INNER, 1536, 96,
        p_Vp, INNER, 96, (long long)LATROWS * INNER, LATROWS, 96, DD, 8,
        nullptr, nullptr);
    reduce_kernel<<<(LATROWS * INNER + 255) / 256, 256>>>(
        p_Vp, (long long)LATROWS * INNER, 8, p_attnv, LATROWS * INNER,
        nullptr, 0, p_bv, INNER, 0);

    // lat1 = attnv @ wout + latents (split-K 2)
    hmma_gemm<<<dim3(DD / 128, 2, 2), 256>>>(
        p_attnv, INNER, 0, wout, DD, 0,
        p_woutp, DD, 0, (long long)LATROWS * DD, LATROWS, DD, INNER, 2,
        nullptr, nullptr);
    reduce_kernel<<<(LATROWS * DD + 255) / 256, 256>>>(
        p_woutp, (long long)LATROWS * DD, 2, p_lat1, LATROWS * DD,
        latents, 2, nullptr, 1, 0);

    // FF
    ln_rows_kernel<<<LATROWS, 256>>>(p_lat1, p_ffln, ff_g, ff_b);
    hmma_gemm<<<dim3(FF / 128, 2, 2), 256>>>(
        p_ffln, DD, 0, w1, FF, 0,
        p_ff1p, FF, 0, (long long)LATROWS * FF, LATROWS, FF, DD, 2,
        nullptr, nullptr);
    reduce_kernel<<<((long long)LATROWS * FF + 255) / 256, 256>>>(
        p_ff1p, (long long)LATROWS * FF, 2, p_h1, (long long)LATROWS * FF,
        nullptr, 0, nullptr, 1, 1);
    hmma_gemm<<<dim3(DD / 128, 2, 2), 256>>>(
        p_h1, FF, 0, w2, DD, 0,
        p_ff2p, DD, 0, (long long)LATROWS * DD, LATROWS, DD, FF, 2,
        nullptr, nullptr);
    reduce_kernel<<<(LATROWS * DD + 255) / 256, 256>>>(
        p_ff2p, (long long)LATROWS * DD, 2, p_lat2, LATROWS * DD,
        p_lat1, 1, nullptr, 1, 0);

    // final LN
    ln_rows_kernel<<<LATROWS, 256>>>(p_lat2, out, fn_g, fn_b);
}

// round 7
// speedup vs baseline: 6.9583x; 1.0693x over previous
#include <cuda_runtime.h>
#include <cuda_bf16.h>
#include <cfloat>
#include <math.h>
#include <stdint.h>

// ---------------- problem constants ----------------
#define NN 1792
#define DD 4096
#define HH 8
#define DHH 96
#define INNER 768
#define NL 16
#define FF 8192
#define BT 16
#define XROWS 28672        // BT*NN
#define LATROWS 256        // BT*NL
#define EPS 1e-5f
#define ATTN_SCALE 0.10206207261596577f  // 96^-0.5

// ---------------- scratch (static device memory) ----------------
__device__ float g_mean[XROWS];
__device__ float g_rstd[XROWS];
__device__ int   g_mask_kind;

__device__ float g_ql[NL * DD];
__device__ float g_qp[8 * NL * INNER];
__device__ float g_q[NL * INNER];

__device__ float g_QTT[DD * 128];
__device__ float g_QG[DD * 128];       // B operand of S0: [K=d][N=128]
__device__ float g_u[128];
__device__ float g_v[128];
__device__ float g_bv[INNER];

__device__ float g_S0[(size_t)XROWS * 128];
__device__ float g_C[(size_t)BT * 128 * NN];
__device__ float g_s[BT * 128];
__device__ float g_AX[(size_t)BT * 128 * DD];
__device__ float g_Y[(size_t)HH * LATROWS * DD];

__device__ float g_Vp[8 * (size_t)LATROWS * INNER];
__device__ float g_attnv[LATROWS * INNER];
__device__ float g_woutp[2 * (size_t)LATROWS * DD];
__device__ float g_lat1[LATROWS * DD];
__device__ float g_ffln[LATROWS * DD];
__device__ float g_ff1p[2 * (size_t)LATROWS * FF];
__device__ float g_h1[(size_t)LATROWS * FF];
__device__ float g_ff2p[2 * (size_t)LATROWS * DD];
__device__ float g_lat2[LATROWS * DD];

// ---------------- helpers ----------------
__device__ __forceinline__ uint32_t smem_u32(const void* p) {
    uint32_t a;
    asm("{ .reg .u64 t; cvta.to.shared.u64 t, %1; cvt.u32.u64 %0, t; }" : "=r"(a) : "l"(p));
    return a;
}
__device__ __forceinline__ void ldm_x4(uint32_t* r, uint32_t addr) {
    asm volatile("ldmatrix.sync.aligned.m8n8.x4.shared.b16 {%0,%1,%2,%3}, [%4];"
                 : "=r"(r[0]), "=r"(r[1]), "=r"(r[2]), "=r"(r[3]) : "r"(addr));
}
__device__ __forceinline__ void ldm_x4t(uint32_t* r, uint32_t addr) {
    asm volatile("ldmatrix.sync.aligned.m8n8.x4.trans.shared.b16 {%0,%1,%2,%3}, [%4];"
                 : "=r"(r[0]), "=r"(r[1]), "=r"(r[2]), "=r"(r[3]) : "r"(addr));
}
__device__ __forceinline__ void mma16816(float* c, const uint32_t* a, const uint32_t* b) {
    asm volatile(
        "mma.sync.aligned.m16n8k16.row.col.f32.bf16.bf16.f32 "
        "{%0,%1,%2,%3}, {%4,%5,%6,%7}, {%8,%9}, {%0,%1,%2,%3};"
        : "+f"(c[0]), "+f"(c[1]), "+f"(c[2]), "+f"(c[3])
        : "r"(a[0]), "r"(a[1]), "r"(a[2]), "r"(a[3]), "r"(b[0]), "r"(b[1]));
}
__device__ __forceinline__ void split2(float x, float y, unsigned& h, unsigned& l) {
    __nv_bfloat162 hh = __floats2bfloat162_rn(x, y);
    float r0 = x - __bfloat162float(__low2bfloat16(hh));
    float r1 = y - __bfloat162float(__high2bfloat16(hh));
    __nv_bfloat162 ll = __floats2bfloat162_rn(r0, r1);
    h = *reinterpret_cast<unsigned*>(&hh);
    l = *reinterpret_cast<unsigned*>(&ll);
}

// ---------------- mask kind detection (parallel) ----------------
__global__ void detect_mask_kernel(const unsigned int* __restrict__ m) {
    __shared__ unsigned int sh[8];
    unsigned int orv = 0;
    for (int i = threadIdx.x; i < XROWS / 4; i += 256) orv |= m[i];
    #pragma unroll
    for (int o = 16; o; o >>= 1) orv |= __shfl_xor_sync(0xffffffffu, orv, o);
    int w = threadIdx.x >> 5;
    if ((threadIdx.x & 31) == 0) sh[w] = orv;
    __syncthreads();
    if (threadIdx.x == 0) {
        unsigned int t = 0;
        #pragma unroll
        for (int i = 0; i < 8; i++) t |= sh[i];
        g_mask_kind = (t <= 1u) ? 1 : 0;
    }
}

// ---------------- full layernorm ----------------
__global__ void ln_rows_kernel(const float* __restrict__ in, float* __restrict__ out,
                               const float* __restrict__ g, const float* __restrict__ b) {
    int row = blockIdx.x;
    const float* xr = in + (size_t)row * DD;
    float s = 0.f, q = 0.f;
    for (int i = threadIdx.x; i < DD; i += blockDim.x) { float v = xr[i]; s += v; q += v * v; }
    #pragma unroll
    for (int o = 16; o; o >>= 1) {
        s += __shfl_xor_sync(0xffffffffu, s, o);
        q += __shfl_xor_sync(0xffffffffu, q, o);
    }
    __shared__ float sh_s[8], sh_q[8];
    __shared__ float m_sh, r_sh;
    int w = threadIdx.x >> 5, l = threadIdx.x & 31;
    if (l == 0) { sh_s[w] = s; sh_q[w] = q; }
    __syncthreads();
    if (threadIdx.x == 0) {
        float S = 0.f, Q = 0.f;
        #pragma unroll
        for (int i = 0; i < 8; i++) { S += sh_s[i]; Q += sh_q[i]; }
        float m = S / (float)DD;
        m_sh = m;
        r_sh = rsqrtf(Q / (float)DD - m * m + EPS);
    }
    __syncthreads();
    float m = m_sh, r = r_sh;
    for (int i = threadIdx.x; i < DD; i += blockDim.x)
        out[(size_t)row * DD + i] = (xr[i] - m) * r * g[i] + b[i];
}

// ---------------- HMMA GEMM: C = A[M,K](fp32) @ B[K,N](fp32), 3-term hi/lo ---
// Software pipelined: register prefetch + double-buffered smem, 1 bar/chunk.
#define HSTRIDE 40    // A smem row stride (bf16)
#define BST 136       // B smem row stride (bf16)
#define A_BUF 5120    // 128*HSTRIDE elems per A tile
#define B_BUF 4352    // 32*BST elems per B tile
#define HSMEM ((4 * A_BUF + 4 * B_BUF) * 2)   // bytes = 75776
__global__ void __launch_bounds__(256, 1)
hmma_gemm(const float* __restrict__ A, long long lda, long long abatch,
          const float* __restrict__ B, long long ldb, long long bbatch,
          float* __restrict__ Cc, long long ldc, long long cbatch, long long csplit,
          int M, int Nvalid, int Ktot, int nsplit,
          float* __restrict__ stats_mean, float* __restrict__ stats_rstd) {
    extern __shared__ __nv_bfloat16 dynsm[];
    uint32_t dm_u = smem_u32(dynsm);

    int tid = threadIdx.x, wid = tid >> 5, lid = tid & 31;
    int z = blockIdx.z;
    int batch = z / nsplit, split = z - batch * nsplit;
    int n0 = blockIdx.x * 128, m0 = blockIdx.y * 128;
    int Kchunk = Ktot / nsplit, kbeg = split * Kchunk;
    int L = Kchunk / 32;

    const float* Ab = A + abatch * batch;
    const float* Bb = B + bbatch * batch;
    float* Cb = Cc + cbatch * batch + csplit * split;

    // A load mapping: thread -> (row ar, 16 cols at ac)
    int ar = tid >> 1, ac = (tid & 1) * 16;
    bool aok = (m0 + ar) < M;
    const float* ap = Ab + (long long)(m0 + ar) * lda + kbeg + ac;
    // B load mapping: thread -> (k-row kb, 16 cols at cb)
    int kb = tid >> 3, cb = (tid & 7) * 16;
    const float* bp = Bb + (long long)(kbeg + kb) * ldb + n0 + cb;
    bool bok0 = (n0 + cb)      < Nvalid;
    bool bok1 = (n0 + cb + 4)  < Nvalid;
    bool bok2 = (n0 + cb + 8)  < Nvalid;
    bool bok3 = (n0 + cb + 12) < Nvalid;

    int wm = wid >> 1, wn = wid & 1;
    float acc[2][8][4];
    #pragma unroll
    for (int a1 = 0; a1 < 2; a1++)
        #pragma unroll
        for (int b1 = 0; b1 < 8; b1++)
            #pragma unroll
            for (int c1 = 0; c1 < 4; c1++) acc[a1][b1][c1] = 0.f;

    uint32_t a_off = (uint32_t)(((lid & 15)) * HSTRIDE + (lid >> 4) * 8) * 2;
    uint32_t b_off = (uint32_t)(((lid & 15)) * BST + ((lid >> 4) << 3)) * 2;
    uint32_t ast_off = (uint32_t)(ar * HSTRIDE + ac) * 2;
    uint32_t bst_off = (uint32_t)(kb * BST + cb) * 2;

    bool do_stats = (stats_mean != nullptr);
    float ssum = 0.f, sqsum = 0.f;

    // ---- prologue: prefetch chunk 0 ----
    float4 pa0, pa1, pa2, pa3, pb0, pb1, pb2, pb3;
    {
        float4 zz = make_float4(0.f, 0.f, 0.f, 0.f);
        pa0 = aok ? *(const float4*)(ap)      : zz;
        pa1 = aok ? *(const float4*)(ap + 4)  : zz;
        pa2 = aok ? *(const float4*)(ap + 8)  : zz;
        pa3 = aok ? *(const float4*)(ap + 12) : zz;
        pb0 = bok0 ? *(const float4*)(bp)      : zz;
        pb1 = bok1 ? *(const float4*)(bp + 4)  : zz;
        pb2 = bok2 ? *(const float4*)(bp + 8)  : zz;
        pb3 = bok3 ? *(const float4*)(bp + 12) : zz;
    }

    for (int cc = 0; cc < L; cc++) {
        int s = cc & 1;
        uint32_t aHi = dm_u + (uint32_t)(s * 2 * A_BUF) * 2;
        uint32_t aLo = aHi + A_BUF * 2;
        uint32_t bHi = dm_u + (uint32_t)(4 * A_BUF + s * 2 * B_BUF) * 2;
        uint32_t bLo = bHi + B_BUF * 2;

        // ---- convert held registers -> smem buffer s ----
        {
            if (do_stats) {
                ssum += pa0.x + pa0.y + pa0.z + pa0.w + pa1.x + pa1.y + pa1.z + pa1.w
                      + pa2.x + pa2.y + pa2.z + pa2.w + pa3.x + pa3.y + pa3.z + pa3.w;
                sqsum += pa0.x*pa0.x + pa0.y*pa0.y + pa0.z*pa0.z + pa0.w*pa0.w
                       + pa1.x*pa1.x + pa1.y*pa1.y + pa1.z*pa1.z + pa1.w*pa1.w
                       + pa2.x*pa2.x + pa2.y*pa2.y + pa2.z*pa2.z + pa2.w*pa2.w
                       + pa3.x*pa3.x + pa3.y*pa3.y + pa3.z*pa3.z + pa3.w*pa3.w;
            }
            unsigned h0, h1, h2, h3, h4, h5, h6, h7;
            unsigned l0, l1, l2, l3, l4, l5, l6, l7;
            split2(pa0.x, pa0.y, h0, l0); split2(pa0.z, pa0.w, h1, l1);
            split2(pa1.x, pa1.y, h2, l2); split2(pa1.z, pa1.w, h3, l3);
            split2(pa2.x, pa2.y, h4, l4); split2(pa2.z, pa2.w, h5, l5);
            split2(pa3.x, pa3.y, h6, l6); split2(pa3.z, pa3.w, h7, l7);
            asm volatile("st.shared.v4.b32 [%0], {%1,%2,%3,%4};" ::
                "r"(aHi + ast_off), "r"(h0), "r"(h1), "r"(h2), "r"(h3));
            asm volatile("st.shared.v4.b32 [%0], {%1,%2,%3,%4};" ::
                "r"(aHi + ast_off + 16), "r"(h4), "r"(h5), "r"(h6), "r"(h7));
            asm volatile("st.shared.v4.b32 [%0], {%1,%2,%3,%4};" ::
                "r"(aLo + ast_off), "r"(l0), "r"(l1), "r"(l2), "r"(l3));
            asm volatile("st.shared.v4.b32 [%0], {%1,%2,%3,%4};" ::
                "r"(aLo + ast_off + 16), "r"(l4), "r"(l5), "r"(l6), "r"(l7));
            split2(pb0.x, pb0.y, h0, l0); split2(pb0.z, pb0.w, h1, l1);
            split2(pb1.x, pb1.y, h2, l2); split2(pb1.z, pb1.w, h3, l3);
            split2(pb2.x, pb2.y, h4, l4); split2(pb2.z, pb2.w, h5, l5);
            split2(pb3.x, pb3.y, h6, l6); split2(pb3.z, pb3.w, h7, l7);
            asm volatile("st.shared.v4.b32 [%0], {%1,%2,%3,%4};" ::
                "r"(bHi + bst_off), "r"(h0), "r"(h1), "r"(h2), "r"(h3));
            asm volatile("st.shared.v4.b32 [%0], {%1,%2,%3,%4};" ::
                "r"(bHi + bst_off + 16), "r"(h4), "r"(h5), "r"(h6), "r"(h7));
            asm volatile("st.shared.v4.b32 [%0], {%1,%2,%3,%4};" ::
                "r"(bLo + bst_off), "r"(l0), "r"(l1), "r"(l2), "r"(l3));
            asm volatile("st.shared.v4.b32 [%0], {%1,%2,%3,%4};" ::
                "r"(bLo + bst_off + 16), "r"(l4), "r"(l5), "r"(l6), "r"(l7));
        }

        // ---- prefetch next chunk (LDGs in flight across compute) ----
        if (cc + 1 < L) {
            int k0 = (cc + 1) * 32;
            const float* an = ap + k0;
            const float* bn = bp + (long long)k0 * ldb;
            float4 zz = make_float4(0.f, 0.f, 0.f, 0.f);
            pa0 = aok ? *(const float4*)(an)      : zz;
            pa1 = aok ? *(const float4*)(an + 4)  : zz;
            pa2 = aok ? *(const float4*)(an + 8)  : zz;
            pa3 = aok ? *(const float4*)(an + 12) : zz;
            pb0 = bok0 ? *(const float4*)(bn)      : zz;
            pb1 = bok1 ? *(const float4*)(bn + 4)  : zz;
            pb2 = bok2 ? *(const float4*)(bn + 8)  : zz;
            pb3 = bok3 ? *(const float4*)(bn + 12) : zz;
        }

        __syncthreads();

        // ---- compute from buffer s ----
        #pragma unroll
        for (int kk = 0; kk < 2; kk++) {
            uint32_t ah[2][4], al[2][4];
            #pragma unroll
            for (int mt = 0; mt < 2; mt++) {
                uint32_t ro = (uint32_t)((wm * 32 + mt * 16) * HSTRIDE) * 2 + a_off + kk * 32;
                ldm_x4(ah[mt], aHi + ro);
                ldm_x4(al[mt], aLo + ro);
            }
            #pragma unroll
            for (int nt2 = 0; nt2 < 4; nt2++) {
                uint32_t bo = (uint32_t)(kk * 16 * BST) * 2 + b_off
                            + (uint32_t)((wn * 64 + nt2 * 16) * 2);
                uint32_t bh[4], bl[4];
                ldm_x4t(bh, bHi + bo);
                ldm_x4t(bl, bLo + bo);
                #pragma unroll
                for (int mt = 0; mt < 2; mt++) {
                    mma16816(acc[mt][nt2 * 2],     ah[mt], bh);
                    mma16816(acc[mt][nt2 * 2],     ah[mt], bl);
                    mma16816(acc[mt][nt2 * 2],     al[mt], bh);
                    mma16816(acc[mt][nt2 * 2 + 1], ah[mt], bh + 2);
                    mma16816(acc[mt][nt2 * 2 + 1], ah[mt], bl + 2);
                    mma16816(acc[mt][nt2 * 2 + 1], al[mt], bh + 2);
                }
            }
        }
        __syncthreads();
    }

    // ---- fused row stats (S0 launch only: nsplit=1, gridDim.x=1, full K) ----
    if (do_stats && aok) {
        float s2 = ssum + __shfl_xor_sync(0xffffffffu, ssum, 1);
        float q2 = sqsum + __shfl_xor_sync(0xffffffffu, sqsum, 1);
        if ((tid & 1) == 0) {
            float m = s2 / (float)DD;
            stats_mean[m0 + ar] = m;
            stats_rstd[m0 + ar] = rsqrtf(q2 / (float)DD - m * m + EPS);
        }
    }

    // ---- epilogue ----
    int rr = lid >> 2, cc2 = (lid & 3) * 2;
    #pragma unroll
    for (int mt = 0; mt < 2; mt++) {
        #pragma unroll
        for (int nt = 0; nt < 8; nt++) {
            int row = m0 + wm * 32 + mt * 16 + rr;
            int col = n0 + wn * 64 + nt * 8 + cc2;
            if (col < Nvalid) {
                if (row < M)
                    *(float2*)(Cb + (long long)row * ldc + col) =
                        make_float2(acc[mt][nt][0], acc[mt][nt][1]);
                if (row + 8 < M)
                    *(float2*)(Cb + (long long)(row + 8) * ldc + col) =
                        make_float2(acc[mt][nt][2], acc[mt][nt][3]);
            }
        }
    }
}

// ---------------- generic split reduce + epilogue ----------------
__global__ void reduce_kernel(const float* __restrict__ parts, long long pstride, int nsplit,
                              float* __restrict__ out, long long n,
                              const float* __restrict__ addsrc, int add_mode,
                              const float* __restrict__ bias, int bias_period,
                              int do_gelu) {
    long long i = (long long)blockIdx.x * 256 + threadIdx.x;
    if (i >= n) return;
    float s = 0.f;
    for (int p = 0; p < nsplit; p++) s += parts[p * pstride + i];
    if (bias) s += bias[i % bias_period];
    if (do_gelu) s = 0.5f * s * (1.0f + erff(s * 0.70710678118654752f));
    if (add_mode == 1) s += addsrc[i];
    else if (add_mode == 2) {
        long long r = i >> 12;
        s += addsrc[((r & 15) << 12) + (i & 4095)];
    }
    out[i] = s;
}

// ---------------- QT precompute: QTT & QG fp32 [d][128] ----------------
__global__ void qt_kernel(const float* __restrict__ q, const float* __restrict__ wkv,
                          const float* __restrict__ g,
                          float* __restrict__ QTT, float* __restrict__ QG) {
    __shared__ float qs[NL * INNER];
    for (int i = threadIdx.x; i < NL * INNER; i += 256) qs[i] = q[i];
    __syncthreads();
    int d = blockIdx.x * 32 + (threadIdx.x >> 3);
    int h = threadIdx.x & 7;
    const float* wrow = wkv + (long long)d * 1536 + h * DHH;
    float acc[NL];
    #pragma unroll
    for (int i = 0; i < NL; i++) acc[i] = 0.f;
    for (int dh = 0; dh < DHH; dh++) {
        float w = wrow[dh];
        #pragma unroll
        for (int i = 0; i < NL; i++) acc[i] = fmaf(qs[i * INNER + h * DHH + dh], w, acc[i]);
    }
    float gd = g[d];
    #pragma unroll
    for (int i = 0; i < NL; i++) {
        int ih = h * NL + i;
        QTT[(long long)d * 128 + ih] = acc[i];
        QG[(long long)d * 128 + ih] = acc[i] * gd;
    }
}

__global__ void uv_kernel(const float* __restrict__ QTT, const float* __restrict__ g,
                          const float* __restrict__ b,
                          float* __restrict__ u, float* __restrict__ v) {
    int ih = threadIdx.x;
    float uu = 0.f, vv = 0.f;
    for (int d = 0; d < DD; d++) {
        float t = QTT[(long long)d * 128 + ih];
        uu = fmaf(t, g[d], uu);
        vv = fmaf(t, b[d], vv);
    }
    u[ih] = uu; v[ih] = vv;
}

__global__ void bv_kernel(const float* __restrict__ b, const float* __restrict__ wkv,
                          float* __restrict__ bv) {
    int e = blockIdx.x * 128 + threadIdx.x;
    float a = 0.f;
    for (int d = 0; d < DD; d++) a = fmaf(b[d], wkv[(long long)d * 1536 + INNER + e], a);
    bv[e] = a;
}

// ---------------- attention softmax: block per (bt, h) ----------------
__global__ void attn_kernel(const float* __restrict__ guid, const void* __restrict__ mask,
                            const float* __restrict__ S0, const float* __restrict__ mean,
                            const float* __restrict__ rstd,
                            const float* __restrict__ u, const float* __restrict__ v,
                            float* __restrict__ C, float* __restrict__ s_out) {
    extern __shared__ float sm[];
    float* sim = sm;
    float* rj  = sim + NL * NN;
    float* mj  = rj + NN;
    float* gu  = mj + NN;
    float* mk  = gu + NN;
    float* us  = mk + NN;
    float* vs  = us + NL;

    int bt = blockIdx.x >> 3;
    int h  = blockIdx.x & 7;
    int tid = threadIdx.x;
    int kind = g_mask_kind;

    for (int j = tid; j < NN; j += 256) {
        rj[j] = rstd[bt * NN + j];
        mj[j] = mean[bt * NN + j];
        gu[j] = guid[bt * NN + j];
        mk[j] = (kind == 1) ? (float)((const int*)mask)[bt * NN + j]
                            : (float)((const unsigned char*)mask)[bt * NN + j];
    }
    if (tid < NL) { us[tid] = u[h * NL + tid]; vs[tid] = v[h * NL + tid]; }
    __syncthreads();

    for (int idx = tid; idx < NL * NN; idx += 256) {
        int j = idx >> 4, i = idx & 15;
        float t = S0[((size_t)bt * NN + j) * 128 + h * NL + i];
        sim[i * NN + j] = ATTN_SCALE * (rj[j] * t - rj[j] * mj[j] * us[i] + vs[i]);
    }
    __syncthreads();

    int warp = tid >> 5, lane = tid & 31;
    for (int r = warp; r < NL; r += 8) {
        float* srow = sim + r * NN;
        float m0 = -FLT_MAX;
        for (int j = lane; j < NN; j += 32) m0 = fmaxf(m0, srow[j]);
        #pragma unroll
        for (int o = 16; o; o >>= 1) m0 = fmaxf(m0, __shfl_xor_sync(0xffffffffu, m0, o));

        float m1 = -FLT_MAX;
        for (int j = lane; j < NN; j += 32) {
            float s = srow[j] - m0;
            if (mk[j] != 0.f) s = -3.402823466e38f;
            s *= gu[j];
            srow[j] = s;
            m1 = fmaxf(m1, s);
        }
        #pragma unroll
        for (int o = 16; o; o >>= 1) m1 = fmaxf(m1, __shfl_xor_sync(0xffffffffu, m1, o));

        float sum = 0.f;
        for (int j = lane; j < NN; j += 32) {
            float e = expf(srow[j] - m1);
            srow[j] = e;
            sum += e;
        }
        #pragma unroll
        for (int o = 16; o; o >>= 1) sum += __shfl_xor_sync(0xffffffffu, sum, o);
        float inv = 1.f / sum;

        float sacc = 0.f;
        float* crow = C + ((size_t)bt * 128 + h * NL + r) * NN;
        for (int j = lane; j < NN; j += 32) {
            float a = srow[j] * inv;
            float c = a * rj[j];
            crow[j] = c;
            sacc = fmaf(c, mj[j], sacc);
        }
        #pragma unroll
        for (int o = 16; o; o >>= 1) sacc += __shfl_xor_sync(0xffffffffu, sacc, o);
        if (lane == 0) s_out[bt * 128 + h * NL + r] = sacc;
    }
}

// ---------------- Y[h][bt*16+i][d] = (AX[bt][h*16+i][d] - s)*g[d] -------------
__global__ void y_kernel(const float* __restrict__ AX, const float* __restrict__ s,
                         const float* __restrict__ g, float* __restrict__ Y) {
    long long idx = (long long)blockIdx.x * 256 + threadIdx.x;
    int d = idx & 4095;
    long long r = idx >> 12;
    int bt = (int)(r >> 7);
    int hi = (int)(r & 127);
    int h = hi >> 4, i = hi & 15;
    Y[(((long long)h * LATROWS + bt * NL + i) << 12) + d] = (AX[idx] - s[r]) * g[d];
}

// ---------------- launch ----------------
extern "C" void kernel_launch(void* const* d_in, const int* in_sizes, int n_in,
                              void* d_out, int out_size) {
    const float* x       = (const float*)d_in[0];
    const float* guid    = (const float*)d_in[1];
    const void*  mask    = d_in[2];
    const float* latents = (const float*)d_in[3];
    const float* nm_g    = (const float*)d_in[4];
    const float* nm_b    = (const float*)d_in[5];
    const float* nl_g    = (const float*)d_in[6];
    const float* nl_b    = (const float*)d_in[7];
    const float* wq      = (const float*)d_in[8];
    const float* wkv     = (const float*)d_in[9];
    const float* wout    = (const float*)d_in[10];
    const float* ff_g    = (const float*)d_in[11];
    const float* ff_b    = (const float*)d_in[12];
    const float* w1      = (const float*)d_in[13];
    const float* w2      = (const float*)d_in[14];
    const float* fn_g    = (const float*)d_in[15];
    const float* fn_b    = (const float*)d_in[16];
    float* out = (float*)d_out;

    float *p_mean, *p_rstd, *p_ql, *p_qp, *p_q, *p_QTT, *p_QG, *p_u, *p_v, *p_bv;
    float *p_S0, *p_C, *p_s, *p_AX, *p_Y, *p_Vp, *p_attnv, *p_woutp;
    float *p_lat1, *p_ffln, *p_ff1p, *p_h1, *p_ff2p, *p_lat2;
    cudaGetSymbolAddress((void**)&p_mean, g_mean);
    cudaGetSymbolAddress((void**)&p_rstd, g_rstd);
    cudaGetSymbolAddress((void**)&p_ql, g_ql);
    cudaGetSymbolAddress((void**)&p_qp, g_qp);
    cudaGetSymbolAddress((void**)&p_q, g_q);
    cudaGetSymbolAddress((void**)&p_QTT, g_QTT);
    cudaGetSymbolAddress((void**)&p_QG, g_QG);
    cudaGetSymbolAddress((void**)&p_u, g_u);
    cudaGetSymbolAddress((void**)&p_v, g_v);
    cudaGetSymbolAddress((void**)&p_bv, g_bv);
    cudaGetSymbolAddress((void**)&p_S0, g_S0);
    cudaGetSymbolAddress((void**)&p_C, g_C);
    cudaGetSymbolAddress((void**)&p_s, g_s);
    cudaGetSymbolAddress((void**)&p_AX, g_AX);
    cudaGetSymbolAddress((void**)&p_Y, g_Y);
    cudaGetSymbolAddress((void**)&p_Vp, g_Vp);
    cudaGetSymbolAddress((void**)&p_attnv, g_attnv);
    cudaGetSymbolAddress((void**)&p_woutp, g_woutp);
    cudaGetSymbolAddress((void**)&p_lat1, g_lat1);
    cudaGetSymbolAddress((void**)&p_ffln, g_ffln);
    cudaGetSymbolAddress((void**)&p_ff1p, g_ff1p);
    cudaGetSymbolAddress((void**)&p_h1, g_h1);
    cudaGetSymbolAddress((void**)&p_ff2p, g_ff2p);
    cudaGetSymbolAddress((void**)&p_lat2, g_lat2);

    cudaFuncSetAttribute(hmma_gemm, cudaFuncAttributeMaxDynamicSharedMemorySize, HSMEM);

    // mask kind
    detect_mask_kernel<<<1, 256>>>((const unsigned int*)mask);

    // q = LN(latents) @ wq  (split-K 8; B = wq natural [D][INNER])
    ln_rows_kernel<<<NL, 256>>>(latents, p_ql, nl_g, nl_b);
    hmma_gemm<<<dim3(6, 1, 8), 256, HSMEM>>>(p_ql, DD, 0, wq, INNER, 0,
                                             p_qp, INNER, 0, NL * INNER,
                                             NL, INNER, DD, 8, nullptr, nullptr);
    reduce_kernel<<<(NL * INNER + 255) / 256, 256>>>(p_qp, NL * INNER, 8, p_q, NL * INNER,
                                                     nullptr, 0, nullptr, 1, 0);

    // QT / QG / u / v / bv
    qt_kernel<<<DD / 32, 256>>>(p_q, wkv, nm_g, p_QTT, p_QG);
    uv_kernel<<<1, 128>>>(p_QTT, nm_g, nm_b, p_u, p_v);
    bv_kernel<<<INNER / 128, 128>>>(nm_b, wkv, p_bv);

    // S0 = x @ QG  (28672 x 128, K=4096; fused row stats of x)
    hmma_gemm<<<dim3(1, XROWS / 128, 1), 256, HSMEM>>>(x, DD, 0, p_QG, 128, 0,
                                                       p_S0, 128, 0, 0,
                                                       XROWS, 128, DD, 1, p_mean, p_rstd);

    // softmax -> C, s
    {
        int smemb = (NL * NN + 4 * NN + 2 * NL) * (int)sizeof(float);
        cudaFuncSetAttribute(attn_kernel, cudaFuncAttributeMaxDynamicSharedMemorySize, smemb);
        attn_kernel<<<BT * HH, 256, smemb>>>(guid, mask, p_S0, p_mean, p_rstd,
                                             p_u, p_v, p_C, p_s);
    }

    // AX[bt] = C[bt] @ x[bt]   (128 x 4096, K=1792; B = x natural [j][d])
    hmma_gemm<<<dim3(DD / 128, 1, BT), 256, HSMEM>>>(
        p_C, NN, (long long)128 * NN, x, DD, (long long)NN * DD,
        p_AX, DD, (long long)128 * DD, 0, 128, DD, NN, 1, nullptr, nullptr);

    // Y = (AX - s) * g, head-major
    y_kernel<<<(BT * 128 * DD) / 256, 256>>>(p_AX, p_s, nm_g, p_Y);

    // attnV: per head h: Y[h] (256x4096) @ Wv_h (B = wkv cols, natural), split-K 8
    hmma_gemm<<<dim3(1, 2, HH * 8), 256, HSMEM>>>(
        p_Y, DD, (long long)LATROWS * DD, wkv + INNER, 1536, 96,
        p_Vp, INNER, 96, (long long)LATROWS * INNER, LATROWS, 96, DD, 8,
        nullptr, nullptr);
    reduce_kernel<<<(LATROWS * INNER + 255) / 256, 256>>>(
        p_Vp, (long long)LATROWS * INNER, 8, p_attnv, LATROWS * INNER,
        nullptr, 0, p_bv, INNER, 0);

    // lat1 = attnv @ wout + latents (split-K 2)
    hmma_gemm<<<dim3(DD / 128, 2, 2), 256, HSMEM>>>(
        p_attnv, INNER, 0, wout, DD, 0,
        p_woutp, DD, 0, (long long)LATROWS * DD, LATROWS, DD, INNER, 2,
        nullptr, nullptr);
    reduce_kernel<<<(LATROWS * DD + 255) / 256, 256>>>(
        p_woutp, (long long)LATROWS * DD, 2, p_lat1, LATROWS * DD,
        latents, 2, nullptr, 1, 0);

    // FF
    ln_rows_kernel<<<LATROWS, 256>>>(p_lat1, p_ffln, ff_g, ff_b);
    hmma_gemm<<<dim3(FF / 128, 2, 2), 256, HSMEM>>>(
        p_ffln, DD, 0, w1, FF, 0,
        p_ff1p, FF, 0, (long long)LATROWS * FF, LATROWS, FF, DD, 2,
        nullptr, nullptr);
    reduce_kernel<<<((long long)LATROWS * FF + 255) / 256, 256>>>(
        p_ff1p, (long long)LATROWS * FF, 2, p_h1, (long long)LATROWS * FF,
        nullptr, 0, nullptr, 1, 1);
    hmma_gemm<<<dim3(DD / 128, 2, 2), 256, HSMEM>>>(
        p_h1, FF, 0, w2, DD, 0,
        p_ff2p, DD, 0, (long long)LATROWS * DD, LATROWS, DD, FF, 2,
        nullptr, nullptr);
    reduce_kernel<<<(LATROWS * DD + 255) / 256, 256>>>(
        p_ff2p, (long long)LATROWS * DD, 2, p_lat2, LATROWS * DD,
        p_lat1, 1, nullptr, 1, 0);

    // final LN
    ln_rows_kernel<<<LATROWS, 256>>>(p_lat2, out, fn_g, fn_b);
}

// round 8
// speedup vs baseline: 7.2677x; 1.0445x over previous
#include <cuda_runtime.h>
#include <cuda_bf16.h>
#include <cuda_fp16.h>
#include <cfloat>
#include <math.h>
#include <stdint.h>

// ---------------- problem constants ----------------
#define NN 1792
#define DD 4096
#define HH 8
#define DHH 96
#define INNER 768
#define NL 16
#define FF 8192
#define BT 16
#define XROWS 28672        // BT*NN
#define LATROWS 256        // BT*NL
#define EPS 1e-5f
#define ATTN_SCALE 0.10206207261596577f  // 96^-0.5

// ---------------- scratch (static device memory) ----------------
__device__ float g_mean[XROWS];
__device__ float g_rstd[XROWS];
__device__ int   g_mask_kind;

__device__ float g_ql[NL * DD];
__device__ float g_qp[8 * NL * INNER];

__device__ float g_QTT[DD * 128];
__device__ float g_QG[DD * 128];       // B operand of S0: [K=d][N=128]
__device__ float g_u[128];
__device__ float g_v[128];
__device__ float g_bv[INNER];

__device__ float g_S0[(size_t)XROWS * 128];
__device__ float g_C[(size_t)BT * 128 * NN];
__device__ float g_s[BT * 128];
__device__ float g_AX[(size_t)BT * 128 * DD];
__device__ float g_Y[(size_t)HH * LATROWS * DD];

__device__ float g_Vp[8 * (size_t)LATROWS * INNER];
__device__ float g_attnv[LATROWS * INNER];
__device__ float g_woutp[2 * (size_t)LATROWS * DD];
__device__ float g_lat1[LATROWS * DD];
__device__ float g_ffln[LATROWS * DD];
__device__ float g_ff1p[2 * (size_t)LATROWS * FF];
__device__ float g_h1[(size_t)LATROWS * FF];
__device__ float g_ff2p[2 * (size_t)LATROWS * DD];
__device__ float g_lat2[LATROWS * DD];

// ---------------- helpers ----------------
__device__ __forceinline__ uint32_t smem_u32(const void* p) {
    uint32_t a;
    asm("{ .reg .u64 t; cvta.to.shared.u64 t, %1; cvt.u32.u64 %0, t; }" : "=r"(a) : "l"(p));
    return a;
}
__device__ __forceinline__ void ldm_x4(uint32_t* r, uint32_t addr) {
    asm volatile("ldmatrix.sync.aligned.m8n8.x4.shared.b16 {%0,%1,%2,%3}, [%4];"
                 : "=r"(r[0]), "=r"(r[1]), "=r"(r[2]), "=r"(r[3]) : "r"(addr));
}
__device__ __forceinline__ void ldm_x4t(uint32_t* r, uint32_t addr) {
    asm volatile("ldmatrix.sync.aligned.m8n8.x4.trans.shared.b16 {%0,%1,%2,%3}, [%4];"
                 : "=r"(r[0]), "=r"(r[1]), "=r"(r[2]), "=r"(r[3]) : "r"(addr));
}
__device__ __forceinline__ void mma16816(float* c, const uint32_t* a, const uint32_t* b) {
    asm volatile(
        "mma.sync.aligned.m16n8k16.row.col.f32.bf16.bf16.f32 "
        "{%0,%1,%2,%3}, {%4,%5,%6,%7}, {%8,%9}, {%0,%1,%2,%3};"
        : "+f"(c[0]), "+f"(c[1]), "+f"(c[2]), "+f"(c[3])
        : "r"(a[0]), "r"(a[1]), "r"(a[2]), "r"(a[3]), "r"(b[0]), "r"(b[1]));
}
__device__ __forceinline__ void mma16816h(float* c, const uint32_t* a, const uint32_t* b) {
    asm volatile(
        "mma.sync.aligned.m16n8k16.row.col.f32.f16.f16.f32 "
        "{%0,%1,%2,%3}, {%4,%5,%6,%7}, {%8,%9}, {%0,%1,%2,%3};"
        : "+f"(c[0]), "+f"(c[1]), "+f"(c[2]), "+f"(c[3])
        : "r"(a[0]), "r"(a[1]), "r"(a[2]), "r"(a[3]), "r"(b[0]), "r"(b[1]));
}
__device__ __forceinline__ void split2(float x, float y, unsigned& h, unsigned& l) {
    __nv_bfloat162 hh = __floats2bfloat162_rn(x, y);
    float r0 = x - __bfloat162float(__low2bfloat16(hh));
    float r1 = y - __bfloat162float(__high2bfloat16(hh));
    __nv_bfloat162 ll = __floats2bfloat162_rn(r0, r1);
    h = *reinterpret_cast<unsigned*>(&hh);
    l = *reinterpret_cast<unsigned*>(&ll);
}
__device__ __forceinline__ void split2h(float x, float y, unsigned& h, unsigned& l) {
    __half2 hh = __floats2half2_rn(x, y);
    float r0 = x - __half2float(__low2half(hh));
    float r1 = y - __half2float(__high2half(hh));
    __half2 ll = __floats2half2_rn(r0, r1);
    h = *reinterpret_cast<unsigned*>(&hh);
    l = *reinterpret_cast<unsigned*>(&ll);
}
__device__ __forceinline__ unsigned packh(float x, float y) {
    __half2 hh = __floats2half2_rn(x, y);
    return *reinterpret_cast<unsigned*>(&hh);
}

// ---------------- mask kind detection (parallel) ----------------
__global__ void detect_mask_kernel(const unsigned int* __restrict__ m) {
    __shared__ unsigned int sh[8];
    unsigned int orv = 0;
    for (int i = threadIdx.x; i < XROWS / 4; i += 256) orv |= m[i];
    #pragma unroll
    for (int o = 16; o; o >>= 1) orv |= __shfl_xor_sync(0xffffffffu, orv, o);
    int w = threadIdx.x >> 5;
    if ((threadIdx.x & 31) == 0) sh[w] = orv;
    __syncthreads();
    if (threadIdx.x == 0) {
        unsigned int t = 0;
        #pragma unroll
        for (int i = 0; i < 8; i++) t |= sh[i];
        g_mask_kind = (t <= 1u) ? 1 : 0;
    }
}

// ---------------- full layernorm ----------------
__global__ void ln_rows_kernel(const float* __restrict__ in, float* __restrict__ out,
                               const float* __restrict__ g, const float* __restrict__ b) {
    int row = blockIdx.x;
    const float* xr = in + (size_t)row * DD;
    float s = 0.f, q = 0.f;
    for (int i = threadIdx.x; i < DD; i += blockDim.x) { float v = xr[i]; s += v; q += v * v; }
    #pragma unroll
    for (int o = 16; o; o >>= 1) {
        s += __shfl_xor_sync(0xffffffffu, s, o);
        q += __shfl_xor_sync(0xffffffffu, q, o);
    }
    __shared__ float sh_s[8], sh_q[8];
    __shared__ float m_sh, r_sh;
    int w = threadIdx.x >> 5, l = threadIdx.x & 31;
    if (l == 0) { sh_s[w] = s; sh_q[w] = q; }
    __syncthreads();
    if (threadIdx.x == 0) {
        float S = 0.f, Q = 0.f;
        #pragma unroll
        for (int i = 0; i < 8; i++) { S += sh_s[i]; Q += sh_q[i]; }
        float m = S / (float)DD;
        m_sh = m;
        r_sh = rsqrtf(Q / (float)DD - m * m + EPS);
    }
    __syncthreads();
    float m = m_sh, r = r_sh;
    for (int i = threadIdx.x; i < DD; i += blockDim.x)
        out[(size_t)row * DD + i] = (xr[i] - m) * r * g[i] + b[i];
}

// ================= hmma3: bf16 3-term (exactish), pipelined =================
#define HSTRIDE 40    // A smem row stride (bf16)
#define BST 136       // B smem row stride (bf16)
#define A_BUF 5120    // 128*HSTRIDE
#define B_BUF 4352    // 32*BST
#define HSMEM3 ((4 * A_BUF + 4 * B_BUF) * 2)   // 75776 B
__global__ void __launch_bounds__(256, 1)
hmma3(const float* __restrict__ A, long long lda, long long abatch,
      const float* __restrict__ B, long long ldb, long long bbatch,
      float* __restrict__ Cc, long long ldc, long long cbatch, long long csplit,
      int M, int Nvalid, int Ktot, int nsplit,
      float* __restrict__ stats_mean, float* __restrict__ stats_rstd) {
    extern __shared__ __nv_bfloat16 dynsm[];
    uint32_t dm_u = smem_u32(dynsm);

    int tid = threadIdx.x, wid = tid >> 5, lid = tid & 31;
    int z = blockIdx.z;
    int batch = z / nsplit, split = z - batch * nsplit;
    int n0 = blockIdx.x * 128, m0 = blockIdx.y * 128;
    int Kchunk = Ktot / nsplit, kbeg = split * Kchunk;
    int L = Kchunk / 32;

    const float* Ab = A + abatch * batch;
    const float* Bb = B + bbatch * batch;
    float* Cb = Cc + cbatch * batch + csplit * split;

    int ar = tid >> 1, ac = (tid & 1) * 16;
    bool aok = (m0 + ar) < M;
    const float* ap = Ab + (long long)(m0 + ar) * lda + kbeg + ac;
    int kb = tid >> 3, cb = (tid & 7) * 16;
    const float* bp = Bb + (long long)(kbeg + kb) * ldb + n0 + cb;
    bool bok0 = (n0 + cb)      < Nvalid;
    bool bok1 = (n0 + cb + 4)  < Nvalid;
    bool bok2 = (n0 + cb + 8)  < Nvalid;
    bool bok3 = (n0 + cb + 12) < Nvalid;

    int wm = wid >> 1, wn = wid & 1;
    float acc[2][8][4];
    #pragma unroll
    for (int a1 = 0; a1 < 2; a1++)
        #pragma unroll
        for (int b1 = 0; b1 < 8; b1++)
            #pragma unroll
            for (int c1 = 0; c1 < 4; c1++) acc[a1][b1][c1] = 0.f;

    uint32_t a_off = (uint32_t)(((lid & 15)) * HSTRIDE + (lid >> 4) * 8) * 2;
    uint32_t b_off = (uint32_t)(((lid & 15)) * BST + ((lid >> 4) << 3)) * 2;
    uint32_t ast_off = (uint32_t)(ar * HSTRIDE + ac) * 2;
    uint32_t bst_off = (uint32_t)(kb * BST + cb) * 2;

    bool do_stats = (stats_mean != nullptr);
    float ssum = 0.f, sqsum = 0.f;

    float4 pa0, pa1, pa2, pa3, pb0, pb1, pb2, pb3;
    {
        float4 zz = make_float4(0.f, 0.f, 0.f, 0.f);
        pa0 = aok ? *(const float4*)(ap)      : zz;
        pa1 = aok ? *(const float4*)(ap + 4)  : zz;
        pa2 = aok ? *(const float4*)(ap + 8)  : zz;
        pa3 = aok ? *(const float4*)(ap + 12) : zz;
        pb0 = bok0 ? *(const float4*)(bp)      : zz;
        pb1 = bok1 ? *(const float4*)(bp + 4)  : zz;
        pb2 = bok2 ? *(const float4*)(bp + 8)  : zz;
        pb3 = bok3 ? *(const float4*)(bp + 12) : zz;
    }

    for (int cc = 0; cc < L; cc++) {
        int s = cc & 1;
        uint32_t aHi = dm_u + (uint32_t)(s * 2 * A_BUF) * 2;
        uint32_t aLo = aHi + A_BUF * 2;
        uint32_t bHi = dm_u + (uint32_t)(4 * A_BUF + s * 2 * B_BUF) * 2;
        uint32_t bLo = bHi + B_BUF * 2;

        {
            if (do_stats) {
                ssum += pa0.x + pa0.y + pa0.z + pa0.w + pa1.x + pa1.y + pa1.z + pa1.w
                      + pa2.x + pa2.y + pa2.z + pa2.w + pa3.x + pa3.y + pa3.z + pa3.w;
                sqsum += pa0.x*pa0.x + pa0.y*pa0.y + pa0.z*pa0.z + pa0.w*pa0.w
                       + pa1.x*pa1.x + pa1.y*pa1.y + pa1.z*pa1.z + pa1.w*pa1.w
                       + pa2.x*pa2.x + pa2.y*pa2.y + pa2.z*pa2.z + pa2.w*pa2.w
                       + pa3.x*pa3.x + pa3.y*pa3.y + pa3.z*pa3.z + pa3.w*pa3.w;
            }
            unsigned h0, h1, h2, h3, h4, h5, h6, h7;
            unsigned l0, l1, l2, l3, l4, l5, l6, l7;
            split2(pa0.x, pa0.y, h0, l0); split2(pa0.z, pa0.w, h1, l1);
            split2(pa1.x, pa1.y, h2, l2); split2(pa1.z, pa1.w, h3, l3);
            split2(pa2.x, pa2.y, h4, l4); split2(pa2.z, pa2.w, h5, l5);
            split2(pa3.x, pa3.y, h6, l6); split2(pa3.z, pa3.w, h7, l7);
            asm volatile("st.shared.v4.b32 [%0], {%1,%2,%3,%4};" ::
                "r"(aHi + ast_off), "r"(h0), "r"(h1), "r"(h2), "r"(h3));
            asm volatile("st.shared.v4.b32 [%0], {%1,%2,%3,%4};" ::
                "r"(aHi + ast_off + 16), "r"(h4), "r"(h5), "r"(h6), "r"(h7));
            asm volatile("st.shared.v4.b32 [%0], {%1,%2,%3,%4};" ::
                "r"(aLo + ast_off), "r"(l0), "r"(l1), "r"(l2), "r"(l3));
            asm volatile("st.shared.v4.b32 [%0], {%1,%2,%3,%4};" ::
                "r"(aLo + ast_off + 16), "r"(l4), "r"(l5), "r"(l6), "r"(l7));
            split2(pb0.x, pb0.y, h0, l0); split2(pb0.z, pb0.w, h1, l1);
            split2(pb1.x, pb1.y, h2, l2); split2(pb1.z, pb1.w, h3, l3);
            split2(pb2.x, pb2.y, h4, l4); split2(pb2.z, pb2.w, h5, l5);
            split2(pb3.x, pb3.y, h6, l6); split2(pb3.z, pb3.w, h7, l7);
            asm volatile("st.shared.v4.b32 [%0], {%1,%2,%3,%4};" ::
                "r"(bHi + bst_off), "r"(h0), "r"(h1), "r"(h2), "r"(h3));
            asm volatile("st.shared.v4.b32 [%0], {%1,%2,%3,%4};" ::
                "r"(bHi + bst_off + 16), "r"(h4), "r"(h5), "r"(h6), "r"(h7));
            asm volatile("st.shared.v4.b32 [%0], {%1,%2,%3,%4};" ::
                "r"(bLo + bst_off), "r"(l0), "r"(l1), "r"(l2), "r"(l3));
            asm volatile("st.shared.v4.b32 [%0], {%1,%2,%3,%4};" ::
                "r"(bLo + bst_off + 16), "r"(l4), "r"(l5), "r"(l6), "r"(l7));
        }

        if (cc + 1 < L) {
            int k0 = (cc + 1) * 32;
            const float* an = ap + k0;
            const float* bn = bp + (long long)k0 * ldb;
            float4 zz = make_float4(0.f, 0.f, 0.f, 0.f);
            pa0 = aok ? *(const float4*)(an)      : zz;
            pa1 = aok ? *(const float4*)(an + 4)  : zz;
            pa2 = aok ? *(const float4*)(an + 8)  : zz;
            pa3 = aok ? *(const float4*)(an + 12) : zz;
            pb0 = bok0 ? *(const float4*)(bn)      : zz;
            pb1 = bok1 ? *(const float4*)(bn + 4)  : zz;
            pb2 = bok2 ? *(const float4*)(bn + 8)  : zz;
            pb3 = bok3 ? *(const float4*)(bn + 12) : zz;
        }

        __syncthreads();

        #pragma unroll
        for (int kk = 0; kk < 2; kk++) {
            uint32_t ah[2][4], al[2][4];
            #pragma unroll
            for (int mt = 0; mt < 2; mt++) {
                uint32_t ro = (uint32_t)((wm * 32 + mt * 16) * HSTRIDE) * 2 + a_off + kk * 32;
                ldm_x4(ah[mt], aHi + ro);
                ldm_x4(al[mt], aLo + ro);
            }
            #pragma unroll
            for (int nt2 = 0; nt2 < 4; nt2++) {
                uint32_t bo = (uint32_t)(kk * 16 * BST) * 2 + b_off
                            + (uint32_t)((wn * 64 + nt2 * 16) * 2);
                uint32_t bh[4], bl[4];
                ldm_x4t(bh, bHi + bo);
                ldm_x4t(bl, bLo + bo);
                #pragma unroll
                for (int mt = 0; mt < 2; mt++) {
                    mma16816(acc[mt][nt2 * 2],     ah[mt], bh);
                    mma16816(acc[mt][nt2 * 2],     ah[mt], bl);
                    mma16816(acc[mt][nt2 * 2],     al[mt], bh);
                    mma16816(acc[mt][nt2 * 2 + 1], ah[mt], bh + 2);
                    mma16816(acc[mt][nt2 * 2 + 1], ah[mt], bl + 2);
                    mma16816(acc[mt][nt2 * 2 + 1], al[mt], bh + 2);
                }
            }
        }
        __syncthreads();
    }

    if (do_stats && aok) {
        float s2 = ssum + __shfl_xor_sync(0xffffffffu, ssum, 1);
        float q2 = sqsum + __shfl_xor_sync(0xffffffffu, sqsum, 1);
        if ((tid & 1) == 0) {
            float m = s2 / (float)DD;
            stats_mean[m0 + ar] = m;
            stats_rstd[m0 + ar] = rsqrtf(q2 / (float)DD - m * m + EPS);
        }
    }

    int rr = lid >> 2, cc2 = (lid & 3) * 2;
    #pragma unroll
    for (int mt = 0; mt < 2; mt++) {
        #pragma unroll
        for (int nt = 0; nt < 8; nt++) {
            int row = m0 + wm * 32 + mt * 16 + rr;
            int col = n0 + wn * 64 + nt * 8 + cc2;
            if (col < Nvalid) {
                if (row < M)
                    *(float2*)(Cb + (long long)row * ldc + col) =
                        make_float2(acc[mt][nt][0], acc[mt][nt][1]);
                if (row + 8 < M)
                    *(float2*)(Cb + (long long)(row + 8) * ldc + col) =
                        make_float2(acc[mt][nt][2], acc[mt][nt][3]);
            }
        }
    }
}

// ============ hmma2: fp16 2-term (A hi/lo exact, B single-rounded) ===========
#define HSMEM2 ((4 * A_BUF + 2 * B_BUF) * 2)   // 58368 B
__global__ void __launch_bounds__(256, 1)
hmma2(const float* __restrict__ A, long long lda, long long abatch,
      const float* __restrict__ B, long long ldb, long long bbatch,
      float* __restrict__ Cc, long long ldc, long long cbatch, long long csplit,
      int M, int Nvalid, int Ktot, int nsplit) {
    extern __shared__ __nv_bfloat16 dynsm[];
    uint32_t dm_u = smem_u32(dynsm);

    int tid = threadIdx.x, wid = tid >> 5, lid = tid & 31;
    int z = blockIdx.z;
    int batch = z / nsplit, split = z - batch * nsplit;
    int n0 = blockIdx.x * 128, m0 = blockIdx.y * 128;
    int Kchunk = Ktot / nsplit, kbeg = split * Kchunk;
    int L = Kchunk / 32;

    const float* Ab = A + abatch * batch;
    const float* Bb = B + bbatch * batch;
    float* Cb = Cc + cbatch * batch + csplit * split;

    int ar = tid >> 1, ac = (tid & 1) * 16;
    bool aok = (m0 + ar) < M;
    const float* ap = Ab + (long long)(m0 + ar) * lda + kbeg + ac;
    int kb = tid >> 3, cb = (tid & 7) * 16;
    const float* bp = Bb + (long long)(kbeg + kb) * ldb + n0 + cb;
    bool bok0 = (n0 + cb)      < Nvalid;
    bool bok1 = (n0 + cb + 4)  < Nvalid;
    bool bok2 = (n0 + cb + 8)  < Nvalid;
    bool bok3 = (n0 + cb + 12) < Nvalid;

    int wm = wid >> 1, wn = wid & 1;
    float acc[2][8][4];
    #pragma unroll
    for (int a1 = 0; a1 < 2; a1++)
        #pragma unroll
        for (int b1 = 0; b1 < 8; b1++)
            #pragma unroll
            for (int c1 = 0; c1 < 4; c1++) acc[a1][b1][c1] = 0.f;

    uint32_t a_off = (uint32_t)(((lid & 15)) * HSTRIDE + (lid >> 4) * 8) * 2;
    uint32_t b_off = (uint32_t)(((lid & 15)) * BST + ((lid >> 4) << 3)) * 2;
    uint32_t ast_off = (uint32_t)(ar * HSTRIDE + ac) * 2;
    uint32_t bst_off = (uint32_t)(kb * BST + cb) * 2;

    float4 pa0, pa1, pa2, pa3, pb0, pb1, pb2, pb3;
    {
        float4 zz = make_float4(0.f, 0.f, 0.f, 0.f);
        pa0 = aok ? *(const float4*)(ap)      : zz;
        pa1 = aok ? *(const float4*)(ap + 4)  : zz;
        pa2 = aok ? *(const float4*)(ap + 8)  : zz;
        pa3 = aok ? *(const float4*)(ap + 12) : zz;
        pb0 = bok0 ? *(const float4*)(bp)      : zz;
        pb1 = bok1 ? *(const float4*)(bp + 4)  : zz;
        pb2 = bok2 ? *(const float4*)(bp + 8)  : zz;
        pb3 = bok3 ? *(const float4*)(bp + 12) : zz;
    }

    for (int cc = 0; cc < L; cc++) {
        int s = cc & 1;
        uint32_t aHi = dm_u + (uint32_t)(s * 2 * A_BUF) * 2;
        uint32_t aLo = aHi + A_BUF * 2;
        uint32_t bB  = dm_u + (uint32_t)(4 * A_BUF + s * B_BUF) * 2;

        {
            unsigned h0, h1, h2, h3, h4, h5, h6, h7;
            unsigned l0, l1, l2, l3, l4, l5, l6, l7;
            split2h(pa0.x, pa0.y, h0, l0); split2h(pa0.z, pa0.w, h1, l1);
            split2h(pa1.x, pa1.y, h2, l2); split2h(pa1.z, pa1.w, h3, l3);
            split2h(pa2.x, pa2.y, h4, l4); split2h(pa2.z, pa2.w, h5, l5);
            split2h(pa3.x, pa3.y, h6, l6); split2h(pa3.z, pa3.w, h7, l7);
            asm volatile("st.shared.v4.b32 [%0], {%1,%2,%3,%4};" ::
                "r"(aHi + ast_off), "r"(h0), "r"(h1), "r"(h2), "r"(h3));
            asm volatile("st.shared.v4.b32 [%0], {%1,%2,%3,%4};" ::
                "r"(aHi + ast_off + 16), "r"(h4), "r"(h5), "r"(h6), "r"(h7));
            asm volatile("st.shared.v4.b32 [%0], {%1,%2,%3,%4};" ::
                "r"(aLo + ast_off), "r"(l0), "r"(l1), "r"(l2), "r"(l3));
            asm volatile("st.shared.v4.b32 [%0], {%1,%2,%3,%4};" ::
                "r"(aLo + ast_off + 16), "r"(l4), "r"(l5), "r"(l6), "r"(l7));
            h0 = packh(pb0.x, pb0.y); h1 = packh(pb0.z, pb0.w);
            h2 = packh(pb1.x, pb1.y); h3 = packh(pb1.z, pb1.w);
            h4 = packh(pb2.x, pb2.y); h5 = packh(pb2.z, pb2.w);
            h6 = packh(pb3.x, pb3.y); h7 = packh(pb3.z, pb3.w);
            asm volatile("st.shared.v4.b32 [%0], {%1,%2,%3,%4};" ::
                "r"(bB + bst_off), "r"(h0), "r"(h1), "r"(h2), "r"(h3));
            asm volatile("st.shared.v4.b32 [%0], {%1,%2,%3,%4};" ::
                "r"(bB + bst_off + 16), "r"(h4), "r"(h5), "r"(h6), "r"(h7));
        }

        if (cc + 1 < L) {
            int k0 = (cc + 1) * 32;
            const float* an = ap + k0;
            const float* bn = bp + (long long)k0 * ldb;
            float4 zz = make_float4(0.f, 0.f, 0.f, 0.f);
            pa0 = aok ? *(const float4*)(an)      : zz;
            pa1 = aok ? *(const float4*)(an + 4)  : zz;
            pa2 = aok ? *(const float4*)(an + 8)  : zz;
            pa3 = aok ? *(const float4*)(an + 12) : zz;
            pb0 = bok0 ? *(const float4*)(bn)      : zz;
            pb1 = bok1 ? *(const float4*)(bn + 4)  : zz;
            pb2 = bok2 ? *(const float4*)(bn + 8)  : zz;
            pb3 = bok3 ? *(const float4*)(bn + 12) : zz;
        }

        __syncthreads();

        #pragma unroll
        for (int kk = 0; kk < 2; kk++) {
            uint32_t ah[2][4], al[2][4];
            #pragma unroll
            for (int mt = 0; mt < 2; mt++) {
                uint32_t ro = (uint32_t)((wm * 32 + mt * 16) * HSTRIDE) * 2 + a_off + kk * 32;
                ldm_x4(ah[mt], aHi + ro);
                ldm_x4(al[mt], aLo + ro);
            }
            #pragma unroll
            for (int nt2 = 0; nt2 < 4; nt2++) {
                uint32_t bo = (uint32_t)(kk * 16 * BST) * 2 + b_off
                            + (uint32_t)((wn * 64 + nt2 * 16) * 2);
                uint32_t bh[4];
                ldm_x4t(bh, bB + bo);
                #pragma unroll
                for (int mt = 0; mt < 2; mt++) {
                    mma16816h(acc[mt][nt2 * 2],     ah[mt], bh);
                    mma16816h(acc[mt][nt2 * 2],     al[mt], bh);
                    mma16816h(acc[mt][nt2 * 2 + 1], ah[mt], bh + 2);
                    mma16816h(acc[mt][nt2 * 2 + 1], al[mt], bh + 2);
                }
            }
        }
        __syncthreads();
    }

    int rr = lid >> 2, cc2 = (lid & 3) * 2;
    #pragma unroll
    for (int mt = 0; mt < 2; mt++) {
        #pragma unroll
        for (int nt = 0; nt < 8; nt++) {
            int row = m0 + wm * 32 + mt * 16 + rr;
            int col = n0 + wn * 64 + nt * 8 + cc2;
            if (col < Nvalid) {
                if (row < M)
                    *(float2*)(Cb + (long long)row * ldc + col) =
                        make_float2(acc[mt][nt][0], acc[mt][nt][1]);
                if (row + 8 < M)
                    *(float2*)(Cb + (long long)(row + 8) * ldc + col) =
                        make_float2(acc[mt][nt][2], acc[mt][nt][3]);
            }
        }
    }
}

// ---------------- generic split reduce + epilogue ----------------
__global__ void reduce_kernel(const float* __restrict__ parts, long long pstride, int nsplit,
                              float* __restrict__ out, long long n,
                              const float* __restrict__ addsrc, int add_mode,
                              const float* __restrict__ bias, int bias_period,
                              int do_gelu) {
    long long i = (long long)blockIdx.x * 256 + threadIdx.x;
    if (i >= n) return;
    float s = 0.f;
    for (int p = 0; p < nsplit; p++) s += parts[p * pstride + i];
    if (bias) s += bias[i % bias_period];
    if (do_gelu) s = 0.5f * s * (1.0f + erff(s * 0.70710678118654752f));
    if (add_mode == 1) s += addsrc[i];
    else if (add_mode == 2) {
        long long r = i >> 12;
        s += addsrc[((r & 15) << 12) + (i & 4095)];
    }
    out[i] = s;
}

// ---------------- qt_all: reduce qp internally, emit QTT & QG [d][128] -------
__global__ void qt_all_kernel(const float* __restrict__ qp, const float* __restrict__ wkv,
                              const float* __restrict__ g,
                              float* __restrict__ QTT, float* __restrict__ QG) {
    __shared__ float qs[NL * INNER];
    for (int i = threadIdx.x; i < NL * INNER; i += 256) {
        float s = 0.f;
        #pragma unroll
        for (int p = 0; p < 8; p++) s += qp[p * NL * INNER + i];
        qs[i] = s;
    }
    __syncthreads();
    int d = blockIdx.x * 32 + (threadIdx.x >> 3);
    int h = threadIdx.x & 7;
    const float* wrow = wkv + (long long)d * 1536 + h * DHH;
    float acc[NL];
    #pragma unroll
    for (int i = 0; i < NL; i++) acc[i] = 0.f;
    for (int dh = 0; dh < DHH; dh++) {
        float w = wrow[dh];
        #pragma unroll
        for (int i = 0; i < NL; i++) acc[i] = fmaf(qs[i * INNER + h * DHH + dh], w, acc[i]);
    }
    float gd = g[d];
    #pragma unroll
    for (int i = 0; i < NL; i++) {
        int ih = h * NL + i;
        QTT[(long long)d * 128 + ih] = acc[i];
        QG[(long long)d * 128 + ih] = acc[i] * gd;
    }
}

__global__ void uv_kernel(const float* __restrict__ QTT, const float* __restrict__ g,
                          const float* __restrict__ b,
                          float* __restrict__ u, float* __restrict__ v) {
    int ih = threadIdx.x;
    float uu = 0.f, vv = 0.f;
    for (int d = 0; d < DD; d++) {
        float t = QTT[(long long)d * 128 + ih];
        uu = fmaf(t, g[d], uu);
        vv = fmaf(t, b[d], vv);
    }
    u[ih] = uu; v[ih] = vv;
}

__global__ void bv_kernel(const float* __restrict__ b, const float* __restrict__ wkv,
                          float* __restrict__ bv) {
    int e = blockIdx.x * 128 + threadIdx.x;
    float a = 0.f;
    for (int d = 0; d < DD; d++) a = fmaf(b[d], wkv[(long long)d * 1536 + INNER + e], a);
    bv[e] = a;
}

// ---------------- attention softmax: block per (bt, h) ----------------
__global__ void attn_kernel(const float* __restrict__ guid, const void* __restrict__ mask,
                            const float* __restrict__ S0, const float* __restrict__ mean,
                            const float* __restrict__ rstd,
                            const float* __restrict__ u, const float* __restrict__ v,
                            float* __restrict__ C, float* __restrict__ s_out) {
    extern __shared__ float sm[];
    float* sim = sm;
    float* rj  = sim + NL * NN;
    float* mj  = rj + NN;
    float* gu  = mj + NN;
    float* mk  = gu + NN;
    float* us  = mk + NN;
    float* vs  = us + NL;

    int bt = blockIdx.x >> 3;
    int h  = blockIdx.x & 7;
    int tid = threadIdx.x;
    int kind = g_mask_kind;

    for (int j = tid; j < NN; j += 256) {
        rj[j] = rstd[bt * NN + j];
        mj[j] = mean[bt * NN + j];
        gu[j] = guid[bt * NN + j];
        mk[j] = (kind == 1) ? (float)((const int*)mask)[bt * NN + j]
                            : (float)((const unsigned char*)mask)[bt * NN + j];
    }
    if (tid < NL) { us[tid] = u[h * NL + tid]; vs[tid] = v[h * NL + tid]; }
    __syncthreads();

    for (int idx = tid; idx < NL * NN; idx += 256) {
        int j = idx >> 4, i = idx & 15;
        float t = S0[((size_t)bt * NN + j) * 128 + h * NL + i];
        sim[i * NN + j] = ATTN_SCALE * (rj[j] * t - rj[j] * mj[j] * us[i] + vs[i]);
    }
    __syncthreads();

    int warp = tid >> 5, lane = tid & 31;
    for (int r = warp; r < NL; r += 8) {
        float* srow = sim + r * NN;
        float m0 = -FLT_MAX;
        for (int j = lane; j < NN; j += 32) m0 = fmaxf(m0, srow[j]);
        #pragma unroll
        for (int o = 16; o; o >>= 1) m0 = fmaxf(m0, __shfl_xor_sync(0xffffffffu, m0, o));

        float m1 = -FLT_MAX;
        for (int j = lane; j < NN; j += 32) {
            float s = srow[j] - m0;
            if (mk[j] != 0.f) s = -3.402823466e38f;
            s *= gu[j];
            srow[j] = s;
            m1 = fmaxf(m1, s);
        }
        #pragma unroll
        for (int o = 16; o; o >>= 1) m1 = fmaxf(m1, __shfl_xor_sync(0xffffffffu, m1, o));

        float sum = 0.f;
        for (int j = lane; j < NN; j += 32) {
            float e = expf(srow[j] - m1);
            srow[j] = e;
            sum += e;
        }
        #pragma unroll
        for (int o = 16; o; o >>= 1) sum += __shfl_xor_sync(0xffffffffu, sum, o);
        float inv = 1.f / sum;

        float sacc = 0.f;
        float* crow = C + ((size_t)bt * 128 + h * NL + r) * NN;
        for (int j = lane; j < NN; j += 32) {
            float a = srow[j] * inv;
            float c = a * rj[j];
            crow[j] = c;
            sacc = fmaf(c, mj[j], sacc);
        }
        #pragma unroll
        for (int o = 16; o; o >>= 1) sacc += __shfl_xor_sync(0xffffffffu, sacc, o);
        if (lane == 0) s_out[bt * 128 + h * NL + r] = sacc;
    }
}

// ---------------- Y[h][bt*16+i][d] = (AX[bt][h*16+i][d] - s)*g[d] -------------
__global__ void y_kernel(const float* __restrict__ AX, const float* __restrict__ s,
                         const float* __restrict__ g, float* __restrict__ Y) {
    long long idx = (long long)blockIdx.x * 256 + threadIdx.x;
    int d = idx & 4095;
    long long r = idx >> 12;
    int bt = (int)(r >> 7);
    int hi = (int)(r & 127);
    int h = hi >> 4, i = hi & 15;
    Y[(((long long)h * LATROWS + bt * NL + i) << 12) + d] = (AX[idx] - s[r]) * g[d];
}

// ---------------- launch ----------------
extern "C" void kernel_launch(void* const* d_in, const int* in_sizes, int n_in,
                              void* d_out, int out_size) {
    const float* x       = (const float*)d_in[0];
    const float* guid    = (const float*)d_in[1];
    const void*  mask    = d_in[2];
    const float* latents = (const float*)d_in[3];
    const float* nm_g    = (const float*)d_in[4];
    const float* nm_b    = (const float*)d_in[5];
    const float* nl_g    = (const float*)d_in[6];
    const float* nl_b    = (const float*)d_in[7];
    const float* wq      = (const float*)d_in[8];
    const float* wkv     = (const float*)d_in[9];
    const float* wout    = (const float*)d_in[10];
    const float* ff_g    = (const float*)d_in[11];
    const float* ff_b    = (const float*)d_in[12];
    const float* w1      = (const float*)d_in[13];
    const float* w2      = (const float*)d_in[14];
    const float* fn_g    = (const float*)d_in[15];
    const float* fn_b    = (const float*)d_in[16];
    float* out = (float*)d_out;

    float *p_mean, *p_rstd, *p_ql, *p_qp, *p_QTT, *p_QG, *p_u, *p_v, *p_bv;
    float *p_S0, *p_C, *p_s, *p_AX, *p_Y, *p_Vp, *p_attnv, *p_woutp;
    float *p_lat1, *p_ffln, *p_ff1p, *p_h1, *p_ff2p, *p_lat2;
    cudaGetSymbolAddress((void**)&p_mean, g_mean);
    cudaGetSymbolAddress((void**)&p_rstd, g_rstd);
    cudaGetSymbolAddress((void**)&p_ql, g_ql);
    cudaGetSymbolAddress((void**)&p_qp, g_qp);
    cudaGetSymbolAddress((void**)&p_QTT, g_QTT);
    cudaGetSymbolAddress((void**)&p_QG, g_QG);
    cudaGetSymbolAddress((void**)&p_u, g_u);
    cudaGetSymbolAddress((void**)&p_v, g_v);
    cudaGetSymbolAddress((void**)&p_bv, g_bv);
    cudaGetSymbolAddress((void**)&p_S0, g_S0);
    cudaGetSymbolAddress((void**)&p_C, g_C);
    cudaGetSymbolAddress((void**)&p_s, g_s);
    cudaGetSymbolAddress((void**)&p_AX, g_AX);
    cudaGetSymbolAddress((void**)&p_Y, g_Y);
    cudaGetSymbolAddress((void**)&p_Vp, g_Vp);
    cudaGetSymbolAddress((void**)&p_attnv, g_attnv);
    cudaGetSymbolAddress((void**)&p_woutp, g_woutp);
    cudaGetSymbolAddress((void**)&p_lat1, g_lat1);
    cudaGetSymbolAddress((void**)&p_ffln, g_ffln);
    cudaGetSymbolAddress((void**)&p_ff1p, g_ff1p);
    cudaGetSymbolAddress((void**)&p_h1, g_h1);
    cudaGetSymbolAddress((void**)&p_ff2p, g_ff2p);
    cudaGetSymbolAddress((void**)&p_lat2, g_lat2);

    cudaFuncSetAttribute(hmma3, cudaFuncAttributeMaxDynamicSharedMemorySize, HSMEM3);
    cudaFuncSetAttribute(hmma2, cudaFuncAttributeMaxDynamicSharedMemorySize, HSMEM2);

    // #1 ql = LN(latents)
    ln_rows_kernel<<<NL, 256>>>(latents, p_ql, nl_g, nl_b);
    // #2 qp = ql @ wq partials (split-K 8)
    hmma3<<<dim3(6, 1, 8), 256, HSMEM3>>>(p_ql, DD, 0, wq, INNER, 0,
                                          p_qp, INNER, 0, NL * INNER,
                                          NL, INNER, DD, 8, nullptr, nullptr);
    // #3 qt_all: reduce qp + QTT/QG
    qt_all_kernel<<<DD / 32, 256>>>(p_qp, wkv, nm_g, p_QTT, p_QG);

    // #4 S0 = x @ QG  (profiled slot) + fused x row stats
    hmma3<<<dim3(1, XROWS / 128, 1), 256, HSMEM3>>>(x, DD, 0, p_QG, 128, 0,
                                                    p_S0, 128, 0, 0,
                                                    XROWS, 128, DD, 1, p_mean, p_rstd);

    // u/v/bv/mask-kind (independent of S0)
    uv_kernel<<<1, 128>>>(p_QTT, nm_g, nm_b, p_u, p_v);
    bv_kernel<<<INNER / 128, 128>>>(nm_b, wkv, p_bv);
    detect_mask_kernel<<<1, 256>>>((const unsigned int*)mask);

    // softmax -> C, s
    {
        int smemb = (NL * NN + 4 * NN + 2 * NL) * (int)sizeof(float);
        cudaFuncSetAttribute(attn_kernel, cudaFuncAttributeMaxDynamicSharedMemorySize, smemb);
        attn_kernel<<<BT * HH, 256, smemb>>>(guid, mask, p_S0, p_mean, p_rstd,
                                             p_u, p_v, p_C, p_s);
    }

    // AX[bt] = C[bt] @ x[bt]   (fp16 2-term)
    hmma2<<<dim3(DD / 128, 1, BT), 256, HSMEM2>>>(
        p_C, NN, (long long)128 * NN, x, DD, (long long)NN * DD,
        p_AX, DD, (long long)128 * DD, 0, 128, DD, NN, 1);

    // Y = (AX - s) * g, head-major
    y_kernel<<<(BT * 128 * DD) / 256, 256>>>(p_AX, p_s, nm_g, p_Y);

    // attnV (fp16 2-term, split-K 8)
    hmma2<<<dim3(1, 2, HH * 8), 256, HSMEM2>>>(
        p_Y, DD, (long long)LATROWS * DD, wkv + INNER, 1536, 96,
        p_Vp, INNER, 96, (long long)LATROWS * INNER, LATROWS, 96, DD, 8);
    reduce_kernel<<<(LATROWS * INNER + 255) / 256, 256>>>(
        p_Vp, (long long)LATROWS * INNER, 8, p_attnv, LATROWS * INNER,
        nullptr, 0, p_bv, INNER, 0);

    // lat1 = attnv @ wout + latents (fp16 2-term, split-K 2)
    hmma2<<<dim3(DD / 128, 2, 2), 256, HSMEM2>>>(
        p_attnv, INNER, 0, wout, DD, 0,
        p_woutp, DD, 0, (long long)LATROWS * DD, LATROWS, DD, INNER, 2);
    reduce_kernel<<<(LATROWS * DD + 255) / 256, 256>>>(
        p_woutp, (long long)LATROWS * DD, 2, p_lat1, LATROWS * DD,
        latents, 2, nullptr, 1, 0);

    // FF (fp16 2-term)
    ln_rows_kernel<<<LATROWS, 256>>>(p_lat1, p_ffln, ff_g, ff_b);
    hmma2<<<dim3(FF / 128, 2, 2), 256, HSMEM2>>>(
        p_ffln, DD, 0, w1, FF, 0,
        p_ff1p, FF, 0, (long long)LATROWS * FF, LATROWS, FF, DD, 2);
    reduce_kernel<<<((long long)LATROWS * FF + 255) / 256, 256>>>(
        p_ff1p, (long long)LATROWS * FF, 2, p_h1, (long long)LATROWS * FF,
        nullptr, 0, nullptr, 1, 1);
    hmma2<<<dim3(DD / 128, 2, 2), 256, HSMEM2>>>(
        p_h1, FF, 0, w2, DD, 0,
        p_ff2p, DD, 0, (long long)LATROWS * DD, LATROWS, DD, FF, 2);
    reduce_kernel<<<(LATROWS * DD + 255) / 256, 256>>>(
        p_ff2p, (long long)LATROWS * DD, 2, p_lat2, LATROWS * DD,
        p_lat1, 1, nullptr, 1, 0);

    // final LN
    ln_rows_kernel<<<LATROWS, 256>>>(p_lat2, out, fn_g, fn_b);
}

// round 9
// speedup vs baseline: 7.3083x; 1.0056x over previous
#include <cuda_runtime.h>
#include <cuda_bf16.h>
#include <cuda_fp16.h>
#include <cfloat>
#include <math.h>
#include <stdint.h>

// ---------------- problem constants ----------------
#define NN 1792
#define DD 4096
#define HH 8
#define DHH 96
#define INNER 768
#define NL 16
#define FF 8192
#define BT 16
#define XROWS 28672        // BT*NN
#define LATROWS 256        // BT*NL
#define EPS 1e-5f
#define ATTN_SCALE 0.10206207261596577f  // 96^-0.5

// ---------------- scratch (static device memory) ----------------
__device__ float g_mean[XROWS];
__device__ float g_rstd[XROWS];
__device__ int   g_mask_kind;

__device__ float g_ql[NL * DD];
__device__ float g_qp[8 * NL * INNER];

__device__ float g_QTT[DD * 128];
__device__ float g_QG[DD * 128];       // B operand of S0: [K=d][N=128]
__device__ float g_u[128];
__device__ float g_v[128];
__device__ float g_bv[INNER];

__device__ float g_S0[(size_t)XROWS * 128];
__device__ float g_C[(size_t)BT * 128 * NN];
__device__ float g_s[BT * 128];
__device__ float g_AX[(size_t)BT * 128 * DD];
__device__ float g_Y[(size_t)HH * LATROWS * DD];

__device__ float g_Vp[8 * (size_t)LATROWS * INNER];
__device__ float g_attnv[LATROWS * INNER];
__device__ float g_woutp[2 * (size_t)LATROWS * DD];
__device__ float g_lat1[LATROWS * DD];
__device__ float g_ffln[LATROWS * DD];
__device__ float g_ff1p[2 * (size_t)LATROWS * FF];
__device__ float g_h1[(size_t)LATROWS * FF];
__device__ float g_ff2p[2 * (size_t)LATROWS * DD];
__device__ float g_lat2[LATROWS * DD];

// ---------------- helpers ----------------
__device__ __forceinline__ uint32_t smem_u32(const void* p) {
    uint32_t a;
    asm("{ .reg .u64 t; cvta.to.shared.u64 t, %1; cvt.u32.u64 %0, t; }" : "=r"(a) : "l"(p));
    return a;
}
__device__ __forceinline__ void ldm_x4(uint32_t* r, uint32_t addr) {
    asm volatile("ldmatrix.sync.aligned.m8n8.x4.shared.b16 {%0,%1,%2,%3}, [%4];"
                 : "=r"(r[0]), "=r"(r[1]), "=r"(r[2]), "=r"(r[3]) : "r"(addr));
}
__device__ __forceinline__ void ldm_x4t(uint32_t* r, uint32_t addr) {
    asm volatile("ldmatrix.sync.aligned.m8n8.x4.trans.shared.b16 {%0,%1,%2,%3}, [%4];"
                 : "=r"(r[0]), "=r"(r[1]), "=r"(r[2]), "=r"(r[3]) : "r"(addr));
}
__device__ __forceinline__ void mma16816(float* c, const uint32_t* a, const uint32_t* b) {
    asm volatile(
        "mma.sync.aligned.m16n8k16.row.col.f32.bf16.bf16.f32 "
        "{%0,%1,%2,%3}, {%4,%5,%6,%7}, {%8,%9}, {%0,%1,%2,%3};"
        : "+f"(c[0]), "+f"(c[1]), "+f"(c[2]), "+f"(c[3])
        : "r"(a[0]), "r"(a[1]), "r"(a[2]), "r"(a[3]), "r"(b[0]), "r"(b[1]));
}
__device__ __forceinline__ void mma16816h(float* c, const uint32_t* a, const uint32_t* b) {
    asm volatile(
        "mma.sync.aligned.m16n8k16.row.col.f32.f16.f16.f32 "
        "{%0,%1,%2,%3}, {%4,%5,%6,%7}, {%8,%9}, {%0,%1,%2,%3};"
        : "+f"(c[0]), "+f"(c[1]), "+f"(c[2]), "+f"(c[3])
        : "r"(a[0]), "r"(a[1]), "r"(a[2]), "r"(a[3]), "r"(b[0]), "r"(b[1]));
}
__device__ __forceinline__ void split2(float x, float y, unsigned& h, unsigned& l) {
    __nv_bfloat162 hh = __floats2bfloat162_rn(x, y);
    float r0 = x - __bfloat162float(__low2bfloat16(hh));
    float r1 = y - __bfloat162float(__high2bfloat16(hh));
    __nv_bfloat162 ll = __floats2bfloat162_rn(r0, r1);
    h = *reinterpret_cast<unsigned*>(&hh);
    l = *reinterpret_cast<unsigned*>(&ll);
}
__device__ __forceinline__ void split2h(float x, float y, unsigned& h, unsigned& l) {
    __half2 hh = __floats2half2_rn(x, y);
    float r0 = x - __half2float(__low2half(hh));
    float r1 = y - __half2float(__high2half(hh));
    __half2 ll = __floats2half2_rn(r0, r1);
    h = *reinterpret_cast<unsigned*>(&hh);
    l = *reinterpret_cast<unsigned*>(&ll);
}
__device__ __forceinline__ unsigned packh(float x, float y) {
    __half2 hh = __floats2half2_rn(x, y);
    return *reinterpret_cast<unsigned*>(&hh);
}

// ---------------- mask kind detection (parallel) ----------------
__global__ void detect_mask_kernel(const unsigned int* __restrict__ m) {
    __shared__ unsigned int sh[8];
    unsigned int orv = 0;
    for (int i = threadIdx.x; i < XROWS / 4; i += 256) orv |= m[i];
    #pragma unroll
    for (int o = 16; o; o >>= 1) orv |= __shfl_xor_sync(0xffffffffu, orv, o);
    int w = threadIdx.x >> 5;
    if ((threadIdx.x & 31) == 0) sh[w] = orv;
    __syncthreads();
    if (threadIdx.x == 0) {
        unsigned int t = 0;
        #pragma unroll
        for (int i = 0; i < 8; i++) t |= sh[i];
        g_mask_kind = (t <= 1u) ? 1 : 0;
    }
}

// ---------------- full layernorm ----------------
__global__ void ln_rows_kernel(const float* __restrict__ in, float* __restrict__ out,
                               const float* __restrict__ g, const float* __restrict__ b) {
    int row = blockIdx.x;
    const float* xr = in + (size_t)row * DD;
    float s = 0.f, q = 0.f;
    for (int i = threadIdx.x; i < DD; i += blockDim.x) { float v = xr[i]; s += v; q += v * v; }
    #pragma unroll
    for (int o = 16; o; o >>= 1) {
        s += __shfl_xor_sync(0xffffffffu, s, o);
        q += __shfl_xor_sync(0xffffffffu, q, o);
    }
    __shared__ float sh_s[8], sh_q[8];
    __shared__ float m_sh, r_sh;
    int w = threadIdx.x >> 5, l = threadIdx.x & 31;
    if (l == 0) { sh_s[w] = s; sh_q[w] = q; }
    __syncthreads();
    if (threadIdx.x == 0) {
        float S = 0.f, Q = 0.f;
        #pragma unroll
        for (int i = 0; i < 8; i++) { S += sh_s[i]; Q += sh_q[i]; }
        float m = S / (float)DD;
        m_sh = m;
        r_sh = rsqrtf(Q / (float)DD - m * m + EPS);
    }
    __syncthreads();
    float m = m_sh, r = r_sh;
    for (int i = threadIdx.x; i < DD; i += blockDim.x)
        out[(size_t)row * DD + i] = (xr[i] - m) * r * g[i] + b[i];
}

// ================= hmma3: bf16 3-term (exactish), pipelined =================
#define HSTRIDE 40    // A smem row stride (bf16)
#define BST 136       // B smem row stride (bf16)
#define A_BUF 5120    // 128*HSTRIDE
#define B_BUF 4352    // 32*BST
#define HSMEM3 ((4 * A_BUF + 4 * B_BUF) * 2)   // 75776 B
__global__ void __launch_bounds__(256, 1)
hmma3(const float* __restrict__ A, long long lda, long long abatch,
      const float* __restrict__ B, long long ldb, long long bbatch,
      float* __restrict__ Cc, long long ldc, long long cbatch, long long csplit,
      int M, int Nvalid, int Ktot, int nsplit,
      float* __restrict__ stats_mean, float* __restrict__ stats_rstd) {
    extern __shared__ __nv_bfloat16 dynsm[];
    uint32_t dm_u = smem_u32(dynsm);

    int tid = threadIdx.x, wid = tid >> 5, lid = tid & 31;
    int z = blockIdx.z;
    int batch = z / nsplit, split = z - batch * nsplit;
    int n0 = blockIdx.x * 128, m0 = blockIdx.y * 128;
    int Kchunk = Ktot / nsplit, kbeg = split * Kchunk;
    int L = Kchunk / 32;

    const float* Ab = A + abatch * batch;
    const float* Bb = B + bbatch * batch;
    float* Cb = Cc + cbatch * batch + csplit * split;

    int ar = tid >> 1, ac = (tid & 1) * 16;
    bool aok = (m0 + ar) < M;
    const float* ap = Ab + (long long)(m0 + ar) * lda + kbeg + ac;
    int kb = tid >> 3, cb = (tid & 7) * 16;
    const float* bp = Bb + (long long)(kbeg + kb) * ldb + n0 + cb;
    bool bok0 = (n0 + cb)      < Nvalid;
    bool bok1 = (n0 + cb + 4)  < Nvalid;
    bool bok2 = (n0 + cb + 8)  < Nvalid;
    bool bok3 = (n0 + cb + 12) < Nvalid;

    int wm = wid >> 1, wn = wid & 1;
    float acc[2][8][4];
    #pragma unroll
    for (int a1 = 0; a1 < 2; a1++)
        #pragma unroll
        for (int b1 = 0; b1 < 8; b1++)
            #pragma unroll
            for (int c1 = 0; c1 < 4; c1++) acc[a1][b1][c1] = 0.f;

    uint32_t a_off = (uint32_t)(((lid & 15)) * HSTRIDE + (lid >> 4) * 8) * 2;
    uint32_t b_off = (uint32_t)(((lid & 15)) * BST + ((lid >> 4) << 3)) * 2;
    uint32_t ast_off = (uint32_t)(ar * HSTRIDE + ac) * 2;
    uint32_t bst_off = (uint32_t)(kb * BST + cb) * 2;

    bool do_stats = (stats_mean != nullptr);
    float ssum = 0.f, sqsum = 0.f;

    float4 pa0, pa1, pa2, pa3, pb0, pb1, pb2, pb3;
    {
        float4 zz = make_float4(0.f, 0.f, 0.f, 0.f);
        pa0 = aok ? *(const float4*)(ap)      : zz;
        pa1 = aok ? *(const float4*)(ap + 4)  : zz;
        pa2 = aok ? *(const float4*)(ap + 8)  : zz;
        pa3 = aok ? *(const float4*)(ap + 12) : zz;
        pb0 = bok0 ? *(const float4*)(bp)      : zz;
        pb1 = bok1 ? *(const float4*)(bp + 4)  : zz;
        pb2 = bok2 ? *(const float4*)(bp + 8)  : zz;
        pb3 = bok3 ? *(const float4*)(bp + 12) : zz;
    }

    for (int cc = 0; cc < L; cc++) {
        int s = cc & 1;
        uint32_t aHi = dm_u + (uint32_t)(s * 2 * A_BUF) * 2;
        uint32_t aLo = aHi + A_BUF * 2;
        uint32_t bHi = dm_u + (uint32_t)(4 * A_BUF + s * 2 * B_BUF) * 2;
        uint32_t bLo = bHi + B_BUF * 2;

        {
            if (do_stats) {
                ssum += pa0.x + pa0.y + pa0.z + pa0.w + pa1.x + pa1.y + pa1.z + pa1.w
                      + pa2.x + pa2.y + pa2.z + pa2.w + pa3.x + pa3.y + pa3.z + pa3.w;
                sqsum += pa0.x*pa0.x + pa0.y*pa0.y + pa0.z*pa0.z + pa0.w*pa0.w
                       + pa1.x*pa1.x + pa1.y*pa1.y + pa1.z*pa1.z + pa1.w*pa1.w
                       + pa2.x*pa2.x + pa2.y*pa2.y + pa2.z*pa2.z + pa2.w*pa2.w
                       + pa3.x*pa3.x + pa3.y*pa3.y + pa3.z*pa3.z + pa3.w*pa3.w;
            }
            unsigned h0, h1, h2, h3, h4, h5, h6, h7;
            unsigned l0, l1, l2, l3, l4, l5, l6, l7;
            split2(pa0.x, pa0.y, h0, l0); split2(pa0.z, pa0.w, h1, l1);
            split2(pa1.x, pa1.y, h2, l2); split2(pa1.z, pa1.w, h3, l3);
            split2(pa2.x, pa2.y, h4, l4); split2(pa2.z, pa2.w, h5, l5);
            split2(pa3.x, pa3.y, h6, l6); split2(pa3.z, pa3.w, h7, l7);
            asm volatile("st.shared.v4.b32 [%0], {%1,%2,%3,%4};" ::
                "r"(aHi + ast_off), "r"(h0), "r"(h1), "r"(h2), "r"(h3));
            asm volatile("st.shared.v4.b32 [%0], {%1,%2,%3,%4};" ::
                "r"(aHi + ast_off + 16), "r"(h4), "r"(h5), "r"(h6), "r"(h7));
            asm volatile("st.shared.v4.b32 [%0], {%1,%2,%3,%4};" ::
                "r"(aLo + ast_off), "r"(l0), "r"(l1), "r"(l2), "r"(l3));
            asm volatile("st.shared.v4.b32 [%0], {%1,%2,%3,%4};" ::
                "r"(aLo + ast_off + 16), "r"(l4), "r"(l5), "r"(l6), "r"(l7));
            split2(pb0.x, pb0.y, h0, l0); split2(pb0.z, pb0.w, h1, l1);
            split2(pb1.x, pb1.y, h2, l2); split2(pb1.z, pb1.w, h3, l3);
            split2(pb2.x, pb2.y, h4, l4); split2(pb2.z, pb2.w, h5, l5);
            split2(pb3.x, pb3.y, h6, l6); split2(pb3.z, pb3.w, h7, l7);
            asm volatile("st.shared.v4.b32 [%0], {%1,%2,%3,%4};" ::
                "r"(bHi + bst_off), "r"(h0), "r"(h1), "r"(h2), "r"(h3));
            asm volatile("st.shared.v4.b32 [%0], {%1,%2,%3,%4};" ::
                "r"(bHi + bst_off + 16), "r"(h4), "r"(h5), "r"(h6), "r"(h7));
            asm volatile("st.shared.v4.b32 [%0], {%1,%2,%3,%4};" ::
                "r"(bLo + bst_off), "r"(l0), "r"(l1), "r"(l2), "r"(l3));
            asm volatile("st.shared.v4.b32 [%0], {%1,%2,%3,%4};" ::
                "r"(bLo + bst_off + 16), "r"(l4), "r"(l5), "r"(l6), "r"(l7));
        }

        if (cc + 1 < L) {
            int k0 = (cc + 1) * 32;
            const float* an = ap + k0;
            const float* bn = bp + (long long)k0 * ldb;
            float4 zz = make_float4(0.f, 0.f, 0.f, 0.f);
            pa0 = aok ? *(const float4*)(an)      : zz;
            pa1 = aok ? *(const float4*)(an + 4)  : zz;
            pa2 = aok ? *(const float4*)(an + 8)  : zz;
            pa3 = aok ? *(const float4*)(an + 12) : zz;
            pb0 = bok0 ? *(const float4*)(bn)      : zz;
            pb1 = bok1 ? *(const float4*)(bn + 4)  : zz;
            pb2 = bok2 ? *(const float4*)(bn + 8)  : zz;
            pb3 = bok3 ? *(const float4*)(bn + 12) : zz;
        }

        __syncthreads();

        #pragma unroll
        for (int kk = 0; kk < 2; kk++) {
            uint32_t ah[2][4], al[2][4], bh[4][4], bl[4][4];
            #pragma unroll
            for (int mt = 0; mt < 2; mt++) {
                uint32_t ro = (uint32_t)((wm * 32 + mt * 16) * HSTRIDE) * 2 + a_off + kk * 32;
                ldm_x4(ah[mt], aHi + ro);
                ldm_x4(al[mt], aLo + ro);
            }
            #pragma unroll
            for (int nt2 = 0; nt2 < 4; nt2++) {
                uint32_t bo = (uint32_t)(kk * 16 * BST) * 2 + b_off
                            + (uint32_t)((wn * 64 + nt2 * 16) * 2);
                ldm_x4t(bh[nt2], bHi + bo);
                ldm_x4t(bl[nt2], bLo + bo);
            }
            // term 1: Ah*Bh  (16 MMAs, all distinct accumulators)
            #pragma unroll
            for (int nt2 = 0; nt2 < 4; nt2++)
                #pragma unroll
                for (int mt = 0; mt < 2; mt++) {
                    mma16816(acc[mt][nt2 * 2],     ah[mt], bh[nt2]);
                    mma16816(acc[mt][nt2 * 2 + 1], ah[mt], bh[nt2] + 2);
                }
            // term 2: Ah*Bl
            #pragma unroll
            for (int nt2 = 0; nt2 < 4; nt2++)
                #pragma unroll
                for (int mt = 0; mt < 2; mt++) {
                    mma16816(acc[mt][nt2 * 2],     ah[mt], bl[nt2]);
                    mma16816(acc[mt][nt2 * 2 + 1], ah[mt], bl[nt2] + 2);
                }
            // term 3: Al*Bh
            #pragma unroll
            for (int nt2 = 0; nt2 < 4; nt2++)
                #pragma unroll
                for (int mt = 0; mt < 2; mt++) {
                    mma16816(acc[mt][nt2 * 2],     al[mt], bh[nt2]);
                    mma16816(acc[mt][nt2 * 2 + 1], al[mt], bh[nt2] + 2);
                }
        }
        __syncthreads();
    }

    if (do_stats && aok) {
        float s2 = ssum + __shfl_xor_sync(0xffffffffu, ssum, 1);
        float q2 = sqsum + __shfl_xor_sync(0xffffffffu, sqsum, 1);
        if ((tid & 1) == 0) {
            float m = s2 / (float)DD;
            stats_mean[m0 + ar] = m;
            stats_rstd[m0 + ar] = rsqrtf(q2 / (float)DD - m * m + EPS);
        }
    }

    int rr = lid >> 2, cc2 = (lid & 3) * 2;
    #pragma unroll
    for (int mt = 0; mt < 2; mt++) {
        #pragma unroll
        for (int nt = 0; nt < 8; nt++) {
            int row = m0 + wm * 32 + mt * 16 + rr;
            int col = n0 + wn * 64 + nt * 8 + cc2;
            if (col < Nvalid) {
                if (row < M)
                    *(float2*)(Cb + (long long)row * ldc + col) =
                        make_float2(acc[mt][nt][0], acc[mt][nt][1]);
                if (row + 8 < M)
                    *(float2*)(Cb + (long long)(row + 8) * ldc + col) =
                        make_float2(acc[mt][nt][2], acc[mt][nt][3]);
            }
        }
    }
}

// ============ hmma2: fp16 2-term (A hi/lo exact, B single-rounded) ===========
#define HSMEM2 ((4 * A_BUF + 2 * B_BUF) * 2)   // 58368 B
__global__ void __launch_bounds__(256, 1)
hmma2(const float* __restrict__ A, long long lda, long long abatch,
      const float* __restrict__ B, long long ldb, long long bbatch,
      float* __restrict__ Cc, long long ldc, long long cbatch, long long csplit,
      int M, int Nvalid, int Ktot, int nsplit) {
    extern __shared__ __nv_bfloat16 dynsm[];
    uint32_t dm_u = smem_u32(dynsm);

    int tid = threadIdx.x, wid = tid >> 5, lid = tid & 31;
    int z = blockIdx.z;
    int batch = z / nsplit, split = z - batch * nsplit;
    int n0 = blockIdx.x * 128, m0 = blockIdx.y * 128;
    int Kchunk = Ktot / nsplit, kbeg = split * Kchunk;
    int L = Kchunk / 32;

    const float* Ab = A + abatch * batch;
    const float* Bb = B + bbatch * batch;
    float* Cb = Cc + cbatch * batch + csplit * split;

    int ar = tid >> 1, ac = (tid & 1) * 16;
    bool aok = (m0 + ar) < M;
    const float* ap = Ab + (long long)(m0 + ar) * lda + kbeg + ac;
    int kb = tid >> 3, cb = (tid & 7) * 16;
    const float* bp = Bb + (long long)(kbeg + kb) * ldb + n0 + cb;
    bool bok0 = (n0 + cb)      < Nvalid;
    bool bok1 = (n0 + cb + 4)  < Nvalid;
    bool bok2 = (n0 + cb + 8)  < Nvalid;
    bool bok3 = (n0 + cb + 12) < Nvalid;

    int wm = wid >> 1, wn = wid & 1;
    float acc[2][8][4];
    #pragma unroll
    for (int a1 = 0; a1 < 2; a1++)
        #pragma unroll
        for (int b1 = 0; b1 < 8; b1++)
            #pragma unroll
            for (int c1 = 0; c1 < 4; c1++) acc[a1][b1][c1] = 0.f;

    uint32_t a_off = (uint32_t)(((lid & 15)) * HSTRIDE + (lid >> 4) * 8) * 2;
    uint32_t b_off = (uint32_t)(((lid & 15)) * BST + ((lid >> 4) << 3)) * 2;
    uint32_t ast_off = (uint32_t)(ar * HSTRIDE + ac) * 2;
    uint32_t bst_off = (uint32_t)(kb * BST + cb) * 2;

    float4 pa0, pa1, pa2, pa3, pb0, pb1, pb2, pb3;
    {
        float4 zz = make_float4(0.f, 0.f, 0.f, 0.f);
        pa0 = aok ? *(const float4*)(ap)      : zz;
        pa1 = aok ? *(const float4*)(ap + 4)  : zz;
        pa2 = aok ? *(const float4*)(ap + 8)  : zz;
        pa3 = aok ? *(const float4*)(ap + 12) : zz;
        pb0 = bok0 ? *(const float4*)(bp)      : zz;
        pb1 = bok1 ? *(const float4*)(bp + 4)  : zz;
        pb2 = bok2 ? *(const float4*)(bp + 8)  : zz;
        pb3 = bok3 ? *(const float4*)(bp + 12) : zz;
    }

    for (int cc = 0; cc < L; cc++) {
        int s = cc & 1;
        uint32_t aHi = dm_u + (uint32_t)(s * 2 * A_BUF) * 2;
        uint32_t aLo = aHi + A_BUF * 2;
        uint32_t bB  = dm_u + (uint32_t)(4 * A_BUF + s * B_BUF) * 2;

        {
            unsigned h0, h1, h2, h3, h4, h5, h6, h7;
            unsigned l0, l1, l2, l3, l4, l5, l6, l7;
            split2h(pa0.x, pa0.y, h0, l0); split2h(pa0.z, pa0.w, h1, l1);
            split2h(pa1.x, pa1.y, h2, l2); split2h(pa1.z, pa1.w, h3, l3);
            split2h(pa2.x, pa2.y, h4, l4); split2h(pa2.z, pa2.w, h5, l5);
            split2h(pa3.x, pa3.y, h6, l6); split2h(pa3.z, pa3.w, h7, l7);
            asm volatile("st.shared.v4.b32 [%0], {%1,%2,%3,%4};" ::
                "r"(aHi + ast_off), "r"(h0), "r"(h1), "r"(h2), "r"(h3));
            asm volatile("st.shared.v4.b32 [%0], {%1,%2,%3,%4};" ::
                "r"(aHi + ast_off + 16), "r"(h4), "r"(h5), "r"(h6), "r"(h7));
            asm volatile("st.shared.v4.b32 [%0], {%1,%2,%3,%4};" ::
                "r"(aLo + ast_off), "r"(l0), "r"(l1), "r"(l2), "r"(l3));
            asm volatile("st.shared.v4.b32 [%0], {%1,%2,%3,%4};" ::
                "r"(aLo + ast_off + 16), "r"(l4), "r"(l5), "r"(l6), "r"(l7));
            h0 = packh(pb0.x, pb0.y); h1 = packh(pb0.z, pb0.w);
            h2 = packh(pb1.x, pb1.y); h3 = packh(pb1.z, pb1.w);
            h4 = packh(pb2.x, pb2.y); h5 = packh(pb2.z, pb2.w);
            h6 = packh(pb3.x, pb3.y); h7 = packh(pb3.z, pb3.w);
            asm volatile("st.shared.v4.b32 [%0], {%1,%2,%3,%4};" ::
                "r"(bB + bst_off), "r"(h0), "r"(h1), "r"(h2), "r"(h3));
            asm volatile("st.shared.v4.b32 [%0], {%1,%2,%3,%4};" ::
                "r"(bB + bst_off + 16), "r"(h4), "r"(h5), "r"(h6), "r"(h7));
        }

        if (cc + 1 < L) {
            int k0 = (cc + 1) * 32;
            const float* an = ap + k0;
            const float* bn = bp + (long long)k0 * ldb;
            float4 zz = make_float4(0.f, 0.f, 0.f, 0.f);
            pa0 = aok ? *(const float4*)(an)      : zz;
            pa1 = aok ? *(const float4*)(an + 4)  : zz;
            pa2 = aok ? *(const float4*)(an + 8)  : zz;
            pa3 = aok ? *(const float4*)(an + 12) : zz;
            pb0 = bok0 ? *(const float4*)(bn)      : zz;
            pb1 = bok1 ? *(const float4*)(bn + 4)  : zz;
            pb2 = bok2 ? *(const float4*)(bn + 8)  : zz;
            pb3 = bok3 ? *(const float4*)(bn + 12) : zz;
        }

        __syncthreads();

        #pragma unroll
        for (int kk = 0; kk < 2; kk++) {
            uint32_t ah[2][4], al[2][4], bh[4][4];
            #pragma unroll
            for (int mt = 0; mt < 2; mt++) {
                uint32_t ro = (uint32_t)((wm * 32 + mt * 16) * HSTRIDE) * 2 + a_off + kk * 32;
                ldm_x4(ah[mt], aHi + ro);
                ldm_x4(al[mt], aLo + ro);
            }
            #pragma unroll
            for (int nt2 = 0; nt2 < 4; nt2++) {
                uint32_t bo = (uint32_t)(kk * 16 * BST) * 2 + b_off
                            + (uint32_t)((wn * 64 + nt2 * 16) * 2);
                ldm_x4t(bh[nt2], bB + bo);
            }
            // term 1: Ah*B
            #pragma unroll
            for (int nt2 = 0; nt2 < 4; nt2++)
                #pragma unroll
                for (int mt = 0; mt < 2; mt++) {
                    mma16816h(acc[mt][nt2 * 2],     ah[mt], bh[nt2]);
                    mma16816h(acc[mt][nt2 * 2 + 1], ah[mt], bh[nt2] + 2);
                }
            // term 2: Al*B
            #pragma unroll
            for (int nt2 = 0; nt2 < 4; nt2++)
                #pragma unroll
                for (int mt = 0; mt < 2; mt++) {
                    mma16816h(acc[mt][nt2 * 2],     al[mt], bh[nt2]);
                    mma16816h(acc[mt][nt2 * 2 + 1], al[mt], bh[nt2] + 2);
                }
        }
        __syncthreads();
    }

    int rr = lid >> 2, cc2 = (lid & 3) * 2;
    #pragma unroll
    for (int mt = 0; mt < 2; mt++) {
        #pragma unroll
        for (int nt = 0; nt < 8; nt++) {
            int row = m0 + wm * 32 + mt * 16 + rr;
            int col = n0 + wn * 64 + nt * 8 + cc2;
            if (col < Nvalid) {
                if (row < M)
                    *(float2*)(Cb + (long long)row * ldc + col) =
                        make_float2(acc[mt][nt][0], acc[mt][nt][1]);
                if (row + 8 < M)
                    *(float2*)(Cb + (long long)(row + 8) * ldc + col) =
                        make_float2(acc[mt][nt][2], acc[mt][nt][3]);
            }
        }
    }
}

// ---------------- generic split reduce + epilogue ----------------
__global__ void reduce_kernel(const float* __restrict__ parts, long long pstride, int nsplit,
                              float* __restrict__ out, long long n,
                              const float* __restrict__ addsrc, int add_mode,
                              const float* __restrict__ bias, int bias_period,
                              int do_gelu) {
    long long i = (long long)blockIdx.x * 256 + threadIdx.x;
    if (i >= n) return;
    float s = 0.f;
    for (int p = 0; p < nsplit; p++) s += parts[p * pstride + i];
    if (bias) s += bias[i % bias_period];
    if (do_gelu) s = 0.5f * s * (1.0f + erff(s * 0.70710678118654752f));
    if (add_mode == 1) s += addsrc[i];
    else if (add_mode == 2) {
        long long r = i >> 12;
        s += addsrc[((r & 15) << 12) + (i & 4095)];
    }
    out[i] = s;
}

// ---------------- qt_all: reduce qp internally, emit QTT & QG [d][128] -------
__global__ void qt_all_kernel(const float* __restrict__ qp, const float* __restrict__ wkv,
                              const float* __restrict__ g,
                              float* __restrict__ QTT, float* __restrict__ QG) {
    __shared__ float qs[NL * INNER];
    for (int i = threadIdx.x; i < NL * INNER; i += 256) {
        float s = 0.f;
        #pragma unroll
        for (int p = 0; p < 8; p++) s += qp[p * NL * INNER + i];
        qs[i] = s;
    }
    __syncthreads();
    int d = blockIdx.x * 32 + (threadIdx.x >> 3);
    int h = threadIdx.x & 7;
    const float* wrow = wkv + (long long)d * 1536 + h * DHH;
    float acc[NL];
    #pragma unroll
    for (int i = 0; i < NL; i++) acc[i] = 0.f;
    for (int dh = 0; dh < DHH; dh++) {
        float w = wrow[dh];
        #pragma unroll
        for (int i = 0; i < NL; i++) acc[i] = fmaf(qs[i * INNER + h * DHH + dh], w, acc[i]);
    }
    float gd = g[d];
    #pragma unroll
    for (int i = 0; i < NL; i++) {
        int ih = h * NL + i;
        QTT[(long long)d * 128 + ih] = acc[i];
        QG[(long long)d * 128 + ih] = acc[i] * gd;
    }
}

__global__ void uv_kernel(const float* __restrict__ QTT, const float* __restrict__ g,
                          const float* __restrict__ b,
                          float* __restrict__ u, float* __restrict__ v) {
    int ih = threadIdx.x;
    float uu = 0.f, vv = 0.f;
    for (int d = 0; d < DD; d++) {
        float t = QTT[(long long)d * 128 + ih];
        uu = fmaf(t, g[d], uu);
        vv = fmaf(t, b[d], vv);
    }
    u[ih] = uu; v[ih] = vv;
}

__global__ void bv_kernel(const float* __restrict__ b, const float* __restrict__ wkv,
                          float* __restrict__ bv) {
    int e = blockIdx.x * 128 + threadIdx.x;
    float a = 0.f;
    for (int d = 0; d < DD; d++) a = fmaf(b[d], wkv[(long long)d * 1536 + INNER + e], a);
    bv[e] = a;
}

// ---------------- attention softmax: block per (bt, h) ----------------
__global__ void attn_kernel(const float* __restrict__ guid, const void* __restrict__ mask,
                            const float* __restrict__ S0, const float* __restrict__ mean,
                            const float* __restrict__ rstd,
                            const float* __restrict__ u, const float* __restrict__ v,
                            float* __restrict__ C, float* __restrict__ s_out) {
    extern __shared__ float sm[];
    float* sim = sm;
    float* rj  = sim + NL * NN;
    float* mj  = rj + NN;
    float* gu  = mj + NN;
    float* mk  = gu + NN;
    float* us  = mk + NN;
    float* vs  = us + NL;

    int bt = blockIdx.x >> 3;
    int h  = blockIdx.x & 7;
    int tid = threadIdx.x;
    int kind = g_mask_kind;

    for (int j = tid; j < NN; j += 256) {
        rj[j] = rstd[bt * NN + j];
        mj[j] = mean[bt * NN + j];
        gu[j] = guid[bt * NN + j];
        mk[j] = (kind == 1) ? (float)((const int*)mask)[bt * NN + j]
                            : (float)((const unsigned char*)mask)[bt * NN + j];
    }
    if (tid < NL) { us[tid] = u[h * NL + tid]; vs[tid] = v[h * NL + tid]; }
    __syncthreads();

    for (int idx = tid; idx < NL * NN; idx += 256) {
        int j = idx >> 4, i = idx & 15;
        float t = S0[((size_t)bt * NN + j) * 128 + h * NL + i];
        sim[i * NN + j] = ATTN_SCALE * (rj[j] * t - rj[j] * mj[j] * us[i] + vs[i]);
    }
    __syncthreads();

    int warp = tid >> 5, lane = tid & 31;
    for (int r = warp; r < NL; r += 8) {
        float* srow = sim + r * NN;
        float m0 = -FLT_MAX;
        for (int j = lane; j < NN; j += 32) m0 = fmaxf(m0, srow[j]);
        #pragma unroll
        for (int o = 16; o; o >>= 1) m0 = fmaxf(m0, __shfl_xor_sync(0xffffffffu, m0, o));

        float m1 = -FLT_MAX;
        for (int j = lane; j < NN; j += 32) {
            float s = srow[j] - m0;
            if (mk[j] != 0.f) s = -3.402823466e38f;
            s *= gu[j];
            srow[j] = s;
            m1 = fmaxf(m1, s);
        }
        #pragma unroll
        for (int o = 16; o; o >>= 1) m1 = fmaxf(m1, __shfl_xor_sync(0xffffffffu, m1, o));

        float sum = 0.f;
        for (int j = lane; j < NN; j += 32) {
            float e = expf(srow[j] - m1);
            srow[j] = e;
            sum += e;
        }
        #pragma unroll
        for (int o = 16; o; o >>= 1) sum += __shfl_xor_sync(0xffffffffu, sum, o);
        float inv = 1.f / sum;

        float sacc = 0.f;
        float* crow = C + ((size_t)bt * 128 + h * NL + r) * NN;
        for (int j = lane; j < NN; j += 32) {
            float a = srow[j] * inv;
            float c = a * rj[j];
            crow[j] = c;
            sacc = fmaf(c, mj[j], sacc);
        }
        #pragma unroll
        for (int o = 16; o; o >>= 1) sacc += __shfl_xor_sync(0xffffffffu, sacc, o);
        if (lane == 0) s_out[bt * 128 + h * NL + r] = sacc;
    }
}

// ---------------- Y[h][bt*16+i][d] = (AX[bt][h*16+i][d] - s)*g[d] -------------
__global__ void y_kernel(const float* __restrict__ AX, const float* __restrict__ s,
                         const float* __restrict__ g, float* __restrict__ Y) {
    long long idx = (long long)blockIdx.x * 256 + threadIdx.x;
    int d = idx & 4095;
    long long r = idx >> 12;
    int bt = (int)(r >> 7);
    int hi = (int)(r & 127);
    int h = hi >> 4, i = hi & 15;
    Y[(((long long)h * LATROWS + bt * NL + i) << 12) + d] = (AX[idx] - s[r]) * g[d];
}

// ---------------- launch ----------------
extern "C" void kernel_launch(void* const* d_in, const int* in_sizes, int n_in,
                              void* d_out, int out_size) {
    const float* x       = (const float*)d_in[0];
    const float* guid    = (const float*)d_in[1];
    const void*  mask    = d_in[2];
    const float* latents = (const float*)d_in[3];
    const float* nm_g    = (const float*)d_in[4];
    const float* nm_b    = (const float*)d_in[5];
    const float* nl_g    = (const float*)d_in[6];
    const float* nl_b    = (const float*)d_in[7];
    const float* wq      = (const float*)d_in[8];
    const float* wkv     = (const float*)d_in[9];
    const float* wout    = (const float*)d_in[10];
    const float* ff_g    = (const float*)d_in[11];
    const float* ff_b    = (const float*)d_in[12];
    const float* w1      = (const float*)d_in[13];
    const float* w2      = (const float*)d_in[14];
    const float* fn_g    = (const float*)d_in[15];
    const float* fn_b    = (const float*)d_in[16];
    float* out = (float*)d_out;

    float *p_mean, *p_rstd, *p_ql, *p_qp, *p_QTT, *p_QG, *p_u, *p_v, *p_bv;
    float *p_S0, *p_C, *p_s, *p_AX, *p_Y, *p_Vp, *p_attnv, *p_woutp;
    float *p_lat1, *p_ffln, *p_ff1p, *p_h1, *p_ff2p, *p_lat2;
    cudaGetSymbolAddress((void**)&p_mean, g_mean);
    cudaGetSymbolAddress((void**)&p_rstd, g_rstd);
    cudaGetSymbolAddress((void**)&p_ql, g_ql);
    cudaGetSymbolAddress((void**)&p_qp, g_qp);
    cudaGetSymbolAddress((void**)&p_QTT, g_QTT);
    cudaGetSymbolAddress((void**)&p_QG, g_QG);
    cudaGetSymbolAddress((void**)&p_u, g_u);
    cudaGetSymbolAddress((void**)&p_v, g_v);
    cudaGetSymbolAddress((void**)&p_bv, g_bv);
    cudaGetSymbolAddress((void**)&p_S0, g_S0);
    cudaGetSymbolAddress((void**)&p_C, g_C);
    cudaGetSymbolAddress((void**)&p_s, g_s);
    cudaGetSymbolAddress((void**)&p_AX, g_AX);
    cudaGetSymbolAddress((void**)&p_Y, g_Y);
    cudaGetSymbolAddress((void**)&p_Vp, g_Vp);
    cudaGetSymbolAddress((void**)&p_attnv, g_attnv);
    cudaGetSymbolAddress((void**)&p_woutp, g_woutp);
    cudaGetSymbolAddress((void**)&p_lat1, g_lat1);
    cudaGetSymbolAddress((void**)&p_ffln, g_ffln);
    cudaGetSymbolAddress((void**)&p_ff1p, g_ff1p);
    cudaGetSymbolAddress((void**)&p_h1, g_h1);
    cudaGetSymbolAddress((void**)&p_ff2p, g_ff2p);
    cudaGetSymbolAddress((void**)&p_lat2, g_lat2);

    cudaFuncSetAttribute(hmma3, cudaFuncAttributeMaxDynamicSharedMemorySize, HSMEM3);
    cudaFuncSetAttribute(hmma2, cudaFuncAttributeMaxDynamicSharedMemorySize, HSMEM2);

    // #1 ql = LN(latents)
    ln_rows_kernel<<<NL, 256>>>(latents, p_ql, nl_g, nl_b);
    // #2 qp = ql @ wq partials (split-K 8)
    hmma3<<<dim3(6, 1, 8), 256, HSMEM3>>>(p_ql, DD, 0, wq, INNER, 0,
                                          p_qp, INNER, 0, NL * INNER,
                                          NL, INNER, DD, 8, nullptr, nullptr);
    // #3 qt_all: reduce qp + QTT/QG
    qt_all_kernel<<<DD / 32, 256>>>(p_qp, wkv, nm_g, p_QTT, p_QG);

    // #4 S0 = x @ QG  (profiled slot) + fused x row stats
    hmma3<<<dim3(1, XROWS / 128, 1), 256, HSMEM3>>>(x, DD, 0, p_QG, 128, 0,
                                                    p_S0, 128, 0, 0,
                                                    XROWS, 128, DD, 1, p_mean, p_rstd);

    // u/v/bv/mask-kind (independent of S0)
    uv_kernel<<<1, 128>>>(p_QTT, nm_g, nm_b, p_u, p_v);
    bv_kernel<<<INNER / 128, 128>>>(nm_b, wkv, p_bv);
    detect_mask_kernel<<<1, 256>>>((const unsigned int*)mask);

    // softmax -> C, s
    {
        int smemb = (NL * NN + 4 * NN + 2 * NL) * (int)sizeof(float);
        cudaFuncSetAttribute(attn_kernel, cudaFuncAttributeMaxDynamicSharedMemorySize, smemb);
        attn_kernel<<<BT * HH, 256, smemb>>>(guid, mask, p_S0, p_mean, p_rstd,
                                             p_u, p_v, p_C, p_s);
    }

    // AX[bt] = C[bt] @ x[bt]   (fp16 2-term)
    hmma2<<<dim3(DD / 128, 1, BT), 256, HSMEM2>>>(
        p_C, NN, (long long)128 * NN, x, DD, (long long)NN * DD,
        p_AX, DD, (long long)128 * DD, 0, 128, DD, NN, 1);

    // Y = (AX - s) * g, head-major
    y_kernel<<<(BT * 128 * DD) / 256, 256>>>(p_AX, p_s, nm_g, p_Y);

    // attnV (fp16 2-term, split-K 8)
    hmma2<<<dim3(1, 2, HH * 8), 256, HSMEM2>>>(
        p_Y, DD, (long long)LATROWS * DD, wkv + INNER, 1536, 96,
        p_Vp, INNER, 96, (long long)LATROWS * INNER, LATROWS, 96, DD, 8);
    reduce_kernel<<<(LATROWS * INNER + 255) / 256, 256>>>(
        p_Vp, (long long)LATROWS * INNER, 8, p_attnv, LATROWS * INNER,
        nullptr, 0, p_bv, INNER, 0);

    // lat1 = attnv @ wout + latents (fp16 2-term, split-K 2)
    hmma2<<<dim3(DD / 128, 2, 2), 256, HSMEM2>>>(
        p_attnv, INNER, 0, wout, DD, 0,
        p_woutp, DD, 0, (long long)LATROWS * DD, LATROWS, DD, INNER, 2);
    reduce_kernel<<<(LATROWS * DD + 255) / 256, 256>>>(
        p_woutp, (long long)LATROWS * DD, 2, p_lat1, LATROWS * DD,
        latents, 2, nullptr, 1, 0);

    // FF (fp16 2-term)
    ln_rows_kernel<<<LATROWS, 256>>>(p_lat1, p_ffln, ff_g, ff_b);
    hmma2<<<dim3(FF / 128, 2, 2), 256, HSMEM2>>>(
        p_ffln, DD, 0, w1, FF, 0,
        p_ff1p, FF, 0, (long long)LATROWS * FF, LATROWS, FF, DD, 2);
    reduce_kernel<<<((long long)LATROWS * FF + 255) / 256, 256>>>(
        p_ff1p, (long long)LATROWS * FF, 2, p_h1, (long long)LATROWS * FF,
        nullptr, 0, nullptr, 1, 1);
    hmma2<<<dim3(DD / 128, 2, 2), 256, HSMEM2>>>(
        p_h1, FF, 0, w2, DD, 0,
        p_ff2p, DD, 0, (long long)LATROWS * DD, LATROWS, DD, FF, 2);
    reduce_kernel<<<(LATROWS * DD + 255) / 256, 256>>>(
        p_ff2p, (long long)LATROWS * DD, 2, p_lat2, LATROWS * DD,
        p_lat1, 1, nullptr, 1, 0);

    // final LN
    ln_rows_kernel<<<LATROWS, 256>>>(p_lat2, out, fn_g, fn_b);
}